// round 10
// baseline (speedup 1.0000x reference)
#include <cuda_runtime.h>
#include <cuda_bf16.h>
#include <math.h>

// ---------------- problem constants ----------------
#define DMODEL 1024
#define NHEAD  16
#define NKV    4
#define DK     64
#define NEXP   8
#define TOPK   2
#define RLORA  16
#define SCALE_LORA 2.0f
#define HID    4096
#define TTOK   2048
#define SEQ    1024
#define KVDIM  256
#define NSLOT  (TTOK * TOPK)
#define EWELEM (NEXP * DMODEL * HID)   // 33.55M per weight tensor

// ---------------- scratch ----------------
__device__ float d_h   [TTOK * DMODEL];
__device__ float d_WqE [DMODEL * DMODEL];
__device__ float d_WkE [DMODEL * KVDIM];
__device__ float d_WvE [DMODEL * KVDIM];
__device__ float d_gateE[DMODEL * NEXP];
__device__ float d_Q   [TTOK * DMODEL];
__device__ float d_Kb  [TTOK * KVDIM];
__device__ float d_Vb  [TTOK * KVDIM];
__device__ float d_ctx [TTOK * DMODEL];
__device__ float d_xf  [TTOK * DMODEL];
__device__ float d_xfr [TTOK * DMODEL];   // tf32-rna rounded copy for experts
__device__ float d_h1  [NSLOT * HID];
__device__ float d_Ge  [NSLOT * DMODEL];
__device__ float d_Ve  [NSLOT * DMODEL];
// pre-rounded expert weights (tf32-rna)
__device__ float d_W1r [EWELEM];
__device__ float d_Wgr [EWELEM];
__device__ float d_Wvr [EWELEM];
__device__ int   d_top   [NSLOT];
__device__ float d_tw    [NSLOT];
__device__ int   d_pos   [NSLOT];
__device__ int   d_rowof [NSLOT];
__device__ int   d_tokrow[NSLOT];
__device__ int   d_cnt   [NEXP];
__device__ int   d_offs  [NEXP];

__device__ __forceinline__ float tf32r(float f) {
    unsigned u;
    asm("cvt.rna.tf32.f32 %0, %1;" : "=r"(u) : "f"(f));
    return __uint_as_float(u);
}

// ---------------- small kernels ----------------
__global__ void eff_weight_kernel(const float* __restrict__ WT,
                                  const float* __restrict__ A,
                                  const float* __restrict__ B,
                                  float* __restrict__ out, int N, int total) {
    int i = blockIdx.x * blockDim.x + threadIdx.x;
    if (i >= total) return;
    int k = i / N, n = i - k * N;
    float s = 0.f;
#pragma unroll
    for (int r = 0; r < RLORA; ++r) s += A[k * RLORA + r] * B[r * N + n];
    out[i] = WT[i] + SCALE_LORA * s;
}

// round a weight tensor to tf32-rna (float4 vectorized)
__global__ void round_w_kernel(const float4* __restrict__ in,
                               float4* __restrict__ out, int n4) {
    int i = blockIdx.x * blockDim.x + threadIdx.x;
    if (i >= n4) return;
    float4 v = in[i];
    v.x = tf32r(v.x); v.y = tf32r(v.y); v.z = tf32r(v.z); v.w = tf32r(v.w);
    out[i] = v;
}

__global__ void rmsnorm1_kernel(const float* __restrict__ x,
                                const float* __restrict__ w,
                                float* __restrict__ h) {
    int t = blockIdx.x;
    __shared__ float red[256];
    float ss = 0.f;
    for (int d = threadIdx.x; d < DMODEL; d += 256) {
        float v = x[(size_t)t * DMODEL + d];
        ss += v * v;
    }
    red[threadIdx.x] = ss; __syncthreads();
    for (int s = 128; s > 0; s >>= 1) {
        if (threadIdx.x < s) red[threadIdx.x] += red[threadIdx.x + s];
        __syncthreads();
    }
    float rs = rsqrtf(red[0] / (float)DMODEL + 1e-6f);
    for (int d = threadIdx.x; d < DMODEL; d += 256)
        h[(size_t)t * DMODEL + d] = x[(size_t)t * DMODEL + d] * rs * w[d];
}

// writes xf (full fp32, for gate) and xfr (tf32-rna, for expert GEMM1)
__global__ void rmsnorm2_kernel(const float* __restrict__ xin,
                                const float* __restrict__ w,
                                const int* __restrict__ taskid,
                                const float* __restrict__ temb,
                                float* __restrict__ xf,
                                float* __restrict__ xfr) {
    int t = blockIdx.x;
    __shared__ float red[256];
    float ss = 0.f;
    for (int d = threadIdx.x; d < DMODEL; d += 256) {
        float v = xin[(size_t)t * DMODEL + d];
        ss += v * v;
    }
    red[threadIdx.x] = ss; __syncthreads();
    for (int s = 128; s > 0; s >>= 1) {
        if (threadIdx.x < s) red[threadIdx.x] += red[threadIdx.x + s];
        __syncthreads();
    }
    float rs = rsqrtf(red[0] / (float)DMODEL + 1e-6f);
    int tk = taskid[t];
    for (int d = threadIdx.x; d < DMODEL; d += 256) {
        float v = xin[(size_t)t * DMODEL + d] * rs * w[d] + temb[tk * DMODEL + d];
        xf[(size_t)t * DMODEL + d]  = v;
        xfr[(size_t)t * DMODEL + d] = tf32r(v);
    }
}

__global__ void rope_kernel(float* __restrict__ Q, float* __restrict__ K,
                            const float* __restrict__ fcos,
                            const float* __restrict__ fsin) {
    int t = blockIdx.x;
    int s = t & (SEQ - 1);
    int tid = threadIdx.x;
    int h = tid >> 5;
    int d = tid & 31;
    float c1 = fcos[s * DK + d],      s1 = fsin[s * DK + d];
    float c2 = fcos[s * DK + d + 32], s2 = fsin[s * DK + d + 32];
    {
        float* q = Q + (size_t)t * DMODEL + h * DK;
        float x1 = q[d], x2 = q[d + 32];
        q[d]      = x1 * c1 - x2 * s1;
        q[d + 32] = x2 * c2 + x1 * s2;
    }
    if (h < NKV) {
        float* k = K + (size_t)t * KVDIM + h * DK;
        float x1 = k[d], x2 = k[d + 32];
        k[d]      = x1 * c1 - x2 * s1;
        k[d + 32] = x2 * c2 + x1 * s2;
    }
}

// ---------------- fp32 tiled SGEMM: 64x64x16 (pre-routing path) -------------
#define BM 64
#define BN 64
#define BKK 16

__device__ __forceinline__ void sgemm_tile_dev(
    const float* __restrict__ A, int lda,
    const float* __restrict__ B, int ldb,
    const float* __restrict__ Cadd,
    float* __restrict__ C, int ldc,
    int M, int K, int m0, int n0)
{
    __shared__ float As[BKK][BM];
    __shared__ float Bs[BKK][BN];
    const int tid = threadIdx.x;
    const int tx = tid & 15, ty = tid >> 4;
    const int aRow = tid >> 2;
    const int aCol = (tid & 3) * 4;
    const int bRow = tid >> 4;
    const int bCol = (tid & 15) * 4;

    const float* Aptr = A + (size_t)(m0 + aRow) * lda + aCol;
    const float* Bptr = B + (size_t)bRow * ldb + n0 + bCol;

    float acc[4][4];
#pragma unroll
    for (int i = 0; i < 4; ++i)
#pragma unroll
        for (int j = 0; j < 4; ++j) acc[i][j] = 0.f;

    for (int kk = 0; kk < K; kk += BKK) {
        float4 av = *(const float4*)(Aptr + kk);
        float4 bv = *(const float4*)(Bptr + (size_t)kk * ldb);
        __syncthreads();
        As[aCol + 0][aRow] = av.x;
        As[aCol + 1][aRow] = av.y;
        As[aCol + 2][aRow] = av.z;
        As[aCol + 3][aRow] = av.w;
        *(float4*)&Bs[bRow][bCol] = bv;
        __syncthreads();
#pragma unroll
        for (int k = 0; k < BKK; ++k) {
            float4 a = *(const float4*)&As[k][ty * 4];
            float4 b = *(const float4*)&Bs[k][tx * 4];
            acc[0][0] += a.x * b.x; acc[0][1] += a.x * b.y; acc[0][2] += a.x * b.z; acc[0][3] += a.x * b.w;
            acc[1][0] += a.y * b.x; acc[1][1] += a.y * b.y; acc[1][2] += a.y * b.z; acc[1][3] += a.y * b.w;
            acc[2][0] += a.z * b.x; acc[2][1] += a.z * b.y; acc[2][2] += a.z * b.z; acc[2][3] += a.z * b.w;
            acc[3][0] += a.w * b.x; acc[3][1] += a.w * b.y; acc[3][2] += a.w * b.z; acc[3][3] += a.w * b.w;
        }
    }

#pragma unroll
    for (int i = 0; i < 4; ++i) {
        size_t crow = (size_t)(m0 + ty * 4 + i);
#pragma unroll
        for (int j = 0; j < 4; ++j) {
            int c = n0 + tx * 4 + j;
            float v = acc[i][j];
            if (Cadd) v += Cadd[crow * ldc + c];
            C[crow * ldc + c] = v;
        }
    }
}

__global__ __launch_bounds__(256) void sgemm_plain(
    const float* __restrict__ A, int lda,
    const float* __restrict__ B, int ldb,
    const float* __restrict__ Cadd,
    float* __restrict__ C, int ldc, int M, int K)
{
    sgemm_tile_dev(A, lda, B, ldb, Cadd, C, ldc, M, K,
                   blockIdx.y * BM, blockIdx.x * BN);
}

// ------- tf32 tensor-core GEMM v5: cp.async double-buffer, no cvt, 2/SM -----
// All operands are pre-rounded to tf32-rna, so HMMA's low-bit truncation is
// exact; numerics identical to the R5/R9 rna-at-store kernel.
#define TM 128
#define TN 128
#define TKT 32
#define ASTR 36
#define BSTR 136
#define A_FLOATS (TM * ASTR)     // 4608
#define B_FLOATS (TKT * BSTR)    // 4352
#define SMEM_V5_BYTES ((2 * A_FLOATS + 2 * B_FLOATS) * 4)  // 71680

__device__ __forceinline__ void mma_tf32(float* d, const unsigned* a,
                                         const unsigned* b, const float* c) {
    asm volatile(
        "mma.sync.aligned.m16n8k8.row.col.f32.tf32.tf32.f32 "
        "{%0,%1,%2,%3}, {%4,%5,%6,%7}, {%8,%9}, {%10,%11,%12,%13};"
        : "=f"(d[0]), "=f"(d[1]), "=f"(d[2]), "=f"(d[3])
        : "r"(a[0]), "r"(a[1]), "r"(a[2]), "r"(a[3]),
          "r"(b[0]), "r"(b[1]),
          "f"(c[0]), "f"(c[1]), "f"(c[2]), "f"(c[3]));
}

__device__ __forceinline__ void cpasync16(unsigned dst, const void* src, int nbytes) {
    asm volatile("cp.async.cg.shared.global [%0], [%1], 16, %2;\n"
                 :: "r"(dst), "l"(src), "r"(nbytes));
}

__device__ __forceinline__ void mma_tile_v5(
    const float* __restrict__ A, int lda,
    const float* __restrict__ B, int ldb,
    const float* __restrict__ bias,
    float* __restrict__ C, int ldc,
    int M, int K,
    const int* __restrict__ gmap,
    int m0, int n0, int cRow0, int roundC)
{
    extern __shared__ float sm[];
    float* Abuf[2] = { sm, sm + A_FLOATS };
    float* Bbuf[2] = { sm + 2 * A_FLOATS, sm + 2 * A_FLOATS + B_FLOATS };

    const int tid  = threadIdx.x;
    const int lane = tid & 31;
    const int warp = tid >> 5;
    const int wm = (warp & 1) * 64;
    const int wn = (warp >> 1) * 32;
    const int fr = lane >> 2;
    const int fc = lane & 3;

    int aR[4], aKV[4], aOK[4];
    size_t aRowG[4];
    int bKR[4], bNV[4];
#pragma unroll
    for (int i = 0; i < 4; ++i) {
        int lin = tid + i * 256;
        aR[i]  = lin >> 3;
        aKV[i] = (lin & 7) * 4;
        int gr = m0 + aR[i];
        aOK[i] = (gr < M) ? 16 : 0;
        aRowG[i] = (gr < M) ? (size_t)(gmap ? gmap[gr] : gr) : 0;
        bKR[i] = lin >> 5;
        bNV[i] = (lin & 31) * 4;
    }

    float acc[4][4][4];
#pragma unroll
    for (int mi = 0; mi < 4; ++mi)
#pragma unroll
        for (int ni = 0; ni < 4; ++ni)
#pragma unroll
            for (int q = 0; q < 4; ++q) acc[mi][ni][q] = 0.f;

    auto issue_slab = [&](int kt, int buf) {
#pragma unroll
        for (int i = 0; i < 4; ++i) {
            unsigned dst = (unsigned)__cvta_generic_to_shared(
                Abuf[buf] + aR[i] * ASTR + aKV[i]);
            cpasync16(dst, A + aRowG[i] * lda + kt + aKV[i], aOK[i]);
        }
#pragma unroll
        for (int i = 0; i < 4; ++i) {
            unsigned dst = (unsigned)__cvta_generic_to_shared(
                Bbuf[buf] + bKR[i] * BSTR + bNV[i]);
            cpasync16(dst, B + (size_t)(kt + bKR[i]) * ldb + n0 + bNV[i], 16);
        }
        asm volatile("cp.async.commit_group;");
    };

    const int NKT = K / TKT;
    issue_slab(0, 0);
    if (NKT > 1) issue_slab(TKT, 1);

    for (int it = 0; it < NKT; ++it) {
        if (it + 1 < NKT) asm volatile("cp.async.wait_group 1;");
        else              asm volatile("cp.async.wait_group 0;");
        __syncthreads();
        const int buf = it & 1;
        const float* Ab = Abuf[buf];
        const float* Bb = Bbuf[buf];
#pragma unroll
        for (int k0 = 0; k0 < TKT; k0 += 8) {
            unsigned af[4][4], bf[4][2];
#pragma unroll
            for (int mi = 0; mi < 4; ++mi) {
                int rb = wm + mi * 16;
                af[mi][0] = __float_as_uint(Ab[(rb + fr) * ASTR + k0 + fc]);
                af[mi][1] = __float_as_uint(Ab[(rb + fr + 8) * ASTR + k0 + fc]);
                af[mi][2] = __float_as_uint(Ab[(rb + fr) * ASTR + k0 + fc + 4]);
                af[mi][3] = __float_as_uint(Ab[(rb + fr + 8) * ASTR + k0 + fc + 4]);
            }
#pragma unroll
            for (int ni = 0; ni < 4; ++ni) {
                int nb = wn + ni * 8;
                bf[ni][0] = __float_as_uint(Bb[(k0 + fc) * BSTR + nb + fr]);
                bf[ni][1] = __float_as_uint(Bb[(k0 + fc + 4) * BSTR + nb + fr]);
            }
#pragma unroll
            for (int mi = 0; mi < 4; ++mi)
#pragma unroll
                for (int ni = 0; ni < 4; ++ni)
                    mma_tf32(acc[mi][ni], af[mi], bf[ni], acc[mi][ni]);
        }
        __syncthreads();
        if (it + 2 < NKT) issue_slab((it + 2) * TKT, buf);
    }

    const int cc = (lane & 3) * 2;
#pragma unroll
    for (int mi = 0; mi < 4; ++mi) {
        int rloc0 = m0 + wm + mi * 16 + fr;
        int rloc1 = rloc0 + 8;
#pragma unroll
        for (int ni = 0; ni < 4; ++ni) {
            int col = n0 + wn + ni * 8 + cc;
            float b0 = bias ? bias[col] : 0.f;
            float b1 = bias ? bias[col + 1] : 0.f;
            if (rloc0 < M) {
                size_t cr = (size_t)(cRow0 + rloc0) * ldc;
                float v0 = acc[mi][ni][0] + b0;
                float v1 = acc[mi][ni][1] + b1;
                if (roundC) { v0 = tf32r(v0); v1 = tf32r(v1); }
                C[cr + col] = v0; C[cr + col + 1] = v1;
            }
            if (rloc1 < M) {
                size_t cr = (size_t)(cRow0 + rloc1) * ldc;
                float v2 = acc[mi][ni][2] + b0;
                float v3 = acc[mi][ni][3] + b1;
                if (roundC) { v2 = tf32r(v2); v3 = tf32r(v3); }
                C[cr + col] = v2; C[cr + col + 1] = v3;
            }
        }
    }
}

// expert GEMM1: h1[row,:] = tf32rna( xfr[tok(row),:] @ W1r[e] + b1[e] )
__global__ __launch_bounds__(256, 2) void mma_expert_up(
    const float* __restrict__ xfr,
    const float* __restrict__ W1r, const float* __restrict__ b1,
    float* __restrict__ h1)
{
    int e = blockIdx.z;
    int cnt = d_cnt[e];
    int m0 = blockIdx.y * TM;
    if (m0 >= cnt) return;
    int off = d_offs[e];
    mma_tile_v5(xfr, DMODEL,
                W1r + (size_t)e * DMODEL * HID, HID,
                b1 + (size_t)e * HID,
                h1, HID, cnt, DMODEL,
                d_tokrow + off, m0, blockIdx.x * TN, off, 1);
}

// fused expert GEMM2+3: Ge = h1 @ Wgr + bg ; Ve = h1 @ Wvr + bv
__global__ __launch_bounds__(256, 2) void mma_expert_gv(
    const float* __restrict__ h1,
    const float* __restrict__ Wgr, const float* __restrict__ bg,
    const float* __restrict__ Wvr, const float* __restrict__ bv,
    float* __restrict__ Ge, float* __restrict__ Ve)
{
    int e = blockIdx.z;
    int cnt = d_cnt[e];
    int m0 = blockIdx.y * TM;
    if (m0 >= cnt) return;
    int off = d_offs[e];
    const int halfTiles = DMODEL / TN;          // 8
    bool isV = blockIdx.x >= halfTiles;
    int n0 = (blockIdx.x - (isV ? halfTiles : 0)) * TN;
    const float* B    = (isV ? Wvr : Wgr) + (size_t)e * HID * DMODEL;
    const float* bias = (isV ? bv : bg) + (size_t)e * DMODEL;
    float* C = isV ? Ve : Ge;
    mma_tile_v5(h1 + (size_t)off * HID, HID, B, DMODEL, bias,
                C, DMODEL, cnt, HID, nullptr, m0, n0, off, 0);
}

// ---------------- flash attention (fp32, causal, GQA) ----------------
__global__ __launch_bounds__(64) void attn_kernel(
    const float* __restrict__ Q, const float* __restrict__ Kb,
    const float* __restrict__ Vb, float* __restrict__ ctx)
{
    const int qb = blockIdx.x, h = blockIdx.y, b = blockIdx.z;
    const int r = threadIdx.x;
    const int qglob = qb * 64 + r;
    const size_t t = (size_t)b * SEQ + qglob;
    const int kh = h >> 2;

    float q[DK];
    const float* qp = Q + t * DMODEL + h * DK;
#pragma unroll
    for (int d4 = 0; d4 < 16; ++d4) {
        float4 v = *(const float4*)(qp + d4 * 4);
        q[d4 * 4 + 0] = v.x; q[d4 * 4 + 1] = v.y;
        q[d4 * 4 + 2] = v.z; q[d4 * 4 + 3] = v.w;
    }
    float acc[DK];
#pragma unroll
    for (int d = 0; d < DK; ++d) acc[d] = 0.f;
    float mval = -3.4e38f, lsum = 0.f;

    __shared__ float Ksm[64][DK];
    __shared__ float Vsm[64][DK];

    for (int kt = 0; kt <= qb; ++kt) {
        __syncthreads();
        {
            size_t krow = (size_t)b * SEQ + kt * 64 + r;
            const float4* kp = (const float4*)(Kb + krow * KVDIM + kh * DK);
            const float4* vp = (const float4*)(Vb + krow * KVDIM + kh * DK);
#pragma unroll
            for (int c = 0; c < 16; ++c) {
                ((float4*)Ksm[r])[c] = kp[c];
                ((float4*)Vsm[r])[c] = vp[c];
            }
        }
        __syncthreads();
        const int kmax = (kt == qb) ? r : 63;
        for (int c0 = 0; c0 <= kmax; c0 += 16) {
            float s[16];
            float mch = -3.4e38f;
#pragma unroll
            for (int j = 0; j < 16; ++j) {
                int k = c0 + j;
                float dot = 0.f;
                const float4* kr = (const float4*)Ksm[k];
#pragma unroll
                for (int d4 = 0; d4 < 16; ++d4) {
                    float4 kv = kr[d4];
                    dot += q[d4 * 4 + 0] * kv.x + q[d4 * 4 + 1] * kv.y
                         + q[d4 * 4 + 2] * kv.z + q[d4 * 4 + 3] * kv.w;
                }
                s[j] = (k <= kmax) ? dot * 0.125f : -3.4e38f;
                mch = fmaxf(mch, s[j]);
            }
            float mnew = fmaxf(mval, mch);
            float corr = __expf(mval - mnew);
            lsum *= corr;
#pragma unroll
            for (int d = 0; d < DK; ++d) acc[d] *= corr;
#pragma unroll
            for (int j = 0; j < 16; ++j) {
                float p = __expf(s[j] - mnew);
                lsum += p;
                const float4* vr = (const float4*)Vsm[c0 + j];
#pragma unroll
                for (int d4 = 0; d4 < 16; ++d4) {
                    float4 vv = vr[d4];
                    acc[d4 * 4 + 0] += p * vv.x;
                    acc[d4 * 4 + 1] += p * vv.y;
                    acc[d4 * 4 + 2] += p * vv.z;
                    acc[d4 * 4 + 3] += p * vv.w;
                }
            }
            mval = mnew;
        }
    }
    float inv = 1.f / lsum;
    float* op = ctx + t * DMODEL + h * DK;
#pragma unroll
    for (int d = 0; d < DK; ++d) op[d] = acc[d] * inv;
}

// ---------------- gating ----------------
__global__ void gate_kernel(const float* __restrict__ xf,
                            const float* __restrict__ gateE) {
    int warp = (blockIdx.x * blockDim.x + threadIdx.x) >> 5;
    int lane = threadIdx.x & 31;
    if (warp >= TTOK) return;
    int t = warp;
    float acc[NEXP];
#pragma unroll
    for (int e = 0; e < NEXP; ++e) acc[e] = 0.f;
    for (int d = lane; d < DMODEL; d += 32) {
        float xv = xf[(size_t)t * DMODEL + d];
#pragma unroll
        for (int e = 0; e < NEXP; ++e) acc[e] += xv * gateE[d * NEXP + e];
    }
#pragma unroll
    for (int e = 0; e < NEXP; ++e)
#pragma unroll
        for (int o = 16; o > 0; o >>= 1)
            acc[e] += __shfl_xor_sync(0xffffffff, acc[e], o);
    if (lane == 0) {
        int i0 = 0; float v0 = acc[0];
#pragma unroll
        for (int e = 1; e < NEXP; ++e) if (acc[e] > v0) { v0 = acc[e]; i0 = e; }
        int i1 = -1; float v1 = -3.4e38f;
#pragma unroll
        for (int e = 0; e < NEXP; ++e)
            if (e != i0 && acc[e] > v1) { v1 = acc[e]; i1 = e; }
        if (i1 < 0) { i1 = (i0 + 1) & (NEXP - 1); v1 = v0; }
        float w0 = 1.f / (1.f + __expf(v1 - v0));
        float w1 = 1.f - w0;
        d_top[2 * t]     = i0;  d_tw[2 * t]     = w0;
        d_top[2 * t + 1] = i1;  d_tw[2 * t + 1] = w1;
    }
}

__global__ void bucket_kernel() {
    __shared__ int tops[NSLOT];
    __shared__ int cnt[NEXP];
    for (int s = threadIdx.x; s < NSLOT; s += blockDim.x) tops[s] = d_top[s];
    if (threadIdx.x < NEXP) cnt[threadIdx.x] = 0;
    __syncthreads();
    if (threadIdx.x == 0) {
        for (int s = 0; s < NSLOT; ++s) {
            int e = tops[s];
            d_pos[s] = cnt[e]++;
        }
        int o = 0;
        for (int e = 0; e < NEXP; ++e) { d_offs[e] = o; d_cnt[e] = cnt[e]; o += cnt[e]; }
    }
    __syncthreads();
    for (int s = threadIdx.x; s < NSLOT; s += blockDim.x) {
        int e = tops[s];
        int j = d_offs[e] + d_pos[s];
        d_rowof[s] = j;
        d_tokrow[j] = s >> 1;
    }
}

__global__ void combine_kernel(const float* __restrict__ Ge,
                               const float* __restrict__ Ve,
                               float* __restrict__ out) {
    int t = blockIdx.x;
    int j0 = d_rowof[2 * t],     j1 = d_rowof[2 * t + 1];
    float w0 = d_tw[2 * t],      w1 = d_tw[2 * t + 1];
    const float4* g0p = (const float4*)(Ge + (size_t)j0 * DMODEL);
    const float4* v0p = (const float4*)(Ve + (size_t)j0 * DMODEL);
    const float4* g1p = (const float4*)(Ge + (size_t)j1 * DMODEL);
    const float4* v1p = (const float4*)(Ve + (size_t)j1 * DMODEL);
    float4* op = (float4*)(out + (size_t)t * DMODEL);
    for (int d = threadIdx.x; d < DMODEL / 4; d += blockDim.x) {
        float4 g0 = g0p[d], g1 = g1p[d], v0 = v0p[d], v1 = v1p[d], o = op[d];
        o.x += w0 * (g0.x / (1.f + __expf(-g0.x))) * v0.x + w1 * (g1.x / (1.f + __expf(-g1.x))) * v1.x;
        o.y += w0 * (g0.y / (1.f + __expf(-g0.y))) * v0.y + w1 * (g1.y / (1.f + __expf(-g1.y))) * v1.y;
        o.z += w0 * (g0.z / (1.f + __expf(-g0.z))) * v0.z + w1 * (g1.z / (1.f + __expf(-g1.z))) * v1.z;
        o.w += w0 * (g0.w / (1.f + __expf(-g0.w))) * v0.w + w1 * (g1.w / (1.f + __expf(-g1.w))) * v1.w;
        op[d] = o;
    }
}

// ---------------- launch ----------------
extern "C" void kernel_launch(void* const* d_in, const int* in_sizes, int n_in,
                              void* d_out, int out_size) {
    const float* x      = (const float*)d_in[0];
    const float* fcos   = (const float*)d_in[1];
    const float* fsin   = (const float*)d_in[2];
    const int*   taskid = (const int*)  d_in[3];
    const float* n1w    = (const float*)d_in[4];
    const float* n2w    = (const float*)d_in[5];
    const float* WqT    = (const float*)d_in[6];
    const float* WkT    = (const float*)d_in[7];
    const float* WvT    = (const float*)d_in[8];
    const float* WoT    = (const float*)d_in[9];
    const float* qA     = (const float*)d_in[10];
    const float* qB     = (const float*)d_in[11];
    const float* kA     = (const float*)d_in[12];
    const float* kB     = (const float*)d_in[13];
    const float* vA     = (const float*)d_in[14];
    const float* vB     = (const float*)d_in[15];
    const float* gateWT = (const float*)d_in[16];
    const float* gA     = (const float*)d_in[17];
    const float* gB     = (const float*)d_in[18];
    const float* temb   = (const float*)d_in[19];
    const float* eW1    = (const float*)d_in[20];
    const float* eb1    = (const float*)d_in[21];
    const float* eWg    = (const float*)d_in[22];
    const float* ebg    = (const float*)d_in[23];
    const float* eWv    = (const float*)d_in[24];
    const float* ebv    = (const float*)d_in[25];
    float* out = (float*)d_out;

    float *p_h, *p_WqE, *p_WkE, *p_WvE, *p_gateE, *p_Q, *p_Kb, *p_Vb,
          *p_ctx, *p_xf, *p_xfr, *p_h1, *p_Ge, *p_Ve, *p_W1r, *p_Wgr, *p_Wvr;
    cudaGetSymbolAddress((void**)&p_h,     d_h);
    cudaGetSymbolAddress((void**)&p_WqE,   d_WqE);
    cudaGetSymbolAddress((void**)&p_WkE,   d_WkE);
    cudaGetSymbolAddress((void**)&p_WvE,   d_WvE);
    cudaGetSymbolAddress((void**)&p_gateE, d_gateE);
    cudaGetSymbolAddress((void**)&p_Q,     d_Q);
    cudaGetSymbolAddress((void**)&p_Kb,    d_Kb);
    cudaGetSymbolAddress((void**)&p_Vb,    d_Vb);
    cudaGetSymbolAddress((void**)&p_ctx,   d_ctx);
    cudaGetSymbolAddress((void**)&p_xf,    d_xf);
    cudaGetSymbolAddress((void**)&p_xfr,   d_xfr);
    cudaGetSymbolAddress((void**)&p_h1,    d_h1);
    cudaGetSymbolAddress((void**)&p_Ge,    d_Ge);
    cudaGetSymbolAddress((void**)&p_Ve,    d_Ve);
    cudaGetSymbolAddress((void**)&p_W1r,   d_W1r);
    cudaGetSymbolAddress((void**)&p_Wgr,   d_Wgr);
    cudaGetSymbolAddress((void**)&p_Wvr,   d_Wvr);

    cudaFuncSetAttribute(mma_expert_up,
        cudaFuncAttributeMaxDynamicSharedMemorySize, SMEM_V5_BYTES);
    cudaFuncSetAttribute(mma_expert_gv,
        cudaFuncAttributeMaxDynamicSharedMemorySize, SMEM_V5_BYTES);

    // pre-round expert weights to tf32-rna (exact under HMMA truncation)
    const int n4 = EWELEM / 4;
    round_w_kernel<<<(n4 + 255) / 256, 256>>>((const float4*)eW1, (float4*)p_W1r, n4);
    round_w_kernel<<<(n4 + 255) / 256, 256>>>((const float4*)eWg, (float4*)p_Wgr, n4);
    round_w_kernel<<<(n4 + 255) / 256, 256>>>((const float4*)eWv, (float4*)p_Wvr, n4);

    eff_weight_kernel<<<(DMODEL * DMODEL + 255) / 256, 256>>>(WqT, qA, qB, p_WqE, DMODEL, DMODEL * DMODEL);
    eff_weight_kernel<<<(DMODEL * KVDIM + 255) / 256, 256>>>(WkT, kA, kB, p_WkE, KVDIM, DMODEL * KVDIM);
    eff_weight_kernel<<<(DMODEL * KVDIM + 255) / 256, 256>>>(WvT, vA, vB, p_WvE, KVDIM, DMODEL * KVDIM);
    eff_weight_kernel<<<(DMODEL * NEXP + 255) / 256, 256>>>(gateWT, gA, gB, p_gateE, NEXP, DMODEL * NEXP);

    rmsnorm1_kernel<<<TTOK, 256>>>(x, n1w, p_h);

    // pre-routing path: exact fp32 (routing stability)
    sgemm_plain<<<dim3(DMODEL / BN, TTOK / BM), 256>>>(p_h, DMODEL, p_WqE, DMODEL, nullptr, p_Q, DMODEL, TTOK, DMODEL);
    sgemm_plain<<<dim3(KVDIM / BN, TTOK / BM), 256>>>(p_h, DMODEL, p_WkE, KVDIM, nullptr, p_Kb, KVDIM, TTOK, DMODEL);
    sgemm_plain<<<dim3(KVDIM / BN, TTOK / BM), 256>>>(p_h, DMODEL, p_WvE, KVDIM, nullptr, p_Vb, KVDIM, TTOK, DMODEL);

    rope_kernel<<<TTOK, 512>>>(p_Q, p_Kb, fcos, fsin);

    attn_kernel<<<dim3(SEQ / 64, NHEAD, 2), 64>>>(p_Q, p_Kb, p_Vb, p_ctx);

    sgemm_plain<<<dim3(DMODEL / BN, TTOK / BM), 256>>>(p_ctx, DMODEL, WoT, DMODEL, x, out, DMODEL, TTOK, DMODEL);

    rmsnorm2_kernel<<<TTOK, 256>>>(out, n2w, taskid, temb, p_xf, p_xfr);

    gate_kernel<<<(TTOK * 32 + 255) / 256, 256>>>(p_xf, p_gateE);
    bucket_kernel<<<1, 256>>>();

    // post-routing expert GEMMs: cp.async pipelined, 2 blocks/SM, no cvt
    mma_expert_up<<<dim3(HID / TN, TTOK / TM, NEXP), 256, SMEM_V5_BYTES>>>(
        p_xfr, p_W1r, eb1, p_h1);
    mma_expert_gv<<<dim3(2 * DMODEL / TN, TTOK / TM, NEXP), 256, SMEM_V5_BYTES>>>(
        p_h1, p_Wgr, ebg, p_Wvr, ebv, p_Ge, p_Ve);

    combine_kernel<<<TTOK, 256>>>(p_Ge, p_Ve, out);
}

// round 11
// speedup vs baseline: 1.1587x; 1.1587x over previous
#include <cuda_runtime.h>
#include <cuda_bf16.h>
#include <math.h>

// ---------------- problem constants ----------------
#define DMODEL 1024
#define NHEAD  16
#define NKV    4
#define DK     64
#define NEXP   8
#define TOPK   2
#define RLORA  16
#define SCALE_LORA 2.0f
#define HID    4096
#define TTOK   2048
#define SEQ    1024
#define KVDIM  256
#define NSLOT  (TTOK * TOPK)

// ---------------- scratch ----------------
__device__ float d_h   [TTOK * DMODEL];
__device__ float d_WqE [DMODEL * DMODEL];
__device__ float d_WkE [DMODEL * KVDIM];
__device__ float d_WvE [DMODEL * KVDIM];
__device__ float d_gateE[DMODEL * NEXP];
__device__ float d_Q   [TTOK * DMODEL];
__device__ float d_Kb  [TTOK * KVDIM];
__device__ float d_Vb  [TTOK * KVDIM];
__device__ float d_ctx [TTOK * DMODEL];
__device__ float d_xf  [TTOK * DMODEL];
__device__ float d_h1  [NSLOT * HID];
__device__ float d_Ge  [NSLOT * DMODEL];
__device__ float d_Ve  [NSLOT * DMODEL];
__device__ int   d_top   [NSLOT];
__device__ float d_tw    [NSLOT];
__device__ int   d_pos   [NSLOT];
__device__ int   d_rowof [NSLOT];
__device__ int   d_tokrow[NSLOT];
__device__ int   d_cnt   [NEXP];
__device__ int   d_offs  [NEXP];

// ---------------- small kernels ----------------
__global__ void eff_weight_kernel(const float* __restrict__ WT,
                                  const float* __restrict__ A,
                                  const float* __restrict__ B,
                                  float* __restrict__ out, int N, int total) {
    int i = blockIdx.x * blockDim.x + threadIdx.x;
    if (i >= total) return;
    int k = i / N, n = i - k * N;
    float s = 0.f;
#pragma unroll
    for (int r = 0; r < RLORA; ++r) s += A[k * RLORA + r] * B[r * N + n];
    out[i] = WT[i] + SCALE_LORA * s;
}

__global__ void rmsnorm1_kernel(const float* __restrict__ x,
                                const float* __restrict__ w,
                                float* __restrict__ h) {
    int t = blockIdx.x;
    __shared__ float red[256];
    float ss = 0.f;
    for (int d = threadIdx.x; d < DMODEL; d += 256) {
        float v = x[(size_t)t * DMODEL + d];
        ss += v * v;
    }
    red[threadIdx.x] = ss; __syncthreads();
    for (int s = 128; s > 0; s >>= 1) {
        if (threadIdx.x < s) red[threadIdx.x] += red[threadIdx.x + s];
        __syncthreads();
    }
    float rs = rsqrtf(red[0] / (float)DMODEL + 1e-6f);
    for (int d = threadIdx.x; d < DMODEL; d += 256)
        h[(size_t)t * DMODEL + d] = x[(size_t)t * DMODEL + d] * rs * w[d];
}

__global__ void rmsnorm2_kernel(const float* __restrict__ xin,
                                const float* __restrict__ w,
                                const int* __restrict__ taskid,
                                const float* __restrict__ temb,
                                float* __restrict__ xf) {
    int t = blockIdx.x;
    __shared__ float red[256];
    float ss = 0.f;
    for (int d = threadIdx.x; d < DMODEL; d += 256) {
        float v = xin[(size_t)t * DMODEL + d];
        ss += v * v;
    }
    red[threadIdx.x] = ss; __syncthreads();
    for (int s = 128; s > 0; s >>= 1) {
        if (threadIdx.x < s) red[threadIdx.x] += red[threadIdx.x + s];
        __syncthreads();
    }
    float rs = rsqrtf(red[0] / (float)DMODEL + 1e-6f);
    int tk = taskid[t];
    for (int d = threadIdx.x; d < DMODEL; d += 256)
        xf[(size_t)t * DMODEL + d] =
            xin[(size_t)t * DMODEL + d] * rs * w[d] + temb[tk * DMODEL + d];
}

__global__ void rope_kernel(float* __restrict__ Q, float* __restrict__ K,
                            const float* __restrict__ fcos,
                            const float* __restrict__ fsin) {
    int t = blockIdx.x;
    int s = t & (SEQ - 1);
    int tid = threadIdx.x;
    int h = tid >> 5;
    int d = tid & 31;
    float c1 = fcos[s * DK + d],      s1 = fsin[s * DK + d];
    float c2 = fcos[s * DK + d + 32], s2 = fsin[s * DK + d + 32];
    {
        float* q = Q + (size_t)t * DMODEL + h * DK;
        float x1 = q[d], x2 = q[d + 32];
        q[d]      = x1 * c1 - x2 * s1;
        q[d + 32] = x2 * c2 + x1 * s2;
    }
    if (h < NKV) {
        float* k = K + (size_t)t * KVDIM + h * DK;
        float x1 = k[d], x2 = k[d + 32];
        k[d]      = x1 * c1 - x2 * s1;
        k[d + 32] = x2 * c2 + x1 * s2;
    }
}

// ---------------- fp32 tiled SGEMM: 64x64x16 (Wo / gate-critical path) ------
#define BM 64
#define BN 64
#define BKK 16

__device__ __forceinline__ void sgemm_tile_dev(
    const float* __restrict__ A, int lda,
    const float* __restrict__ B, int ldb,
    const float* __restrict__ Cadd,
    float* __restrict__ C, int ldc,
    int M, int K, int m0, int n0)
{
    __shared__ float As[BKK][BM];
    __shared__ float Bs[BKK][BN];
    const int tid = threadIdx.x;
    const int tx = tid & 15, ty = tid >> 4;
    const int aRow = tid >> 2;
    const int aCol = (tid & 3) * 4;
    const int bRow = tid >> 4;
    const int bCol = (tid & 15) * 4;

    const float* Aptr = A + (size_t)(m0 + aRow) * lda + aCol;
    const float* Bptr = B + (size_t)bRow * ldb + n0 + bCol;

    float acc[4][4];
#pragma unroll
    for (int i = 0; i < 4; ++i)
#pragma unroll
        for (int j = 0; j < 4; ++j) acc[i][j] = 0.f;

    for (int kk = 0; kk < K; kk += BKK) {
        float4 av = *(const float4*)(Aptr + kk);
        float4 bv = *(const float4*)(Bptr + (size_t)kk * ldb);
        __syncthreads();
        As[aCol + 0][aRow] = av.x;
        As[aCol + 1][aRow] = av.y;
        As[aCol + 2][aRow] = av.z;
        As[aCol + 3][aRow] = av.w;
        *(float4*)&Bs[bRow][bCol] = bv;
        __syncthreads();
#pragma unroll
        for (int k = 0; k < BKK; ++k) {
            float4 a = *(const float4*)&As[k][ty * 4];
            float4 b = *(const float4*)&Bs[k][tx * 4];
            acc[0][0] += a.x * b.x; acc[0][1] += a.x * b.y; acc[0][2] += a.x * b.z; acc[0][3] += a.x * b.w;
            acc[1][0] += a.y * b.x; acc[1][1] += a.y * b.y; acc[1][2] += a.y * b.z; acc[1][3] += a.y * b.w;
            acc[2][0] += a.z * b.x; acc[2][1] += a.z * b.y; acc[2][2] += a.z * b.z; acc[2][3] += a.z * b.w;
            acc[3][0] += a.w * b.x; acc[3][1] += a.w * b.y; acc[3][2] += a.w * b.z; acc[3][3] += a.w * b.w;
        }
    }

#pragma unroll
    for (int i = 0; i < 4; ++i) {
        size_t crow = (size_t)(m0 + ty * 4 + i);
#pragma unroll
        for (int j = 0; j < 4; ++j) {
            int c = n0 + tx * 4 + j;
            float v = acc[i][j];
            if (Cadd) v += Cadd[crow * ldc + c];
            C[crow * ldc + c] = v;
        }
    }
}

__global__ __launch_bounds__(256) void sgemm_plain(
    const float* __restrict__ A, int lda,
    const float* __restrict__ B, int ldb,
    const float* __restrict__ Cadd,
    float* __restrict__ C, int ldc, int M, int K)
{
    sgemm_tile_dev(A, lda, B, ldb, Cadd, C, ldc, M, K,
                   blockIdx.y * BM, blockIdx.x * BN);
}

// ---------------- tf32 tensor-core GEMM (R9 tile) ----------------
#define TM 128
#define TN 128
#define TKT 32
#define ASTR 36
#define BSTR 136

__device__ __forceinline__ float tf32r(float f) {
    unsigned u;
    asm("cvt.rna.tf32.f32 %0, %1;" : "=r"(u) : "f"(f));
    return __uint_as_float(u);
}

__device__ __forceinline__ void mma_tf32(float* d, const unsigned* a,
                                         const unsigned* b, const float* c) {
    asm volatile(
        "mma.sync.aligned.m16n8k8.row.col.f32.tf32.tf32.f32 "
        "{%0,%1,%2,%3}, {%4,%5,%6,%7}, {%8,%9}, {%10,%11,%12,%13};"
        : "=f"(d[0]), "=f"(d[1]), "=f"(d[2]), "=f"(d[3])
        : "r"(a[0]), "r"(a[1]), "r"(a[2]), "r"(a[3]),
          "r"(b[0]), "r"(b[1]),
          "f"(c[0]), "f"(c[1]), "f"(c[2]), "f"(c[3]));
}

__device__ __forceinline__ void mma_tile_dev(
    const float* __restrict__ A, int lda,
    const float* __restrict__ B, int ldb,
    const float* __restrict__ bias,
    float* __restrict__ C, int ldc,
    int M, int K,
    const int* __restrict__ gmap,
    int m0, int n0, int cRow0)
{
    __shared__ float Asm[TM][ASTR];
    __shared__ float Bsm[TKT][BSTR];
    const int tid  = threadIdx.x;
    const int lane = tid & 31;
    const int warp = tid >> 5;
    const int wm = (warp & 1) * 64;
    const int wn = (warp >> 1) * 32;
    const int fr = lane >> 2;
    const int fc = lane & 3;

    float acc[4][4][4];
#pragma unroll
    for (int mi = 0; mi < 4; ++mi)
#pragma unroll
        for (int ni = 0; ni < 4; ++ni)
#pragma unroll
            for (int q = 0; q < 4; ++q) acc[mi][ni][q] = 0.f;

    size_t arow[4]; bool avalid[4];
#pragma unroll
    for (int i = 0; i < 4; ++i) {
        int lin = tid + i * 256;
        int r = lin >> 3;
        int gr = m0 + r;
        avalid[i] = gr < M;
        arow[i] = avalid[i] ? (size_t)(gmap ? gmap[gr] : gr) : 0;
    }

    for (int kt = 0; kt < K; kt += TKT) {
        __syncthreads();
#pragma unroll
        for (int i = 0; i < 4; ++i) {
            int lin = tid + i * 256;
            int r  = lin >> 3;
            int kv = (lin & 7) * 4;
            float4 v = make_float4(0.f, 0.f, 0.f, 0.f);
            if (avalid[i]) v = *(const float4*)(A + arow[i] * lda + kt + kv);
            Asm[r][kv + 0] = tf32r(v.x);
            Asm[r][kv + 1] = tf32r(v.y);
            Asm[r][kv + 2] = tf32r(v.z);
            Asm[r][kv + 3] = tf32r(v.w);
        }
#pragma unroll
        for (int i = 0; i < 4; ++i) {
            int lin = tid + i * 256;
            int kr = lin >> 5;
            int nv = (lin & 31) * 4;
            float4 v = *(const float4*)(B + (size_t)(kt + kr) * ldb + n0 + nv);
            Bsm[kr][nv + 0] = tf32r(v.x);
            Bsm[kr][nv + 1] = tf32r(v.y);
            Bsm[kr][nv + 2] = tf32r(v.z);
            Bsm[kr][nv + 3] = tf32r(v.w);
        }
        __syncthreads();
#pragma unroll
        for (int k0 = 0; k0 < TKT; k0 += 8) {
            unsigned af[4][4], bf[4][2];
#pragma unroll
            for (int mi = 0; mi < 4; ++mi) {
                int rb = wm + mi * 16;
                af[mi][0] = __float_as_uint(Asm[rb + fr][k0 + fc]);
                af[mi][1] = __float_as_uint(Asm[rb + fr + 8][k0 + fc]);
                af[mi][2] = __float_as_uint(Asm[rb + fr][k0 + fc + 4]);
                af[mi][3] = __float_as_uint(Asm[rb + fr + 8][k0 + fc + 4]);
            }
#pragma unroll
            for (int ni = 0; ni < 4; ++ni) {
                int nb = wn + ni * 8;
                bf[ni][0] = __float_as_uint(Bsm[k0 + fc][nb + fr]);
                bf[ni][1] = __float_as_uint(Bsm[k0 + fc + 4][nb + fr]);
            }
#pragma unroll
            for (int mi = 0; mi < 4; ++mi)
#pragma unroll
                for (int ni = 0; ni < 4; ++ni)
                    mma_tf32(acc[mi][ni], af[mi], bf[ni], acc[mi][ni]);
        }
    }

    const int cc = (lane & 3) * 2;
#pragma unroll
    for (int mi = 0; mi < 4; ++mi) {
        int rloc0 = m0 + wm + mi * 16 + fr;
        int rloc1 = rloc0 + 8;
#pragma unroll
        for (int ni = 0; ni < 4; ++ni) {
            int col = n0 + wn + ni * 8 + cc;
            float b0 = bias ? bias[col] : 0.f;
            float b1 = bias ? bias[col + 1] : 0.f;
            if (rloc0 < M) {
                size_t cr = (size_t)(cRow0 + rloc0) * ldc;
                C[cr + col]     = acc[mi][ni][0] + b0;
                C[cr + col + 1] = acc[mi][ni][1] + b1;
            }
            if (rloc1 < M) {
                size_t cr = (size_t)(cRow0 + rloc1) * ldc;
                C[cr + col]     = acc[mi][ni][2] + b0;
                C[cr + col + 1] = acc[mi][ni][3] + b1;
            }
        }
    }
}

// plain tf32 GEMM (QKV path — damped ×0.03 before gate, flip-safe)
__global__ __launch_bounds__(256, 2) void mma_plain(
    const float* __restrict__ A, int lda,
    const float* __restrict__ B, int ldb,
    float* __restrict__ C, int ldc, int M, int K)
{
    mma_tile_dev(A, lda, B, ldb, nullptr, C, ldc, M, K,
                 nullptr, blockIdx.y * TM, blockIdx.x * TN, 0);
}

// forced 2 blocks/SM: caps registers at 128 so two CTAs overlap load/compute
__global__ __launch_bounds__(256, 2) void mma_expert(
    const float* __restrict__ A, int lda,
    const float* __restrict__ Ball, size_t bStride, int ldb,
    const float* __restrict__ biasAll, int biasStride,
    float* __restrict__ C, int ldc, int K, int useGather)
{
    int e = blockIdx.z;
    int cnt = d_cnt[e];
    int m0 = blockIdx.y * TM;
    if (m0 >= cnt) return;
    int off = d_offs[e];
    const int* gmap = useGather ? (d_tokrow + off) : nullptr;
    const float* Aeff = useGather ? A : A + (size_t)off * lda;
    mma_tile_dev(Aeff, lda, Ball + (size_t)e * bStride, ldb,
                 biasAll + (size_t)e * biasStride,
                 C, ldc, cnt, K, gmap, m0, blockIdx.x * TN, off);
}

// ---------------- flash attention (fp32, causal, GQA) ----------------
__global__ __launch_bounds__(64) void attn_kernel(
    const float* __restrict__ Q, const float* __restrict__ Kb,
    const float* __restrict__ Vb, float* __restrict__ ctx)
{
    const int qb = blockIdx.x, h = blockIdx.y, b = blockIdx.z;
    const int r = threadIdx.x;
    const int qglob = qb * 64 + r;
    const size_t t = (size_t)b * SEQ + qglob;
    const int kh = h >> 2;

    float q[DK];
    const float* qp = Q + t * DMODEL + h * DK;
#pragma unroll
    for (int d4 = 0; d4 < 16; ++d4) {
        float4 v = *(const float4*)(qp + d4 * 4);
        q[d4 * 4 + 0] = v.x; q[d4 * 4 + 1] = v.y;
        q[d4 * 4 + 2] = v.z; q[d4 * 4 + 3] = v.w;
    }
    float acc[DK];
#pragma unroll
    for (int d = 0; d < DK; ++d) acc[d] = 0.f;
    float mval = -3.4e38f, lsum = 0.f;

    __shared__ float Ksm[64][DK];
    __shared__ float Vsm[64][DK];

    for (int kt = 0; kt <= qb; ++kt) {
        __syncthreads();
        {
            size_t krow = (size_t)b * SEQ + kt * 64 + r;
            const float4* kp = (const float4*)(Kb + krow * KVDIM + kh * DK);
            const float4* vp = (const float4*)(Vb + krow * KVDIM + kh * DK);
#pragma unroll
            for (int c = 0; c < 16; ++c) {
                ((float4*)Ksm[r])[c] = kp[c];
                ((float4*)Vsm[r])[c] = vp[c];
            }
        }
        __syncthreads();
        const int kmax = (kt == qb) ? r : 63;
        for (int c0 = 0; c0 <= kmax; c0 += 16) {
            float s[16];
            float mch = -3.4e38f;
#pragma unroll
            for (int j = 0; j < 16; ++j) {
                int k = c0 + j;
                float dot = 0.f;
                const float4* kr = (const float4*)Ksm[k];
#pragma unroll
                for (int d4 = 0; d4 < 16; ++d4) {
                    float4 kv = kr[d4];
                    dot += q[d4 * 4 + 0] * kv.x + q[d4 * 4 + 1] * kv.y
                         + q[d4 * 4 + 2] * kv.z + q[d4 * 4 + 3] * kv.w;
                }
                s[j] = (k <= kmax) ? dot * 0.125f : -3.4e38f;
                mch = fmaxf(mch, s[j]);
            }
            float mnew = fmaxf(mval, mch);
            float corr = __expf(mval - mnew);
            lsum *= corr;
#pragma unroll
            for (int d = 0; d < DK; ++d) acc[d] *= corr;
#pragma unroll
            for (int j = 0; j < 16; ++j) {
                float p = __expf(s[j] - mnew);
                lsum += p;
                const float4* vr = (const float4*)Vsm[c0 + j];
#pragma unroll
                for (int d4 = 0; d4 < 16; ++d4) {
                    float4 vv = vr[d4];
                    acc[d4 * 4 + 0] += p * vv.x;
                    acc[d4 * 4 + 1] += p * vv.y;
                    acc[d4 * 4 + 2] += p * vv.z;
                    acc[d4 * 4 + 3] += p * vv.w;
                }
            }
            mval = mnew;
        }
    }
    float inv = 1.f / lsum;
    float* op = ctx + t * DMODEL + h * DK;
#pragma unroll
    for (int d = 0; d < DK; ++d) op[d] = acc[d] * inv;
}

// ---------------- gating ----------------
__global__ void gate_kernel(const float* __restrict__ xf,
                            const float* __restrict__ gateE) {
    int warp = (blockIdx.x * blockDim.x + threadIdx.x) >> 5;
    int lane = threadIdx.x & 31;
    if (warp >= TTOK) return;
    int t = warp;
    float acc[NEXP];
#pragma unroll
    for (int e = 0; e < NEXP; ++e) acc[e] = 0.f;
    for (int d = lane; d < DMODEL; d += 32) {
        float xv = xf[(size_t)t * DMODEL + d];
#pragma unroll
        for (int e = 0; e < NEXP; ++e) acc[e] += xv * gateE[d * NEXP + e];
    }
#pragma unroll
    for (int e = 0; e < NEXP; ++e)
#pragma unroll
        for (int o = 16; o > 0; o >>= 1)
            acc[e] += __shfl_xor_sync(0xffffffff, acc[e], o);
    if (lane == 0) {
        int i0 = 0; float v0 = acc[0];
#pragma unroll
        for (int e = 1; e < NEXP; ++e) if (acc[e] > v0) { v0 = acc[e]; i0 = e; }
        int i1 = -1; float v1 = -3.4e38f;
#pragma unroll
        for (int e = 0; e < NEXP; ++e)
            if (e != i0 && acc[e] > v1) { v1 = acc[e]; i1 = e; }
        if (i1 < 0) { i1 = (i0 + 1) & (NEXP - 1); v1 = v0; }
        float w0 = 1.f / (1.f + __expf(v1 - v0));
        float w1 = 1.f - w0;
        d_top[2 * t]     = i0;  d_tw[2 * t]     = w0;
        d_top[2 * t + 1] = i1;  d_tw[2 * t + 1] = w1;
    }
}

__global__ void bucket_kernel() {
    __shared__ int tops[NSLOT];
    __shared__ int cnt[NEXP];
    for (int s = threadIdx.x; s < NSLOT; s += blockDim.x) tops[s] = d_top[s];
    if (threadIdx.x < NEXP) cnt[threadIdx.x] = 0;
    __syncthreads();
    if (threadIdx.x == 0) {
        for (int s = 0; s < NSLOT; ++s) {
            int e = tops[s];
            d_pos[s] = cnt[e]++;
        }
        int o = 0;
        for (int e = 0; e < NEXP; ++e) { d_offs[e] = o; d_cnt[e] = cnt[e]; o += cnt[e]; }
    }
    __syncthreads();
    for (int s = threadIdx.x; s < NSLOT; s += blockDim.x) {
        int e = tops[s];
        int j = d_offs[e] + d_pos[s];
        d_rowof[s] = j;
        d_tokrow[j] = s >> 1;
    }
}

// out[t] += sum_k w_k * silu(Ge[j_k]) * Ve[j_k]   (float4 vectorized)
__global__ void combine_kernel(const float* __restrict__ Ge,
                               const float* __restrict__ Ve,
                               float* __restrict__ out) {
    int t = blockIdx.x;
    int j0 = d_rowof[2 * t],     j1 = d_rowof[2 * t + 1];
    float w0 = d_tw[2 * t],      w1 = d_tw[2 * t + 1];
    const float4* g0p = (const float4*)(Ge + (size_t)j0 * DMODEL);
    const float4* v0p = (const float4*)(Ve + (size_t)j0 * DMODEL);
    const float4* g1p = (const float4*)(Ge + (size_t)j1 * DMODEL);
    const float4* v1p = (const float4*)(Ve + (size_t)j1 * DMODEL);
    float4* op = (float4*)(out + (size_t)t * DMODEL);
    for (int d = threadIdx.x; d < DMODEL / 4; d += blockDim.x) {
        float4 g0 = g0p[d], g1 = g1p[d], v0 = v0p[d], v1 = v1p[d], o = op[d];
        o.x += w0 * (g0.x / (1.f + __expf(-g0.x))) * v0.x + w1 * (g1.x / (1.f + __expf(-g1.x))) * v1.x;
        o.y += w0 * (g0.y / (1.f + __expf(-g0.y))) * v0.y + w1 * (g1.y / (1.f + __expf(-g1.y))) * v1.y;
        o.z += w0 * (g0.z / (1.f + __expf(-g0.z))) * v0.z + w1 * (g1.z / (1.f + __expf(-g1.z))) * v1.z;
        o.w += w0 * (g0.w / (1.f + __expf(-g0.w))) * v0.w + w1 * (g1.w / (1.f + __expf(-g1.w))) * v1.w;
        op[d] = o;
    }
}

// ---------------- launch ----------------
extern "C" void kernel_launch(void* const* d_in, const int* in_sizes, int n_in,
                              void* d_out, int out_size) {
    const float* x      = (const float*)d_in[0];
    const float* fcos   = (const float*)d_in[1];
    const float* fsin   = (const float*)d_in[2];
    const int*   taskid = (const int*)  d_in[3];
    const float* n1w    = (const float*)d_in[4];
    const float* n2w    = (const float*)d_in[5];
    const float* WqT    = (const float*)d_in[6];
    const float* WkT    = (const float*)d_in[7];
    const float* WvT    = (const float*)d_in[8];
    const float* WoT    = (const float*)d_in[9];
    const float* qA     = (const float*)d_in[10];
    const float* qB     = (const float*)d_in[11];
    const float* kA     = (const float*)d_in[12];
    const float* kB     = (const float*)d_in[13];
    const float* vA     = (const float*)d_in[14];
    const float* vB     = (const float*)d_in[15];
    const float* gateWT = (const float*)d_in[16];
    const float* gA     = (const float*)d_in[17];
    const float* gB     = (const float*)d_in[18];
    const float* temb   = (const float*)d_in[19];
    const float* eW1    = (const float*)d_in[20];
    const float* eb1    = (const float*)d_in[21];
    const float* eWg    = (const float*)d_in[22];
    const float* ebg    = (const float*)d_in[23];
    const float* eWv    = (const float*)d_in[24];
    const float* ebv    = (const float*)d_in[25];
    float* out = (float*)d_out;

    float *p_h, *p_WqE, *p_WkE, *p_WvE, *p_gateE, *p_Q, *p_Kb, *p_Vb,
          *p_ctx, *p_xf, *p_h1, *p_Ge, *p_Ve;
    cudaGetSymbolAddress((void**)&p_h,     d_h);
    cudaGetSymbolAddress((void**)&p_WqE,   d_WqE);
    cudaGetSymbolAddress((void**)&p_WkE,   d_WkE);
    cudaGetSymbolAddress((void**)&p_WvE,   d_WvE);
    cudaGetSymbolAddress((void**)&p_gateE, d_gateE);
    cudaGetSymbolAddress((void**)&p_Q,     d_Q);
    cudaGetSymbolAddress((void**)&p_Kb,    d_Kb);
    cudaGetSymbolAddress((void**)&p_Vb,    d_Vb);
    cudaGetSymbolAddress((void**)&p_ctx,   d_ctx);
    cudaGetSymbolAddress((void**)&p_xf,    d_xf);
    cudaGetSymbolAddress((void**)&p_h1,    d_h1);
    cudaGetSymbolAddress((void**)&p_Ge,    d_Ge);
    cudaGetSymbolAddress((void**)&p_Ve,    d_Ve);

    eff_weight_kernel<<<(DMODEL * DMODEL + 255) / 256, 256>>>(WqT, qA, qB, p_WqE, DMODEL, DMODEL * DMODEL);
    eff_weight_kernel<<<(DMODEL * KVDIM + 255) / 256, 256>>>(WkT, kA, kB, p_WkE, KVDIM, DMODEL * KVDIM);
    eff_weight_kernel<<<(DMODEL * KVDIM + 255) / 256, 256>>>(WvT, vA, vB, p_WvE, KVDIM, DMODEL * KVDIM);
    eff_weight_kernel<<<(DMODEL * NEXP + 255) / 256, 256>>>(gateWT, gA, gB, p_gateE, NEXP, DMODEL * NEXP);

    rmsnorm1_kernel<<<TTOK, 256>>>(x, n1w, p_h);

    // QKV: tf32 tensor cores (gate impact damped ~x0.03 via attention)
    mma_plain<<<dim3(DMODEL / TN, TTOK / TM), 256>>>(p_h, DMODEL, p_WqE, DMODEL, p_Q, DMODEL, TTOK, DMODEL);
    mma_plain<<<dim3(KVDIM / TN, TTOK / TM), 256>>>(p_h, DMODEL, p_WkE, KVDIM, p_Kb, KVDIM, TTOK, DMODEL);
    mma_plain<<<dim3(KVDIM / TN, TTOK / TM), 256>>>(p_h, DMODEL, p_WvE, KVDIM, p_Vb, KVDIM, TTOK, DMODEL);

    rope_kernel<<<TTOK, 512>>>(p_Q, p_Kb, fcos, fsin);

    attn_kernel<<<dim3(SEQ / 64, NHEAD, 2), 64>>>(p_Q, p_Kb, p_Vb, p_ctx);

    // Wo stays exact fp32 (direct gate input — routing stability)
    sgemm_plain<<<dim3(DMODEL / BN, TTOK / BM), 256>>>(p_ctx, DMODEL, WoT, DMODEL, x, out, DMODEL, TTOK, DMODEL);

    rmsnorm2_kernel<<<TTOK, 256>>>(out, n2w, taskid, temb, p_xf);

    gate_kernel<<<(TTOK * 32 + 255) / 256, 256>>>(p_xf, p_gateE);
    bucket_kernel<<<1, 256>>>();

    // post-routing expert GEMMs: R9 tile, forced 2 blocks/SM
    mma_expert<<<dim3(HID / TN, TTOK / TM, NEXP), 256>>>(
        p_xf, DMODEL, eW1, (size_t)DMODEL * HID, HID, eb1, HID, p_h1, HID, DMODEL, 1);
    mma_expert<<<dim3(DMODEL / TN, TTOK / TM, NEXP), 256>>>(
        p_h1, HID, eWg, (size_t)HID * DMODEL, DMODEL, ebg, DMODEL, p_Ge, DMODEL, HID, 0);
    mma_expert<<<dim3(DMODEL / TN, TTOK / TM, NEXP), 256>>>(
        p_h1, HID, eWv, (size_t)HID * DMODEL, DMODEL, ebv, DMODEL, p_Ve, DMODEL, HID, 0);

    combine_kernel<<<TTOK, 256>>>(p_Ge, p_Ve, out);
}

// round 12
// speedup vs baseline: 1.1842x; 1.0219x over previous
#include <cuda_runtime.h>
#include <cuda_fp16.h>
#include <cuda_bf16.h>
#include <math.h>

// ---------------- problem constants ----------------
#define DMODEL 1024
#define NHEAD  16
#define NKV    4
#define DK     64
#define NEXP   8
#define TOPK   2
#define RLORA  16
#define SCALE_LORA 2.0f
#define HID    4096
#define TTOK   2048
#define SEQ    1024
#define KVDIM  256
#define NSLOT  (TTOK * TOPK)

// ---------------- scratch ----------------
__device__ float d_h   [TTOK * DMODEL];
__device__ float d_WqE [DMODEL * DMODEL];
__device__ float d_WkE [DMODEL * KVDIM];
__device__ float d_WvE [DMODEL * KVDIM];
__device__ float d_gateE[DMODEL * NEXP];
__device__ float d_Q   [TTOK * DMODEL];
__device__ float d_Kb  [TTOK * KVDIM];
__device__ float d_Vb  [TTOK * KVDIM];
__device__ float d_ctx [TTOK * DMODEL];
__device__ float d_xf  [TTOK * DMODEL];
__device__ float d_h1  [NSLOT * HID];
__device__ float d_Ge  [NSLOT * DMODEL];
__device__ float d_Ve  [NSLOT * DMODEL];
__device__ int   d_top   [NSLOT];
__device__ float d_tw    [NSLOT];
__device__ int   d_pos   [NSLOT];
__device__ int   d_rowof [NSLOT];
__device__ int   d_tokrow[NSLOT];
__device__ int   d_cnt   [NEXP];
__device__ int   d_offs  [NEXP];

// ---------------- small kernels ----------------
__global__ void eff_weight_kernel(const float* __restrict__ WT,
                                  const float* __restrict__ A,
                                  const float* __restrict__ B,
                                  float* __restrict__ out, int N, int total) {
    int i = blockIdx.x * blockDim.x + threadIdx.x;
    if (i >= total) return;
    int k = i / N, n = i - k * N;
    float s = 0.f;
#pragma unroll
    for (int r = 0; r < RLORA; ++r) s += A[k * RLORA + r] * B[r * N + n];
    out[i] = WT[i] + SCALE_LORA * s;
}

__global__ void rmsnorm1_kernel(const float* __restrict__ x,
                                const float* __restrict__ w,
                                float* __restrict__ h) {
    int t = blockIdx.x;
    __shared__ float red[256];
    float ss = 0.f;
    for (int d = threadIdx.x; d < DMODEL; d += 256) {
        float v = x[(size_t)t * DMODEL + d];
        ss += v * v;
    }
    red[threadIdx.x] = ss; __syncthreads();
    for (int s = 128; s > 0; s >>= 1) {
        if (threadIdx.x < s) red[threadIdx.x] += red[threadIdx.x + s];
        __syncthreads();
    }
    float rs = rsqrtf(red[0] / (float)DMODEL + 1e-6f);
    for (int d = threadIdx.x; d < DMODEL; d += 256)
        h[(size_t)t * DMODEL + d] = x[(size_t)t * DMODEL + d] * rs * w[d];
}

__global__ void rmsnorm2_kernel(const float* __restrict__ xin,
                                const float* __restrict__ w,
                                const int* __restrict__ taskid,
                                const float* __restrict__ temb,
                                float* __restrict__ xf) {
    int t = blockIdx.x;
    __shared__ float red[256];
    float ss = 0.f;
    for (int d = threadIdx.x; d < DMODEL; d += 256) {
        float v = xin[(size_t)t * DMODEL + d];
        ss += v * v;
    }
    red[threadIdx.x] = ss; __syncthreads();
    for (int s = 128; s > 0; s >>= 1) {
        if (threadIdx.x < s) red[threadIdx.x] += red[threadIdx.x + s];
        __syncthreads();
    }
    float rs = rsqrtf(red[0] / (float)DMODEL + 1e-6f);
    int tk = taskid[t];
    for (int d = threadIdx.x; d < DMODEL; d += 256)
        xf[(size_t)t * DMODEL + d] =
            xin[(size_t)t * DMODEL + d] * rs * w[d] + temb[tk * DMODEL + d];
}

__global__ void rope_kernel(float* __restrict__ Q, float* __restrict__ K,
                            const float* __restrict__ fcos,
                            const float* __restrict__ fsin) {
    int t = blockIdx.x;
    int s = t & (SEQ - 1);
    int tid = threadIdx.x;
    int h = tid >> 5;
    int d = tid & 31;
    float c1 = fcos[s * DK + d],      s1 = fsin[s * DK + d];
    float c2 = fcos[s * DK + d + 32], s2 = fsin[s * DK + d + 32];
    {
        float* q = Q + (size_t)t * DMODEL + h * DK;
        float x1 = q[d], x2 = q[d + 32];
        q[d]      = x1 * c1 - x2 * s1;
        q[d + 32] = x2 * c2 + x1 * s2;
    }
    if (h < NKV) {
        float* k = K + (size_t)t * KVDIM + h * DK;
        float x1 = k[d], x2 = k[d + 32];
        k[d]      = x1 * c1 - x2 * s1;
        k[d + 32] = x2 * c2 + x1 * s2;
    }
}

// ---------------- fp32 tiled SGEMM: 64x64x16 (Wo / gate-critical path) ------
#define BM 64
#define BN 64
#define BKK 16

__device__ __forceinline__ void sgemm_tile_dev(
    const float* __restrict__ A, int lda,
    const float* __restrict__ B, int ldb,
    const float* __restrict__ Cadd,
    float* __restrict__ C, int ldc,
    int M, int K, int m0, int n0)
{
    __shared__ float As[BKK][BM];
    __shared__ float Bs[BKK][BN];
    const int tid = threadIdx.x;
    const int tx = tid & 15, ty = tid >> 4;
    const int aRow = tid >> 2;
    const int aCol = (tid & 3) * 4;
    const int bRow = tid >> 4;
    const int bCol = (tid & 15) * 4;

    const float* Aptr = A + (size_t)(m0 + aRow) * lda + aCol;
    const float* Bptr = B + (size_t)bRow * ldb + n0 + bCol;

    float acc[4][4];
#pragma unroll
    for (int i = 0; i < 4; ++i)
#pragma unroll
        for (int j = 0; j < 4; ++j) acc[i][j] = 0.f;

    for (int kk = 0; kk < K; kk += BKK) {
        float4 av = *(const float4*)(Aptr + kk);
        float4 bv = *(const float4*)(Bptr + (size_t)kk * ldb);
        __syncthreads();
        As[aCol + 0][aRow] = av.x;
        As[aCol + 1][aRow] = av.y;
        As[aCol + 2][aRow] = av.z;
        As[aCol + 3][aRow] = av.w;
        *(float4*)&Bs[bRow][bCol] = bv;
        __syncthreads();
#pragma unroll
        for (int k = 0; k < BKK; ++k) {
            float4 a = *(const float4*)&As[k][ty * 4];
            float4 b = *(const float4*)&Bs[k][tx * 4];
            acc[0][0] += a.x * b.x; acc[0][1] += a.x * b.y; acc[0][2] += a.x * b.z; acc[0][3] += a.x * b.w;
            acc[1][0] += a.y * b.x; acc[1][1] += a.y * b.y; acc[1][2] += a.y * b.z; acc[1][3] += a.y * b.w;
            acc[2][0] += a.z * b.x; acc[2][1] += a.z * b.y; acc[2][2] += a.z * b.z; acc[2][3] += a.z * b.w;
            acc[3][0] += a.w * b.x; acc[3][1] += a.w * b.y; acc[3][2] += a.w * b.z; acc[3][3] += a.w * b.w;
        }
    }

#pragma unroll
    for (int i = 0; i < 4; ++i) {
        size_t crow = (size_t)(m0 + ty * 4 + i);
#pragma unroll
        for (int j = 0; j < 4; ++j) {
            int c = n0 + tx * 4 + j;
            float v = acc[i][j];
            if (Cadd) v += Cadd[crow * ldc + c];
            C[crow * ldc + c] = v;
        }
    }
}

__global__ __launch_bounds__(256) void sgemm_plain(
    const float* __restrict__ A, int lda,
    const float* __restrict__ B, int ldb,
    const float* __restrict__ Cadd,
    float* __restrict__ C, int ldc, int M, int K)
{
    sgemm_tile_dev(A, lda, B, ldb, Cadd, C, ldc, M, K,
                   blockIdx.y * BM, blockIdx.x * BN);
}

// ---------------- tf32 tensor-core GEMM (QKV path, R11) ----------------
#define TM 128
#define TN 128
#define TKT 32
#define ASTR 36
#define BSTR 136

__device__ __forceinline__ float tf32r(float f) {
    unsigned u;
    asm("cvt.rna.tf32.f32 %0, %1;" : "=r"(u) : "f"(f));
    return __uint_as_float(u);
}

__device__ __forceinline__ void mma_tf32(float* d, const unsigned* a,
                                         const unsigned* b, const float* c) {
    asm volatile(
        "mma.sync.aligned.m16n8k8.row.col.f32.tf32.tf32.f32 "
        "{%0,%1,%2,%3}, {%4,%5,%6,%7}, {%8,%9}, {%10,%11,%12,%13};"
        : "=f"(d[0]), "=f"(d[1]), "=f"(d[2]), "=f"(d[3])
        : "r"(a[0]), "r"(a[1]), "r"(a[2]), "r"(a[3]),
          "r"(b[0]), "r"(b[1]),
          "f"(c[0]), "f"(c[1]), "f"(c[2]), "f"(c[3]));
}

__device__ __forceinline__ void mma_tile_dev(
    const float* __restrict__ A, int lda,
    const float* __restrict__ B, int ldb,
    float* __restrict__ C, int ldc,
    int M, int K, int m0, int n0)
{
    __shared__ float Asm[TM][ASTR];
    __shared__ float Bsm[TKT][BSTR];
    const int tid  = threadIdx.x;
    const int lane = tid & 31;
    const int warp = tid >> 5;
    const int wm = (warp & 1) * 64;
    const int wn = (warp >> 1) * 32;
    const int fr = lane >> 2;
    const int fc = lane & 3;

    float acc[4][4][4];
#pragma unroll
    for (int mi = 0; mi < 4; ++mi)
#pragma unroll
        for (int ni = 0; ni < 4; ++ni)
#pragma unroll
            for (int q = 0; q < 4; ++q) acc[mi][ni][q] = 0.f;

    for (int kt = 0; kt < K; kt += TKT) {
        __syncthreads();
#pragma unroll
        for (int i = 0; i < 4; ++i) {
            int lin = tid + i * 256;
            int r  = lin >> 3;
            int kv = (lin & 7) * 4;
            float4 v = *(const float4*)(A + (size_t)(m0 + r) * lda + kt + kv);
            Asm[r][kv + 0] = tf32r(v.x);
            Asm[r][kv + 1] = tf32r(v.y);
            Asm[r][kv + 2] = tf32r(v.z);
            Asm[r][kv + 3] = tf32r(v.w);
        }
#pragma unroll
        for (int i = 0; i < 4; ++i) {
            int lin = tid + i * 256;
            int kr = lin >> 5;
            int nv = (lin & 31) * 4;
            float4 v = *(const float4*)(B + (size_t)(kt + kr) * ldb + n0 + nv);
            Bsm[kr][nv + 0] = tf32r(v.x);
            Bsm[kr][nv + 1] = tf32r(v.y);
            Bsm[kr][nv + 2] = tf32r(v.z);
            Bsm[kr][nv + 3] = tf32r(v.w);
        }
        __syncthreads();
#pragma unroll
        for (int k0 = 0; k0 < TKT; k0 += 8) {
            unsigned af[4][4], bf[4][2];
#pragma unroll
            for (int mi = 0; mi < 4; ++mi) {
                int rb = wm + mi * 16;
                af[mi][0] = __float_as_uint(Asm[rb + fr][k0 + fc]);
                af[mi][1] = __float_as_uint(Asm[rb + fr + 8][k0 + fc]);
                af[mi][2] = __float_as_uint(Asm[rb + fr][k0 + fc + 4]);
                af[mi][3] = __float_as_uint(Asm[rb + fr + 8][k0 + fc + 4]);
            }
#pragma unroll
            for (int ni = 0; ni < 4; ++ni) {
                int nb = wn + ni * 8;
                bf[ni][0] = __float_as_uint(Bsm[k0 + fc][nb + fr]);
                bf[ni][1] = __float_as_uint(Bsm[k0 + fc + 4][nb + fr]);
            }
#pragma unroll
            for (int mi = 0; mi < 4; ++mi)
#pragma unroll
                for (int ni = 0; ni < 4; ++ni)
                    mma_tf32(acc[mi][ni], af[mi], bf[ni], acc[mi][ni]);
        }
    }

    const int cc = (lane & 3) * 2;
#pragma unroll
    for (int mi = 0; mi < 4; ++mi) {
        int rloc0 = m0 + wm + mi * 16 + fr;
        int rloc1 = rloc0 + 8;
#pragma unroll
        for (int ni = 0; ni < 4; ++ni) {
            int col = n0 + wn + ni * 8 + cc;
            {
                size_t cr = (size_t)rloc0 * ldc;
                C[cr + col]     = acc[mi][ni][0];
                C[cr + col + 1] = acc[mi][ni][1];
            }
            {
                size_t cr = (size_t)rloc1 * ldc;
                C[cr + col]     = acc[mi][ni][2];
                C[cr + col + 1] = acc[mi][ni][3];
            }
        }
    }
}

__global__ __launch_bounds__(256, 2) void mma_plain(
    const float* __restrict__ A, int lda,
    const float* __restrict__ B, int ldb,
    float* __restrict__ C, int ldc, int M, int K)
{
    mma_tile_dev(A, lda, B, ldb, C, ldc, M, K,
                 blockIdx.y * TM, blockIdx.x * TN);
}

// -------- fp16 tensor-core GEMM (expert path): m16n8k16 + ldmatrix ---------
// fp16 has the same 10-bit mantissa as tf32; fp32 accumulate. Operands are
// O(0.02..3) so no range hazard. Halves MMA count and fragment LDS traffic.
#define HASTR 40    // half pitch: 80B rows -> ldmatrix row banks all distinct
#define HBSTR 136   // half pitch: 272B rows -> distinct

__device__ __forceinline__ void ldsm_x4(unsigned& r0, unsigned& r1,
                                        unsigned& r2, unsigned& r3,
                                        unsigned addr) {
    asm volatile("ldmatrix.sync.aligned.m8n8.x4.shared.b16 {%0,%1,%2,%3}, [%4];"
                 : "=r"(r0), "=r"(r1), "=r"(r2), "=r"(r3) : "r"(addr));
}
__device__ __forceinline__ void ldsm_x4_t(unsigned& r0, unsigned& r1,
                                          unsigned& r2, unsigned& r3,
                                          unsigned addr) {
    asm volatile("ldmatrix.sync.aligned.m8n8.x4.trans.shared.b16 {%0,%1,%2,%3}, [%4];"
                 : "=r"(r0), "=r"(r1), "=r"(r2), "=r"(r3) : "r"(addr));
}
__device__ __forceinline__ void mma_f16(float* d, const unsigned* a,
                                        const unsigned* b, const float* c) {
    asm volatile(
        "mma.sync.aligned.m16n8k16.row.col.f32.f16.f16.f32 "
        "{%0,%1,%2,%3}, {%4,%5,%6,%7}, {%8,%9}, {%10,%11,%12,%13};"
        : "=f"(d[0]), "=f"(d[1]), "=f"(d[2]), "=f"(d[3])
        : "r"(a[0]), "r"(a[1]), "r"(a[2]), "r"(a[3]),
          "r"(b[0]), "r"(b[1]),
          "f"(c[0]), "f"(c[1]), "f"(c[2]), "f"(c[3]));
}

__device__ __forceinline__ void hmma_tile_dev(
    const float* __restrict__ A, int lda,
    const float* __restrict__ B, int ldb,
    const float* __restrict__ bias,
    float* __restrict__ C, int ldc,
    int M, int K,
    const int* __restrict__ gmap,
    int m0, int n0, int cRow0)
{
    __shared__ __half AsmH[TM * HASTR];    // 10240 B
    __shared__ __half BsmH[TKT * HBSTR];   //  8704 B

    const int tid  = threadIdx.x;
    const int lane = tid & 31;
    const int warp = tid >> 5;
    const int wm = (warp & 1) * 64;
    const int wn = (warp >> 1) * 32;
    const int fr = lane >> 2;

    // ldmatrix per-lane source rows
    const int lm  = lane >> 3;          // matrix index 0..3
    const int l7  = lane & 7;
    // A x4: row = rb + (lm&1)*8 + l7 ; kcol offset = (lm>>1)*8
    const int aRowOff = (lm & 1) * 8 + l7;
    const int aKOff   = (lm >> 1) * 8;
    // B x4.trans: krow = k0 + (lm&1)*8 + l7 ; ncol = nb + (lm>>1)*8
    const int bKOff = (lm & 1) * 8 + l7;
    const int bNOff = (lm >> 1) * 8;

    float acc[4][4][4];
#pragma unroll
    for (int mi = 0; mi < 4; ++mi)
#pragma unroll
        for (int ni = 0; ni < 4; ++ni)
#pragma unroll
            for (int q = 0; q < 4; ++q) acc[mi][ni][q] = 0.f;

    // loader coordinates
    size_t arow[4]; bool avalid[4];
#pragma unroll
    for (int i = 0; i < 4; ++i) {
        int lin = tid + i * 256;
        int r = lin >> 3;
        int gr = m0 + r;
        avalid[i] = gr < M;
        arow[i] = avalid[i] ? (size_t)(gmap ? gmap[gr] : gr) : 0;
    }

    for (int kt = 0; kt < K; kt += TKT) {
        __syncthreads();
#pragma unroll
        for (int i = 0; i < 4; ++i) {
            int lin = tid + i * 256;
            int r  = lin >> 3;
            int kv = (lin & 7) * 4;
            float4 v = make_float4(0.f, 0.f, 0.f, 0.f);
            if (avalid[i]) v = *(const float4*)(A + arow[i] * lda + kt + kv);
            __half2* dst = (__half2*)&AsmH[r * HASTR + kv];
            dst[0] = __floats2half2_rn(v.x, v.y);
            dst[1] = __floats2half2_rn(v.z, v.w);
        }
#pragma unroll
        for (int i = 0; i < 4; ++i) {
            int lin = tid + i * 256;
            int kr = lin >> 5;
            int nv = (lin & 31) * 4;
            float4 v = *(const float4*)(B + (size_t)(kt + kr) * ldb + n0 + nv);
            __half2* dst = (__half2*)&BsmH[kr * HBSTR + nv];
            dst[0] = __floats2half2_rn(v.x, v.y);
            dst[1] = __floats2half2_rn(v.z, v.w);
        }
        __syncthreads();
#pragma unroll
        for (int k0 = 0; k0 < TKT; k0 += 16) {
            unsigned af[4][4], bf[4][2];
#pragma unroll
            for (int mi = 0; mi < 4; ++mi) {
                int rb = wm + mi * 16;
                unsigned addr = (unsigned)__cvta_generic_to_shared(
                    &AsmH[(rb + aRowOff) * HASTR + k0 + aKOff]);
                ldsm_x4(af[mi][0], af[mi][1], af[mi][2], af[mi][3], addr);
            }
#pragma unroll
            for (int p = 0; p < 2; ++p) {
                int nb = wn + p * 16;
                unsigned addr = (unsigned)__cvta_generic_to_shared(
                    &BsmH[(k0 + bKOff) * HBSTR + nb + bNOff]);
                ldsm_x4_t(bf[2 * p][0], bf[2 * p][1],
                          bf[2 * p + 1][0], bf[2 * p + 1][1], addr);
            }
#pragma unroll
            for (int mi = 0; mi < 4; ++mi)
#pragma unroll
                for (int ni = 0; ni < 4; ++ni)
                    mma_f16(acc[mi][ni], af[mi], bf[ni], acc[mi][ni]);
        }
    }

    const int cc = (lane & 3) * 2;
#pragma unroll
    for (int mi = 0; mi < 4; ++mi) {
        int rloc0 = m0 + wm + mi * 16 + fr;
        int rloc1 = rloc0 + 8;
#pragma unroll
        for (int ni = 0; ni < 4; ++ni) {
            int col = n0 + wn + ni * 8 + cc;
            float b0 = bias ? bias[col] : 0.f;
            float b1 = bias ? bias[col + 1] : 0.f;
            if (rloc0 < M) {
                size_t cr = (size_t)(cRow0 + rloc0) * ldc;
                C[cr + col]     = acc[mi][ni][0] + b0;
                C[cr + col + 1] = acc[mi][ni][1] + b1;
            }
            if (rloc1 < M) {
                size_t cr = (size_t)(cRow0 + rloc1) * ldc;
                C[cr + col]     = acc[mi][ni][2] + b0;
                C[cr + col + 1] = acc[mi][ni][3] + b1;
            }
        }
    }
}

__global__ __launch_bounds__(256, 2) void hmma_expert(
    const float* __restrict__ A, int lda,
    const float* __restrict__ Ball, size_t bStride, int ldb,
    const float* __restrict__ biasAll, int biasStride,
    float* __restrict__ C, int ldc, int K, int useGather)
{
    int e = blockIdx.z;
    int cnt = d_cnt[e];
    int m0 = blockIdx.y * TM;
    if (m0 >= cnt) return;
    int off = d_offs[e];
    const int* gmap = useGather ? (d_tokrow + off) : nullptr;
    const float* Aeff = useGather ? A : A + (size_t)off * lda;
    hmma_tile_dev(Aeff, lda, Ball + (size_t)e * bStride, ldb,
                  biasAll + (size_t)e * biasStride,
                  C, ldc, cnt, K, gmap, m0, blockIdx.x * TN, off);
}

// ---------------- flash attention (fp32, causal, GQA) ----------------
__global__ __launch_bounds__(64) void attn_kernel(
    const float* __restrict__ Q, const float* __restrict__ Kb,
    const float* __restrict__ Vb, float* __restrict__ ctx)
{
    const int qb = blockIdx.x, h = blockIdx.y, b = blockIdx.z;
    const int r = threadIdx.x;
    const int qglob = qb * 64 + r;
    const size_t t = (size_t)b * SEQ + qglob;
    const int kh = h >> 2;

    float q[DK];
    const float* qp = Q + t * DMODEL + h * DK;
#pragma unroll
    for (int d4 = 0; d4 < 16; ++d4) {
        float4 v = *(const float4*)(qp + d4 * 4);
        q[d4 * 4 + 0] = v.x; q[d4 * 4 + 1] = v.y;
        q[d4 * 4 + 2] = v.z; q[d4 * 4 + 3] = v.w;
    }
    float acc[DK];
#pragma unroll
    for (int d = 0; d < DK; ++d) acc[d] = 0.f;
    float mval = -3.4e38f, lsum = 0.f;

    __shared__ float Ksm[64][DK];
    __shared__ float Vsm[64][DK];

    for (int kt = 0; kt <= qb; ++kt) {
        __syncthreads();
        {
            size_t krow = (size_t)b * SEQ + kt * 64 + r;
            const float4* kp = (const float4*)(Kb + krow * KVDIM + kh * DK);
            const float4* vp = (const float4*)(Vb + krow * KVDIM + kh * DK);
#pragma unroll
            for (int c = 0; c < 16; ++c) {
                ((float4*)Ksm[r])[c] = kp[c];
                ((float4*)Vsm[r])[c] = vp[c];
            }
        }
        __syncthreads();
        const int kmax = (kt == qb) ? r : 63;
        for (int c0 = 0; c0 <= kmax; c0 += 16) {
            float s[16];
            float mch = -3.4e38f;
#pragma unroll
            for (int j = 0; j < 16; ++j) {
                int k = c0 + j;
                float dot = 0.f;
                const float4* kr = (const float4*)Ksm[k];
#pragma unroll
                for (int d4 = 0; d4 < 16; ++d4) {
                    float4 kv = kr[d4];
                    dot += q[d4 * 4 + 0] * kv.x + q[d4 * 4 + 1] * kv.y
                         + q[d4 * 4 + 2] * kv.z + q[d4 * 4 + 3] * kv.w;
                }
                s[j] = (k <= kmax) ? dot * 0.125f : -3.4e38f;
                mch = fmaxf(mch, s[j]);
            }
            float mnew = fmaxf(mval, mch);
            float corr = __expf(mval - mnew);
            lsum *= corr;
#pragma unroll
            for (int d = 0; d < DK; ++d) acc[d] *= corr;
#pragma unroll
            for (int j = 0; j < 16; ++j) {
                float p = __expf(s[j] - mnew);
                lsum += p;
                const float4* vr = (const float4*)Vsm[c0 + j];
#pragma unroll
                for (int d4 = 0; d4 < 16; ++d4) {
                    float4 vv = vr[d4];
                    acc[d4 * 4 + 0] += p * vv.x;
                    acc[d4 * 4 + 1] += p * vv.y;
                    acc[d4 * 4 + 2] += p * vv.z;
                    acc[d4 * 4 + 3] += p * vv.w;
                }
            }
            mval = mnew;
        }
    }
    float inv = 1.f / lsum;
    float* op = ctx + t * DMODEL + h * DK;
#pragma unroll
    for (int d = 0; d < DK; ++d) op[d] = acc[d] * inv;
}

// ---------------- gating ----------------
__global__ void gate_kernel(const float* __restrict__ xf,
                            const float* __restrict__ gateE) {
    int warp = (blockIdx.x * blockDim.x + threadIdx.x) >> 5;
    int lane = threadIdx.x & 31;
    if (warp >= TTOK) return;
    int t = warp;
    float acc[NEXP];
#pragma unroll
    for (int e = 0; e < NEXP; ++e) acc[e] = 0.f;
    for (int d = lane; d < DMODEL; d += 32) {
        float xv = xf[(size_t)t * DMODEL + d];
#pragma unroll
        for (int e = 0; e < NEXP; ++e) acc[e] += xv * gateE[d * NEXP + e];
    }
#pragma unroll
    for (int e = 0; e < NEXP; ++e)
#pragma unroll
        for (int o = 16; o > 0; o >>= 1)
            acc[e] += __shfl_xor_sync(0xffffffff, acc[e], o);
    if (lane == 0) {
        int i0 = 0; float v0 = acc[0];
#pragma unroll
        for (int e = 1; e < NEXP; ++e) if (acc[e] > v0) { v0 = acc[e]; i0 = e; }
        int i1 = -1; float v1 = -3.4e38f;
#pragma unroll
        for (int e = 0; e < NEXP; ++e)
            if (e != i0 && acc[e] > v1) { v1 = acc[e]; i1 = e; }
        if (i1 < 0) { i1 = (i0 + 1) & (NEXP - 1); v1 = v0; }
        float w0 = 1.f / (1.f + __expf(v1 - v0));
        float w1 = 1.f - w0;
        d_top[2 * t]     = i0;  d_tw[2 * t]     = w0;
        d_top[2 * t + 1] = i1;  d_tw[2 * t + 1] = w1;
    }
}

__global__ void bucket_kernel() {
    __shared__ int tops[NSLOT];
    __shared__ int cnt[NEXP];
    for (int s = threadIdx.x; s < NSLOT; s += blockDim.x) tops[s] = d_top[s];
    if (threadIdx.x < NEXP) cnt[threadIdx.x] = 0;
    __syncthreads();
    if (threadIdx.x == 0) {
        for (int s = 0; s < NSLOT; ++s) {
            int e = tops[s];
            d_pos[s] = cnt[e]++;
        }
        int o = 0;
        for (int e = 0; e < NEXP; ++e) { d_offs[e] = o; d_cnt[e] = cnt[e]; o += cnt[e]; }
    }
    __syncthreads();
    for (int s = threadIdx.x; s < NSLOT; s += blockDim.x) {
        int e = tops[s];
        int j = d_offs[e] + d_pos[s];
        d_rowof[s] = j;
        d_tokrow[j] = s >> 1;
    }
}

// out[t] += sum_k w_k * silu(Ge[j_k]) * Ve[j_k]   (float4 vectorized)
__global__ void combine_kernel(const float* __restrict__ Ge,
                               const float* __restrict__ Ve,
                               float* __restrict__ out) {
    int t = blockIdx.x;
    int j0 = d_rowof[2 * t],     j1 = d_rowof[2 * t + 1];
    float w0 = d_tw[2 * t],      w1 = d_tw[2 * t + 1];
    const float4* g0p = (const float4*)(Ge + (size_t)j0 * DMODEL);
    const float4* v0p = (const float4*)(Ve + (size_t)j0 * DMODEL);
    const float4* g1p = (const float4*)(Ge + (size_t)j1 * DMODEL);
    const float4* v1p = (const float4*)(Ve + (size_t)j1 * DMODEL);
    float4* op = (float4*)(out + (size_t)t * DMODEL);
    for (int d = threadIdx.x; d < DMODEL / 4; d += blockDim.x) {
        float4 g0 = g0p[d], g1 = g1p[d], v0 = v0p[d], v1 = v1p[d], o = op[d];
        o.x += w0 * (g0.x / (1.f + __expf(-g0.x))) * v0.x + w1 * (g1.x / (1.f + __expf(-g1.x))) * v1.x;
        o.y += w0 * (g0.y / (1.f + __expf(-g0.y))) * v0.y + w1 * (g1.y / (1.f + __expf(-g1.y))) * v1.y;
        o.z += w0 * (g0.z / (1.f + __expf(-g0.z))) * v0.z + w1 * (g1.z / (1.f + __expf(-g1.z))) * v1.z;
        o.w += w0 * (g0.w / (1.f + __expf(-g0.w))) * v0.w + w1 * (g1.w / (1.f + __expf(-g1.w))) * v1.w;
        op[d] = o;
    }
}

// ---------------- launch ----------------
extern "C" void kernel_launch(void* const* d_in, const int* in_sizes, int n_in,
                              void* d_out, int out_size) {
    const float* x      = (const float*)d_in[0];
    const float* fcos   = (const float*)d_in[1];
    const float* fsin   = (const float*)d_in[2];
    const int*   taskid = (const int*)  d_in[3];
    const float* n1w    = (const float*)d_in[4];
    const float* n2w    = (const float*)d_in[5];
    const float* WqT    = (const float*)d_in[6];
    const float* WkT    = (const float*)d_in[7];
    const float* WvT    = (const float*)d_in[8];
    const float* WoT    = (const float*)d_in[9];
    const float* qA     = (const float*)d_in[10];
    const float* qB     = (const float*)d_in[11];
    const float* kA     = (const float*)d_in[12];
    const float* kB     = (const float*)d_in[13];
    const float* vA     = (const float*)d_in[14];
    const float* vB     = (const float*)d_in[15];
    const float* gateWT = (const float*)d_in[16];
    const float* gA     = (const float*)d_in[17];
    const float* gB     = (const float*)d_in[18];
    const float* temb   = (const float*)d_in[19];
    const float* eW1    = (const float*)d_in[20];
    const float* eb1    = (const float*)d_in[21];
    const float* eWg    = (const float*)d_in[22];
    const float* ebg    = (const float*)d_in[23];
    const float* eWv    = (const float*)d_in[24];
    const float* ebv    = (const float*)d_in[25];
    float* out = (float*)d_out;

    float *p_h, *p_WqE, *p_WkE, *p_WvE, *p_gateE, *p_Q, *p_Kb, *p_Vb,
          *p_ctx, *p_xf, *p_h1, *p_Ge, *p_Ve;
    cudaGetSymbolAddress((void**)&p_h,     d_h);
    cudaGetSymbolAddress((void**)&p_WqE,   d_WqE);
    cudaGetSymbolAddress((void**)&p_WkE,   d_WkE);
    cudaGetSymbolAddress((void**)&p_WvE,   d_WvE);
    cudaGetSymbolAddress((void**)&p_gateE, d_gateE);
    cudaGetSymbolAddress((void**)&p_Q,     d_Q);
    cudaGetSymbolAddress((void**)&p_Kb,    d_Kb);
    cudaGetSymbolAddress((void**)&p_Vb,    d_Vb);
    cudaGetSymbolAddress((void**)&p_ctx,   d_ctx);
    cudaGetSymbolAddress((void**)&p_xf,    d_xf);
    cudaGetSymbolAddress((void**)&p_h1,    d_h1);
    cudaGetSymbolAddress((void**)&p_Ge,    d_Ge);
    cudaGetSymbolAddress((void**)&p_Ve,    d_Ve);

    eff_weight_kernel<<<(DMODEL * DMODEL + 255) / 256, 256>>>(WqT, qA, qB, p_WqE, DMODEL, DMODEL * DMODEL);
    eff_weight_kernel<<<(DMODEL * KVDIM + 255) / 256, 256>>>(WkT, kA, kB, p_WkE, KVDIM, DMODEL * KVDIM);
    eff_weight_kernel<<<(DMODEL * KVDIM + 255) / 256, 256>>>(WvT, vA, vB, p_WvE, KVDIM, DMODEL * KVDIM);
    eff_weight_kernel<<<(DMODEL * NEXP + 255) / 256, 256>>>(gateWT, gA, gB, p_gateE, NEXP, DMODEL * NEXP);

    rmsnorm1_kernel<<<TTOK, 256>>>(x, n1w, p_h);

    // QKV: tf32 tensor cores (gate impact damped ~x0.03 via attention)
    mma_plain<<<dim3(DMODEL / TN, TTOK / TM), 256>>>(p_h, DMODEL, p_WqE, DMODEL, p_Q, DMODEL, TTOK, DMODEL);
    mma_plain<<<dim3(KVDIM / TN, TTOK / TM), 256>>>(p_h, DMODEL, p_WkE, KVDIM, p_Kb, KVDIM, TTOK, DMODEL);
    mma_plain<<<dim3(KVDIM / TN, TTOK / TM), 256>>>(p_h, DMODEL, p_WvE, KVDIM, p_Vb, KVDIM, TTOK, DMODEL);

    rope_kernel<<<TTOK, 512>>>(p_Q, p_Kb, fcos, fsin);

    attn_kernel<<<dim3(SEQ / 64, NHEAD, 2), 64>>>(p_Q, p_Kb, p_Vb, p_ctx);

    // Wo stays exact fp32 (direct gate input — routing stability)
    sgemm_plain<<<dim3(DMODEL / BN, TTOK / BM), 256>>>(p_ctx, DMODEL, WoT, DMODEL, x, out, DMODEL, TTOK, DMODEL);

    rmsnorm2_kernel<<<TTOK, 256>>>(out, n2w, taskid, temb, p_xf);

    gate_kernel<<<(TTOK * 32 + 255) / 256, 256>>>(p_xf, p_gateE);
    bucket_kernel<<<1, 256>>>();

    // post-routing expert GEMMs: fp16 tensor cores + ldmatrix
    hmma_expert<<<dim3(HID / TN, TTOK / TM, NEXP), 256>>>(
        p_xf, DMODEL, eW1, (size_t)DMODEL * HID, HID, eb1, HID, p_h1, HID, DMODEL, 1);
    hmma_expert<<<dim3(DMODEL / TN, TTOK / TM, NEXP), 256>>>(
        p_h1, HID, eWg, (size_t)HID * DMODEL, DMODEL, ebg, DMODEL, p_Ge, DMODEL, HID, 0);
    hmma_expert<<<dim3(DMODEL / TN, TTOK / TM, NEXP), 256>>>(
        p_h1, HID, eWv, (size_t)HID * DMODEL, DMODEL, ebv, DMODEL, p_Ve, DMODEL, HID, 0);

    combine_kernel<<<TTOK, 256>>>(p_Ge, p_Ve, out);
}

// round 13
// speedup vs baseline: 1.3544x; 1.1438x over previous
#include <cuda_runtime.h>
#include <cuda_fp16.h>
#include <cuda_bf16.h>
#include <math.h>

// ---------------- problem constants ----------------
#define DMODEL 1024
#define NHEAD  16
#define NKV    4
#define DK     64
#define NEXP   8
#define TOPK   2
#define RLORA  16
#define SCALE_LORA 2.0f
#define HID    4096
#define TTOK   2048
#define SEQ    1024
#define KVDIM  256
#define NSLOT  (TTOK * TOPK)

// ---------------- scratch ----------------
__device__ float d_h   [TTOK * DMODEL];
__device__ float d_WqE [DMODEL * DMODEL];
__device__ float d_WkE [DMODEL * KVDIM];
__device__ float d_WvE [DMODEL * KVDIM];
__device__ float d_gateE[DMODEL * NEXP];
__device__ float d_Q   [TTOK * DMODEL];
__device__ float d_Kb  [TTOK * KVDIM];
__device__ float d_Vb  [TTOK * KVDIM];
__device__ float d_ctx [TTOK * DMODEL];
__device__ float d_xf  [TTOK * DMODEL];
__device__ float d_h1  [NSLOT * HID];
__device__ float d_Ge  [NSLOT * DMODEL];
__device__ float d_Ve  [NSLOT * DMODEL];
__device__ int   d_top   [NSLOT];
__device__ float d_tw    [NSLOT];
__device__ int   d_pos   [NSLOT];
__device__ int   d_rowof [NSLOT];
__device__ int   d_tokrow[NSLOT];
__device__ int   d_cnt   [NEXP];
__device__ int   d_offs  [NEXP];

// ---------------- small kernels ----------------
__global__ void eff_weight_kernel(const float* __restrict__ WT,
                                  const float* __restrict__ A,
                                  const float* __restrict__ B,
                                  float* __restrict__ out, int N, int total) {
    int i = blockIdx.x * blockDim.x + threadIdx.x;
    if (i >= total) return;
    int k = i / N, n = i - k * N;
    float s = 0.f;
#pragma unroll
    for (int r = 0; r < RLORA; ++r) s += A[k * RLORA + r] * B[r * N + n];
    out[i] = WT[i] + SCALE_LORA * s;
}

__global__ void rmsnorm1_kernel(const float* __restrict__ x,
                                const float* __restrict__ w,
                                float* __restrict__ h) {
    int t = blockIdx.x;
    __shared__ float red[256];
    float ss = 0.f;
    for (int d = threadIdx.x; d < DMODEL; d += 256) {
        float v = x[(size_t)t * DMODEL + d];
        ss += v * v;
    }
    red[threadIdx.x] = ss; __syncthreads();
    for (int s = 128; s > 0; s >>= 1) {
        if (threadIdx.x < s) red[threadIdx.x] += red[threadIdx.x + s];
        __syncthreads();
    }
    float rs = rsqrtf(red[0] / (float)DMODEL + 1e-6f);
    for (int d = threadIdx.x; d < DMODEL; d += 256)
        h[(size_t)t * DMODEL + d] = x[(size_t)t * DMODEL + d] * rs * w[d];
}

__global__ void rmsnorm2_kernel(const float* __restrict__ xin,
                                const float* __restrict__ w,
                                const int* __restrict__ taskid,
                                const float* __restrict__ temb,
                                float* __restrict__ xf) {
    int t = blockIdx.x;
    __shared__ float red[256];
    float ss = 0.f;
    for (int d = threadIdx.x; d < DMODEL; d += 256) {
        float v = xin[(size_t)t * DMODEL + d];
        ss += v * v;
    }
    red[threadIdx.x] = ss; __syncthreads();
    for (int s = 128; s > 0; s >>= 1) {
        if (threadIdx.x < s) red[threadIdx.x] += red[threadIdx.x + s];
        __syncthreads();
    }
    float rs = rsqrtf(red[0] / (float)DMODEL + 1e-6f);
    int tk = taskid[t];
    for (int d = threadIdx.x; d < DMODEL; d += 256)
        xf[(size_t)t * DMODEL + d] =
            xin[(size_t)t * DMODEL + d] * rs * w[d] + temb[tk * DMODEL + d];
}

__global__ void rope_kernel(float* __restrict__ Q, float* __restrict__ K,
                            const float* __restrict__ fcos,
                            const float* __restrict__ fsin) {
    int t = blockIdx.x;
    int s = t & (SEQ - 1);
    int tid = threadIdx.x;
    int h = tid >> 5;
    int d = tid & 31;
    float c1 = fcos[s * DK + d],      s1 = fsin[s * DK + d];
    float c2 = fcos[s * DK + d + 32], s2 = fsin[s * DK + d + 32];
    {
        float* q = Q + (size_t)t * DMODEL + h * DK;
        float x1 = q[d], x2 = q[d + 32];
        q[d]      = x1 * c1 - x2 * s1;
        q[d + 32] = x2 * c2 + x1 * s2;
    }
    if (h < NKV) {
        float* k = K + (size_t)t * KVDIM + h * DK;
        float x1 = k[d], x2 = k[d + 32];
        k[d]      = x1 * c1 - x2 * s1;
        k[d + 32] = x2 * c2 + x1 * s2;
    }
}

// ---------------- fp32 tiled SGEMM: 64x64x16 (Wo / gate-critical path) ------
#define BM 64
#define BN 64
#define BKK 16

__device__ __forceinline__ void sgemm_tile_dev(
    const float* __restrict__ A, int lda,
    const float* __restrict__ B, int ldb,
    const float* __restrict__ Cadd,
    float* __restrict__ C, int ldc,
    int M, int K, int m0, int n0)
{
    __shared__ float As[BKK][BM];
    __shared__ float Bs[BKK][BN];
    const int tid = threadIdx.x;
    const int tx = tid & 15, ty = tid >> 4;
    const int aRow = tid >> 2;
    const int aCol = (tid & 3) * 4;
    const int bRow = tid >> 4;
    const int bCol = (tid & 15) * 4;

    const float* Aptr = A + (size_t)(m0 + aRow) * lda + aCol;
    const float* Bptr = B + (size_t)bRow * ldb + n0 + bCol;

    float acc[4][4];
#pragma unroll
    for (int i = 0; i < 4; ++i)
#pragma unroll
        for (int j = 0; j < 4; ++j) acc[i][j] = 0.f;

    for (int kk = 0; kk < K; kk += BKK) {
        float4 av = *(const float4*)(Aptr + kk);
        float4 bv = *(const float4*)(Bptr + (size_t)kk * ldb);
        __syncthreads();
        As[aCol + 0][aRow] = av.x;
        As[aCol + 1][aRow] = av.y;
        As[aCol + 2][aRow] = av.z;
        As[aCol + 3][aRow] = av.w;
        *(float4*)&Bs[bRow][bCol] = bv;
        __syncthreads();
#pragma unroll
        for (int k = 0; k < BKK; ++k) {
            float4 a = *(const float4*)&As[k][ty * 4];
            float4 b = *(const float4*)&Bs[k][tx * 4];
            acc[0][0] += a.x * b.x; acc[0][1] += a.x * b.y; acc[0][2] += a.x * b.z; acc[0][3] += a.x * b.w;
            acc[1][0] += a.y * b.x; acc[1][1] += a.y * b.y; acc[1][2] += a.y * b.z; acc[1][3] += a.y * b.w;
            acc[2][0] += a.z * b.x; acc[2][1] += a.z * b.y; acc[2][2] += a.z * b.z; acc[2][3] += a.z * b.w;
            acc[3][0] += a.w * b.x; acc[3][1] += a.w * b.y; acc[3][2] += a.w * b.z; acc[3][3] += a.w * b.w;
        }
    }

#pragma unroll
    for (int i = 0; i < 4; ++i) {
        size_t crow = (size_t)(m0 + ty * 4 + i);
#pragma unroll
        for (int j = 0; j < 4; ++j) {
            int c = n0 + tx * 4 + j;
            float v = acc[i][j];
            if (Cadd) v += Cadd[crow * ldc + c];
            C[crow * ldc + c] = v;
        }
    }
}

__global__ __launch_bounds__(256) void sgemm_plain(
    const float* __restrict__ A, int lda,
    const float* __restrict__ B, int ldb,
    const float* __restrict__ Cadd,
    float* __restrict__ C, int ldc, int M, int K)
{
    sgemm_tile_dev(A, lda, B, ldb, Cadd, C, ldc, M, K,
                   blockIdx.y * BM, blockIdx.x * BN);
}

// ---------------- tf32 tensor-core GEMM (QKV path, R11) ----------------
#define TM 128
#define TN 128
#define TKT 32
#define ASTR 36
#define BSTR 136

__device__ __forceinline__ float tf32r(float f) {
    unsigned u;
    asm("cvt.rna.tf32.f32 %0, %1;" : "=r"(u) : "f"(f));
    return __uint_as_float(u);
}

__device__ __forceinline__ void mma_tf32(float* d, const unsigned* a,
                                         const unsigned* b, const float* c) {
    asm volatile(
        "mma.sync.aligned.m16n8k8.row.col.f32.tf32.tf32.f32 "
        "{%0,%1,%2,%3}, {%4,%5,%6,%7}, {%8,%9}, {%10,%11,%12,%13};"
        : "=f"(d[0]), "=f"(d[1]), "=f"(d[2]), "=f"(d[3])
        : "r"(a[0]), "r"(a[1]), "r"(a[2]), "r"(a[3]),
          "r"(b[0]), "r"(b[1]),
          "f"(c[0]), "f"(c[1]), "f"(c[2]), "f"(c[3]));
}

__device__ __forceinline__ void mma_tile_dev(
    const float* __restrict__ A, int lda,
    const float* __restrict__ B, int ldb,
    float* __restrict__ C, int ldc,
    int M, int K, int m0, int n0)
{
    __shared__ float Asm[TM][ASTR];
    __shared__ float Bsm[TKT][BSTR];
    const int tid  = threadIdx.x;
    const int lane = tid & 31;
    const int warp = tid >> 5;
    const int wm = (warp & 1) * 64;
    const int wn = (warp >> 1) * 32;
    const int fr = lane >> 2;
    const int fc = lane & 3;

    float acc[4][4][4];
#pragma unroll
    for (int mi = 0; mi < 4; ++mi)
#pragma unroll
        for (int ni = 0; ni < 4; ++ni)
#pragma unroll
            for (int q = 0; q < 4; ++q) acc[mi][ni][q] = 0.f;

    for (int kt = 0; kt < K; kt += TKT) {
        __syncthreads();
#pragma unroll
        for (int i = 0; i < 4; ++i) {
            int lin = tid + i * 256;
            int r  = lin >> 3;
            int kv = (lin & 7) * 4;
            float4 v = *(const float4*)(A + (size_t)(m0 + r) * lda + kt + kv);
            Asm[r][kv + 0] = tf32r(v.x);
            Asm[r][kv + 1] = tf32r(v.y);
            Asm[r][kv + 2] = tf32r(v.z);
            Asm[r][kv + 3] = tf32r(v.w);
        }
#pragma unroll
        for (int i = 0; i < 4; ++i) {
            int lin = tid + i * 256;
            int kr = lin >> 5;
            int nv = (lin & 31) * 4;
            float4 v = *(const float4*)(B + (size_t)(kt + kr) * ldb + n0 + nv);
            Bsm[kr][nv + 0] = tf32r(v.x);
            Bsm[kr][nv + 1] = tf32r(v.y);
            Bsm[kr][nv + 2] = tf32r(v.z);
            Bsm[kr][nv + 3] = tf32r(v.w);
        }
        __syncthreads();
#pragma unroll
        for (int k0 = 0; k0 < TKT; k0 += 8) {
            unsigned af[4][4], bf[4][2];
#pragma unroll
            for (int mi = 0; mi < 4; ++mi) {
                int rb = wm + mi * 16;
                af[mi][0] = __float_as_uint(Asm[rb + fr][k0 + fc]);
                af[mi][1] = __float_as_uint(Asm[rb + fr + 8][k0 + fc]);
                af[mi][2] = __float_as_uint(Asm[rb + fr][k0 + fc + 4]);
                af[mi][3] = __float_as_uint(Asm[rb + fr + 8][k0 + fc + 4]);
            }
#pragma unroll
            for (int ni = 0; ni < 4; ++ni) {
                int nb = wn + ni * 8;
                bf[ni][0] = __float_as_uint(Bsm[k0 + fc][nb + fr]);
                bf[ni][1] = __float_as_uint(Bsm[k0 + fc + 4][nb + fr]);
            }
#pragma unroll
            for (int mi = 0; mi < 4; ++mi)
#pragma unroll
                for (int ni = 0; ni < 4; ++ni)
                    mma_tf32(acc[mi][ni], af[mi], bf[ni], acc[mi][ni]);
        }
    }

    const int cc = (lane & 3) * 2;
#pragma unroll
    for (int mi = 0; mi < 4; ++mi) {
        int rloc0 = m0 + wm + mi * 16 + fr;
        int rloc1 = rloc0 + 8;
#pragma unroll
        for (int ni = 0; ni < 4; ++ni) {
            int col = n0 + wn + ni * 8 + cc;
            {
                size_t cr = (size_t)rloc0 * ldc;
                C[cr + col]     = acc[mi][ni][0];
                C[cr + col + 1] = acc[mi][ni][1];
            }
            {
                size_t cr = (size_t)rloc1 * ldc;
                C[cr + col]     = acc[mi][ni][2];
                C[cr + col + 1] = acc[mi][ni][3];
            }
        }
    }
}

__global__ __launch_bounds__(256, 2) void mma_plain(
    const float* __restrict__ A, int lda,
    const float* __restrict__ B, int ldb,
    float* __restrict__ C, int ldc, int M, int K)
{
    mma_tile_dev(A, lda, B, ldb, C, ldc, M, K,
                 blockIdx.y * TM, blockIdx.x * TN);
}

// -------- fp16 expert GEMM: m16n8k16 + ldmatrix + REGISTER PREFETCH --------
#define HASTR 40    // half pitch: 80B rows -> ldmatrix row banks all distinct
#define HBSTR 136   // half pitch: 272B rows -> distinct

__device__ __forceinline__ void ldsm_x4(unsigned& r0, unsigned& r1,
                                        unsigned& r2, unsigned& r3,
                                        unsigned addr) {
    asm volatile("ldmatrix.sync.aligned.m8n8.x4.shared.b16 {%0,%1,%2,%3}, [%4];"
                 : "=r"(r0), "=r"(r1), "=r"(r2), "=r"(r3) : "r"(addr));
}
__device__ __forceinline__ void ldsm_x4_t(unsigned& r0, unsigned& r1,
                                          unsigned& r2, unsigned& r3,
                                          unsigned addr) {
    asm volatile("ldmatrix.sync.aligned.m8n8.x4.trans.shared.b16 {%0,%1,%2,%3}, [%4];"
                 : "=r"(r0), "=r"(r1), "=r"(r2), "=r"(r3) : "r"(addr));
}
__device__ __forceinline__ void mma_f16(float* d, const unsigned* a,
                                        const unsigned* b, const float* c) {
    asm volatile(
        "mma.sync.aligned.m16n8k16.row.col.f32.f16.f16.f32 "
        "{%0,%1,%2,%3}, {%4,%5,%6,%7}, {%8,%9}, {%10,%11,%12,%13};"
        : "=f"(d[0]), "=f"(d[1]), "=f"(d[2]), "=f"(d[3])
        : "r"(a[0]), "r"(a[1]), "r"(a[2]), "r"(a[3]),
          "r"(b[0]), "r"(b[1]),
          "f"(c[0]), "f"(c[1]), "f"(c[2]), "f"(c[3]));
}

__device__ __forceinline__ void hmma_tile_dev(
    const float* __restrict__ A, int lda,
    const float* __restrict__ B, int ldb,
    const float* __restrict__ bias,
    float* __restrict__ C, int ldc,
    int M, int K,
    const int* __restrict__ gmap,
    int m0, int n0, int cRow0)
{
    __shared__ __half AsmH[TM * HASTR];    // 10240 B
    __shared__ __half BsmH[TKT * HBSTR];   //  8704 B

    const int tid  = threadIdx.x;
    const int lane = tid & 31;
    const int warp = tid >> 5;
    const int wm = (warp & 1) * 64;
    const int wn = (warp >> 1) * 32;
    const int fr = lane >> 2;

    const int lm  = lane >> 3;
    const int l7  = lane & 7;
    const int aRowOff = (lm & 1) * 8 + l7;
    const int aKOff   = (lm >> 1) * 8;
    const int bKOff = (lm & 1) * 8 + l7;
    const int bNOff = (lm >> 1) * 8;

    float acc[4][4][4];
#pragma unroll
    for (int mi = 0; mi < 4; ++mi)
#pragma unroll
        for (int ni = 0; ni < 4; ++ni)
#pragma unroll
            for (int q = 0; q < 4; ++q) acc[mi][ni][q] = 0.f;

    // loader coordinates (fixed across K)
    int aR[4], aKV[4]; bool avalid[4]; size_t arow[4];
    int bKR[4], bNV[4];
#pragma unroll
    for (int i = 0; i < 4; ++i) {
        int lin = tid + i * 256;
        aR[i]  = lin >> 3;
        aKV[i] = (lin & 7) * 4;
        int gr = m0 + aR[i];
        avalid[i] = gr < M;
        arow[i] = avalid[i] ? (size_t)(gmap ? gmap[gr] : gr) : 0;
        bKR[i] = lin >> 5;
        bNV[i] = (lin & 31) * 4;
    }

    // register prefetch buffers (32 regs)
    float4 avP[4], bvP[4];
    auto prefetch = [&](int kt) {
#pragma unroll
        for (int i = 0; i < 4; ++i)
            avP[i] = avalid[i] ? *(const float4*)(A + arow[i] * lda + kt + aKV[i])
                               : make_float4(0.f, 0.f, 0.f, 0.f);
#pragma unroll
        for (int i = 0; i < 4; ++i)
            bvP[i] = *(const float4*)(B + (size_t)(kt + bKR[i]) * ldb + n0 + bNV[i]);
    };

    prefetch(0);

    for (int kt = 0; kt < K; kt += TKT) {
        __syncthreads();   // previous compute done; smem free
#pragma unroll
        for (int i = 0; i < 4; ++i) {
            __half2* dst = (__half2*)&AsmH[aR[i] * HASTR + aKV[i]];
            dst[0] = __floats2half2_rn(avP[i].x, avP[i].y);
            dst[1] = __floats2half2_rn(avP[i].z, avP[i].w);
        }
#pragma unroll
        for (int i = 0; i < 4; ++i) {
            __half2* dst = (__half2*)&BsmH[bKR[i] * HBSTR + bNV[i]];
            dst[0] = __floats2half2_rn(bvP[i].x, bvP[i].y);
            dst[1] = __floats2half2_rn(bvP[i].z, bvP[i].w);
        }
        __syncthreads();   // smem ready

        if (kt + TKT < K) prefetch(kt + TKT);   // LDGs overlap the MMA work

#pragma unroll
        for (int k0 = 0; k0 < TKT; k0 += 16) {
            unsigned af[4][4], bf[4][2];
#pragma unroll
            for (int mi = 0; mi < 4; ++mi) {
                int rb = wm + mi * 16;
                unsigned addr = (unsigned)__cvta_generic_to_shared(
                    &AsmH[(rb + aRowOff) * HASTR + k0 + aKOff]);
                ldsm_x4(af[mi][0], af[mi][1], af[mi][2], af[mi][3], addr);
            }
#pragma unroll
            for (int p = 0; p < 2; ++p) {
                int nb = wn + p * 16;
                unsigned addr = (unsigned)__cvta_generic_to_shared(
                    &BsmH[(k0 + bKOff) * HBSTR + nb + bNOff]);
                ldsm_x4_t(bf[2 * p][0], bf[2 * p][1],
                          bf[2 * p + 1][0], bf[2 * p + 1][1], addr);
            }
#pragma unroll
            for (int mi = 0; mi < 4; ++mi)
#pragma unroll
                for (int ni = 0; ni < 4; ++ni)
                    mma_f16(acc[mi][ni], af[mi], bf[ni], acc[mi][ni]);
        }
    }

    const int cc = (lane & 3) * 2;
#pragma unroll
    for (int mi = 0; mi < 4; ++mi) {
        int rloc0 = m0 + wm + mi * 16 + fr;
        int rloc1 = rloc0 + 8;
#pragma unroll
        for (int ni = 0; ni < 4; ++ni) {
            int col = n0 + wn + ni * 8 + cc;
            float b0 = bias ? bias[col] : 0.f;
            float b1 = bias ? bias[col + 1] : 0.f;
            if (rloc0 < M) {
                size_t cr = (size_t)(cRow0 + rloc0) * ldc;
                C[cr + col]     = acc[mi][ni][0] + b0;
                C[cr + col + 1] = acc[mi][ni][1] + b1;
            }
            if (rloc1 < M) {
                size_t cr = (size_t)(cRow0 + rloc1) * ldc;
                C[cr + col]     = acc[mi][ni][2] + b0;
                C[cr + col + 1] = acc[mi][ni][3] + b1;
            }
        }
    }
}

__global__ __launch_bounds__(256, 2) void hmma_expert(
    const float* __restrict__ A, int lda,
    const float* __restrict__ Ball, size_t bStride, int ldb,
    const float* __restrict__ biasAll, int biasStride,
    float* __restrict__ C, int ldc, int K, int useGather)
{
    int e = blockIdx.z;
    int cnt = d_cnt[e];
    int m0 = blockIdx.y * TM;
    if (m0 >= cnt) return;
    int off = d_offs[e];
    const int* gmap = useGather ? (d_tokrow + off) : nullptr;
    const float* Aeff = useGather ? A : A + (size_t)off * lda;
    hmma_tile_dev(Aeff, lda, Ball + (size_t)e * bStride, ldb,
                  biasAll + (size_t)e * biasStride,
                  C, ldc, cnt, K, gmap, m0, blockIdx.x * TN, off);
}

// ---------------- flash attention (fp32, causal, GQA) ----------------
__global__ __launch_bounds__(64) void attn_kernel(
    const float* __restrict__ Q, const float* __restrict__ Kb,
    const float* __restrict__ Vb, float* __restrict__ ctx)
{
    const int qb = blockIdx.x, h = blockIdx.y, b = blockIdx.z;
    const int r = threadIdx.x;
    const int qglob = qb * 64 + r;
    const size_t t = (size_t)b * SEQ + qglob;
    const int kh = h >> 2;

    float q[DK];
    const float* qp = Q + t * DMODEL + h * DK;
#pragma unroll
    for (int d4 = 0; d4 < 16; ++d4) {
        float4 v = *(const float4*)(qp + d4 * 4);
        q[d4 * 4 + 0] = v.x; q[d4 * 4 + 1] = v.y;
        q[d4 * 4 + 2] = v.z; q[d4 * 4 + 3] = v.w;
    }
    float acc[DK];
#pragma unroll
    for (int d = 0; d < DK; ++d) acc[d] = 0.f;
    float mval = -3.4e38f, lsum = 0.f;

    __shared__ float Ksm[64][DK];
    __shared__ float Vsm[64][DK];

    for (int kt = 0; kt <= qb; ++kt) {
        __syncthreads();
        {
            size_t krow = (size_t)b * SEQ + kt * 64 + r;
            const float4* kp = (const float4*)(Kb + krow * KVDIM + kh * DK);
            const float4* vp = (const float4*)(Vb + krow * KVDIM + kh * DK);
#pragma unroll
            for (int c = 0; c < 16; ++c) {
                ((float4*)Ksm[r])[c] = kp[c];
                ((float4*)Vsm[r])[c] = vp[c];
            }
        }
        __syncthreads();
        const int kmax = (kt == qb) ? r : 63;
        for (int c0 = 0; c0 <= kmax; c0 += 16) {
            float s[16];
            float mch = -3.4e38f;
#pragma unroll
            for (int j = 0; j < 16; ++j) {
                int k = c0 + j;
                float dot = 0.f;
                const float4* kr = (const float4*)Ksm[k];
#pragma unroll
                for (int d4 = 0; d4 < 16; ++d4) {
                    float4 kv = kr[d4];
                    dot += q[d4 * 4 + 0] * kv.x + q[d4 * 4 + 1] * kv.y
                         + q[d4 * 4 + 2] * kv.z + q[d4 * 4 + 3] * kv.w;
                }
                s[j] = (k <= kmax) ? dot * 0.125f : -3.4e38f;
                mch = fmaxf(mch, s[j]);
            }
            float mnew = fmaxf(mval, mch);
            float corr = __expf(mval - mnew);
            lsum *= corr;
#pragma unroll
            for (int d = 0; d < DK; ++d) acc[d] *= corr;
#pragma unroll
            for (int j = 0; j < 16; ++j) {
                float p = __expf(s[j] - mnew);
                lsum += p;
                const float4* vr = (const float4*)Vsm[c0 + j];
#pragma unroll
                for (int d4 = 0; d4 < 16; ++d4) {
                    float4 vv = vr[d4];
                    acc[d4 * 4 + 0] += p * vv.x;
                    acc[d4 * 4 + 1] += p * vv.y;
                    acc[d4 * 4 + 2] += p * vv.z;
                    acc[d4 * 4 + 3] += p * vv.w;
                }
            }
            mval = mnew;
        }
    }
    float inv = 1.f / lsum;
    float* op = ctx + t * DMODEL + h * DK;
#pragma unroll
    for (int d = 0; d < DK; ++d) op[d] = acc[d] * inv;
}

// ---------------- gating ----------------
__global__ void gate_kernel(const float* __restrict__ xf,
                            const float* __restrict__ gateE) {
    int warp = (blockIdx.x * blockDim.x + threadIdx.x) >> 5;
    int lane = threadIdx.x & 31;
    if (warp >= TTOK) return;
    int t = warp;
    float acc[NEXP];
#pragma unroll
    for (int e = 0; e < NEXP; ++e) acc[e] = 0.f;
    for (int d = lane; d < DMODEL; d += 32) {
        float xv = xf[(size_t)t * DMODEL + d];
#pragma unroll
        for (int e = 0; e < NEXP; ++e) acc[e] += xv * gateE[d * NEXP + e];
    }
#pragma unroll
    for (int e = 0; e < NEXP; ++e)
#pragma unroll
        for (int o = 16; o > 0; o >>= 1)
            acc[e] += __shfl_xor_sync(0xffffffff, acc[e], o);
    if (lane == 0) {
        int i0 = 0; float v0 = acc[0];
#pragma unroll
        for (int e = 1; e < NEXP; ++e) if (acc[e] > v0) { v0 = acc[e]; i0 = e; }
        int i1 = -1; float v1 = -3.4e38f;
#pragma unroll
        for (int e = 0; e < NEXP; ++e)
            if (e != i0 && acc[e] > v1) { v1 = acc[e]; i1 = e; }
        if (i1 < 0) { i1 = (i0 + 1) & (NEXP - 1); v1 = v0; }
        float w0 = 1.f / (1.f + __expf(v1 - v0));
        float w1 = 1.f - w0;
        d_top[2 * t]     = i0;  d_tw[2 * t]     = w0;
        d_top[2 * t + 1] = i1;  d_tw[2 * t + 1] = w1;
    }
}

__global__ void bucket_kernel() {
    __shared__ int tops[NSLOT];
    __shared__ int cnt[NEXP];
    for (int s = threadIdx.x; s < NSLOT; s += blockDim.x) tops[s] = d_top[s];
    if (threadIdx.x < NEXP) cnt[threadIdx.x] = 0;
    __syncthreads();
    if (threadIdx.x == 0) {
        for (int s = 0; s < NSLOT; ++s) {
            int e = tops[s];
            d_pos[s] = cnt[e]++;
        }
        int o = 0;
        for (int e = 0; e < NEXP; ++e) { d_offs[e] = o; d_cnt[e] = cnt[e]; o += cnt[e]; }
    }
    __syncthreads();
    for (int s = threadIdx.x; s < NSLOT; s += blockDim.x) {
        int e = tops[s];
        int j = d_offs[e] + d_pos[s];
        d_rowof[s] = j;
        d_tokrow[j] = s >> 1;
    }
}

// out[t] += sum_k w_k * silu(Ge[j_k]) * Ve[j_k]   (float4 vectorized)
__global__ void combine_kernel(const float* __restrict__ Ge,
                               const float* __restrict__ Ve,
                               float* __restrict__ out) {
    int t = blockIdx.x;
    int j0 = d_rowof[2 * t],     j1 = d_rowof[2 * t + 1];
    float w0 = d_tw[2 * t],      w1 = d_tw[2 * t + 1];
    const float4* g0p = (const float4*)(Ge + (size_t)j0 * DMODEL);
    const float4* v0p = (const float4*)(Ve + (size_t)j0 * DMODEL);
    const float4* g1p = (const float4*)(Ge + (size_t)j1 * DMODEL);
    const float4* v1p = (const float4*)(Ve + (size_t)j1 * DMODEL);
    float4* op = (float4*)(out + (size_t)t * DMODEL);
    for (int d = threadIdx.x; d < DMODEL / 4; d += blockDim.x) {
        float4 g0 = g0p[d], g1 = g1p[d], v0 = v0p[d], v1 = v1p[d], o = op[d];
        o.x += w0 * (g0.x / (1.f + __expf(-g0.x))) * v0.x + w1 * (g1.x / (1.f + __expf(-g1.x))) * v1.x;
        o.y += w0 * (g0.y / (1.f + __expf(-g0.y))) * v0.y + w1 * (g1.y / (1.f + __expf(-g1.y))) * v1.y;
        o.z += w0 * (g0.z / (1.f + __expf(-g0.z))) * v0.z + w1 * (g1.z / (1.f + __expf(-g1.z))) * v1.z;
        o.w += w0 * (g0.w / (1.f + __expf(-g0.w))) * v0.w + w1 * (g1.w / (1.f + __expf(-g1.w))) * v1.w;
        op[d] = o;
    }
}

// ---------------- launch ----------------
extern "C" void kernel_launch(void* const* d_in, const int* in_sizes, int n_in,
                              void* d_out, int out_size) {
    const float* x      = (const float*)d_in[0];
    const float* fcos   = (const float*)d_in[1];
    const float* fsin   = (const float*)d_in[2];
    const int*   taskid = (const int*)  d_in[3];
    const float* n1w    = (const float*)d_in[4];
    const float* n2w    = (const float*)d_in[5];
    const float* WqT    = (const float*)d_in[6];
    const float* WkT    = (const float*)d_in[7];
    const float* WvT    = (const float*)d_in[8];
    const float* WoT    = (const float*)d_in[9];
    const float* qA     = (const float*)d_in[10];
    const float* qB     = (const float*)d_in[11];
    const float* kA     = (const float*)d_in[12];
    const float* kB     = (const float*)d_in[13];
    const float* vA     = (const float*)d_in[14];
    const float* vB     = (const float*)d_in[15];
    const float* gateWT = (const float*)d_in[16];
    const float* gA     = (const float*)d_in[17];
    const float* gB     = (const float*)d_in[18];
    const float* temb   = (const float*)d_in[19];
    const float* eW1    = (const float*)d_in[20];
    const float* eb1    = (const float*)d_in[21];
    const float* eWg    = (const float*)d_in[22];
    const float* ebg    = (const float*)d_in[23];
    const float* eWv    = (const float*)d_in[24];
    const float* ebv    = (const float*)d_in[25];
    float* out = (float*)d_out;

    float *p_h, *p_WqE, *p_WkE, *p_WvE, *p_gateE, *p_Q, *p_Kb, *p_Vb,
          *p_ctx, *p_xf, *p_h1, *p_Ge, *p_Ve;
    cudaGetSymbolAddress((void**)&p_h,     d_h);
    cudaGetSymbolAddress((void**)&p_WqE,   d_WqE);
    cudaGetSymbolAddress((void**)&p_WkE,   d_WkE);
    cudaGetSymbolAddress((void**)&p_WvE,   d_WvE);
    cudaGetSymbolAddress((void**)&p_gateE, d_gateE);
    cudaGetSymbolAddress((void**)&p_Q,     d_Q);
    cudaGetSymbolAddress((void**)&p_Kb,    d_Kb);
    cudaGetSymbolAddress((void**)&p_Vb,    d_Vb);
    cudaGetSymbolAddress((void**)&p_ctx,   d_ctx);
    cudaGetSymbolAddress((void**)&p_xf,    d_xf);
    cudaGetSymbolAddress((void**)&p_h1,    d_h1);
    cudaGetSymbolAddress((void**)&p_Ge,    d_Ge);
    cudaGetSymbolAddress((void**)&p_Ve,    d_Ve);

    eff_weight_kernel<<<(DMODEL * DMODEL + 255) / 256, 256>>>(WqT, qA, qB, p_WqE, DMODEL, DMODEL * DMODEL);
    eff_weight_kernel<<<(DMODEL * KVDIM + 255) / 256, 256>>>(WkT, kA, kB, p_WkE, KVDIM, DMODEL * KVDIM);
    eff_weight_kernel<<<(DMODEL * KVDIM + 255) / 256, 256>>>(WvT, vA, vB, p_WvE, KVDIM, DMODEL * KVDIM);
    eff_weight_kernel<<<(DMODEL * NEXP + 255) / 256, 256>>>(gateWT, gA, gB, p_gateE, NEXP, DMODEL * NEXP);

    rmsnorm1_kernel<<<TTOK, 256>>>(x, n1w, p_h);

    // QKV: tf32 tensor cores (gate impact damped ~x0.03 via attention)
    mma_plain<<<dim3(DMODEL / TN, TTOK / TM), 256>>>(p_h, DMODEL, p_WqE, DMODEL, p_Q, DMODEL, TTOK, DMODEL);
    mma_plain<<<dim3(KVDIM / TN, TTOK / TM), 256>>>(p_h, DMODEL, p_WkE, KVDIM, p_Kb, KVDIM, TTOK, DMODEL);
    mma_plain<<<dim3(KVDIM / TN, TTOK / TM), 256>>>(p_h, DMODEL, p_WvE, KVDIM, p_Vb, KVDIM, TTOK, DMODEL);

    rope_kernel<<<TTOK, 512>>>(p_Q, p_Kb, fcos, fsin);

    attn_kernel<<<dim3(SEQ / 64, NHEAD, 2), 64>>>(p_Q, p_Kb, p_Vb, p_ctx);

    // Wo stays exact fp32 (direct gate input — routing stability)
    sgemm_plain<<<dim3(DMODEL / BN, TTOK / BM), 256>>>(p_ctx, DMODEL, WoT, DMODEL, x, out, DMODEL, TTOK, DMODEL);

    rmsnorm2_kernel<<<TTOK, 256>>>(out, n2w, taskid, temb, p_xf);

    gate_kernel<<<(TTOK * 32 + 255) / 256, 256>>>(p_xf, p_gateE);
    bucket_kernel<<<1, 256>>>();

    // post-routing expert GEMMs: fp16 + ldmatrix + register prefetch
    hmma_expert<<<dim3(HID / TN, TTOK / TM, NEXP), 256>>>(
        p_xf, DMODEL, eW1, (size_t)DMODEL * HID, HID, eb1, HID, p_h1, HID, DMODEL, 1);
    hmma_expert<<<dim3(DMODEL / TN, TTOK / TM, NEXP), 256>>>(
        p_h1, HID, eWg, (size_t)HID * DMODEL, DMODEL, ebg, DMODEL, p_Ge, DMODEL, HID, 0);
    hmma_expert<<<dim3(DMODEL / TN, TTOK / TM, NEXP), 256>>>(
        p_h1, HID, eWv, (size_t)HID * DMODEL, DMODEL, ebv, DMODEL, p_Ve, DMODEL, HID, 0);

    combine_kernel<<<TTOK, 256>>>(p_Ge, p_Ve, out);
}

// round 14
// speedup vs baseline: 1.3922x; 1.0279x over previous
#include <cuda_runtime.h>
#include <cuda_fp16.h>
#include <cuda_bf16.h>
#include <math.h>

// ---------------- problem constants ----------------
#define DMODEL 1024
#define NHEAD  16
#define NKV    4
#define DK     64
#define NEXP   8
#define TOPK   2
#define RLORA  16
#define SCALE_LORA 2.0f
#define HID    4096
#define TTOK   2048
#define SEQ    1024
#define KVDIM  256
#define NSLOT  (TTOK * TOPK)

// ---------------- scratch ----------------
__device__ float d_h   [TTOK * DMODEL];
__device__ float d_WqE [DMODEL * DMODEL];
__device__ float d_WkE [DMODEL * KVDIM];
__device__ float d_WvE [DMODEL * KVDIM];
__device__ float d_gateE[DMODEL * NEXP];
__device__ float d_Q   [TTOK * DMODEL];
__device__ float d_Kb  [TTOK * KVDIM];
__device__ float d_Vb  [TTOK * KVDIM];
__device__ float d_ctx [TTOK * DMODEL];
__device__ float d_xf  [TTOK * DMODEL];
__device__ float d_h1  [NSLOT * HID];
__device__ float d_Ge  [NSLOT * DMODEL];
__device__ float d_Ve  [NSLOT * DMODEL];
__device__ int   d_top   [NSLOT];
__device__ float d_tw    [NSLOT];
__device__ int   d_pos   [NSLOT];
__device__ int   d_rowof [NSLOT];
__device__ int   d_tokrow[NSLOT];
__device__ int   d_cnt   [NEXP];
__device__ int   d_offs  [NEXP];

// ---------------- small kernels ----------------
__global__ void eff_weight_kernel(const float* __restrict__ WT,
                                  const float* __restrict__ A,
                                  const float* __restrict__ B,
                                  float* __restrict__ out, int N, int total) {
    int i = blockIdx.x * blockDim.x + threadIdx.x;
    if (i >= total) return;
    int k = i / N, n = i - k * N;
    float s = 0.f;
#pragma unroll
    for (int r = 0; r < RLORA; ++r) s += A[k * RLORA + r] * B[r * N + n];
    out[i] = WT[i] + SCALE_LORA * s;
}

__global__ void rmsnorm1_kernel(const float* __restrict__ x,
                                const float* __restrict__ w,
                                float* __restrict__ h) {
    int t = blockIdx.x;
    __shared__ float red[256];
    float ss = 0.f;
    for (int d = threadIdx.x; d < DMODEL; d += 256) {
        float v = x[(size_t)t * DMODEL + d];
        ss += v * v;
    }
    red[threadIdx.x] = ss; __syncthreads();
    for (int s = 128; s > 0; s >>= 1) {
        if (threadIdx.x < s) red[threadIdx.x] += red[threadIdx.x + s];
        __syncthreads();
    }
    float rs = rsqrtf(red[0] / (float)DMODEL + 1e-6f);
    for (int d = threadIdx.x; d < DMODEL; d += 256)
        h[(size_t)t * DMODEL + d] = x[(size_t)t * DMODEL + d] * rs * w[d];
}

__global__ void rmsnorm2_kernel(const float* __restrict__ xin,
                                const float* __restrict__ w,
                                const int* __restrict__ taskid,
                                const float* __restrict__ temb,
                                float* __restrict__ xf) {
    int t = blockIdx.x;
    __shared__ float red[256];
    float ss = 0.f;
    for (int d = threadIdx.x; d < DMODEL; d += 256) {
        float v = xin[(size_t)t * DMODEL + d];
        ss += v * v;
    }
    red[threadIdx.x] = ss; __syncthreads();
    for (int s = 128; s > 0; s >>= 1) {
        if (threadIdx.x < s) red[threadIdx.x] += red[threadIdx.x + s];
        __syncthreads();
    }
    float rs = rsqrtf(red[0] / (float)DMODEL + 1e-6f);
    int tk = taskid[t];
    for (int d = threadIdx.x; d < DMODEL; d += 256)
        xf[(size_t)t * DMODEL + d] =
            xin[(size_t)t * DMODEL + d] * rs * w[d] + temb[tk * DMODEL + d];
}

__global__ void rope_kernel(float* __restrict__ Q, float* __restrict__ K,
                            const float* __restrict__ fcos,
                            const float* __restrict__ fsin) {
    int t = blockIdx.x;
    int s = t & (SEQ - 1);
    int tid = threadIdx.x;
    int h = tid >> 5;
    int d = tid & 31;
    float c1 = fcos[s * DK + d],      s1 = fsin[s * DK + d];
    float c2 = fcos[s * DK + d + 32], s2 = fsin[s * DK + d + 32];
    {
        float* q = Q + (size_t)t * DMODEL + h * DK;
        float x1 = q[d], x2 = q[d + 32];
        q[d]      = x1 * c1 - x2 * s1;
        q[d + 32] = x2 * c2 + x1 * s2;
    }
    if (h < NKV) {
        float* k = K + (size_t)t * KVDIM + h * DK;
        float x1 = k[d], x2 = k[d + 32];
        k[d]      = x1 * c1 - x2 * s1;
        k[d + 32] = x2 * c2 + x1 * s2;
    }
}

// ---------------- fp32 tiled SGEMM: 64x64x16 (Wo / gate-critical path) ------
#define BM 64
#define BN 64
#define BKK 16

__device__ __forceinline__ void sgemm_tile_dev(
    const float* __restrict__ A, int lda,
    const float* __restrict__ B, int ldb,
    const float* __restrict__ Cadd,
    float* __restrict__ C, int ldc,
    int M, int K, int m0, int n0)
{
    __shared__ float As[BKK][BM];
    __shared__ float Bs[BKK][BN];
    const int tid = threadIdx.x;
    const int tx = tid & 15, ty = tid >> 4;
    const int aRow = tid >> 2;
    const int aCol = (tid & 3) * 4;
    const int bRow = tid >> 4;
    const int bCol = (tid & 15) * 4;

    const float* Aptr = A + (size_t)(m0 + aRow) * lda + aCol;
    const float* Bptr = B + (size_t)bRow * ldb + n0 + bCol;

    float acc[4][4];
#pragma unroll
    for (int i = 0; i < 4; ++i)
#pragma unroll
        for (int j = 0; j < 4; ++j) acc[i][j] = 0.f;

    for (int kk = 0; kk < K; kk += BKK) {
        float4 av = *(const float4*)(Aptr + kk);
        float4 bv = *(const float4*)(Bptr + (size_t)kk * ldb);
        __syncthreads();
        As[aCol + 0][aRow] = av.x;
        As[aCol + 1][aRow] = av.y;
        As[aCol + 2][aRow] = av.z;
        As[aCol + 3][aRow] = av.w;
        *(float4*)&Bs[bRow][bCol] = bv;
        __syncthreads();
#pragma unroll
        for (int k = 0; k < BKK; ++k) {
            float4 a = *(const float4*)&As[k][ty * 4];
            float4 b = *(const float4*)&Bs[k][tx * 4];
            acc[0][0] += a.x * b.x; acc[0][1] += a.x * b.y; acc[0][2] += a.x * b.z; acc[0][3] += a.x * b.w;
            acc[1][0] += a.y * b.x; acc[1][1] += a.y * b.y; acc[1][2] += a.y * b.z; acc[1][3] += a.y * b.w;
            acc[2][0] += a.z * b.x; acc[2][1] += a.z * b.y; acc[2][2] += a.z * b.z; acc[2][3] += a.z * b.w;
            acc[3][0] += a.w * b.x; acc[3][1] += a.w * b.y; acc[3][2] += a.w * b.z; acc[3][3] += a.w * b.w;
        }
    }

#pragma unroll
    for (int i = 0; i < 4; ++i) {
        size_t crow = (size_t)(m0 + ty * 4 + i);
#pragma unroll
        for (int j = 0; j < 4; ++j) {
            int c = n0 + tx * 4 + j;
            float v = acc[i][j];
            if (Cadd) v += Cadd[crow * ldc + c];
            C[crow * ldc + c] = v;
        }
    }
}

__global__ __launch_bounds__(256) void sgemm_plain(
    const float* __restrict__ A, int lda,
    const float* __restrict__ B, int ldb,
    const float* __restrict__ Cadd,
    float* __restrict__ C, int ldc, int M, int K)
{
    sgemm_tile_dev(A, lda, B, ldb, Cadd, C, ldc, M, K,
                   blockIdx.y * BM, blockIdx.x * BN);
}

// ------- tf32 tensor-core GEMM (QKV path) + register prefetch ----------
#define TM 128
#define TN 128
#define TKT 32
#define ASTR 36
#define BSTR 136

__device__ __forceinline__ float tf32r(float f) {
    unsigned u;
    asm("cvt.rna.tf32.f32 %0, %1;" : "=r"(u) : "f"(f));
    return __uint_as_float(u);
}

__device__ __forceinline__ void mma_tf32(float* d, const unsigned* a,
                                         const unsigned* b, const float* c) {
    asm volatile(
        "mma.sync.aligned.m16n8k8.row.col.f32.tf32.tf32.f32 "
        "{%0,%1,%2,%3}, {%4,%5,%6,%7}, {%8,%9}, {%10,%11,%12,%13};"
        : "=f"(d[0]), "=f"(d[1]), "=f"(d[2]), "=f"(d[3])
        : "r"(a[0]), "r"(a[1]), "r"(a[2]), "r"(a[3]),
          "r"(b[0]), "r"(b[1]),
          "f"(c[0]), "f"(c[1]), "f"(c[2]), "f"(c[3]));
}

__device__ __forceinline__ void mma_tile_dev(
    const float* __restrict__ A, int lda,
    const float* __restrict__ B, int ldb,
    float* __restrict__ C, int ldc,
    int M, int K, int m0, int n0)
{
    __shared__ float Asm[TM][ASTR];
    __shared__ float Bsm[TKT][BSTR];
    const int tid  = threadIdx.x;
    const int lane = tid & 31;
    const int warp = tid >> 5;
    const int wm = (warp & 1) * 64;
    const int wn = (warp >> 1) * 32;
    const int fr = lane >> 2;
    const int fc = lane & 3;

    float acc[4][4][4];
#pragma unroll
    for (int mi = 0; mi < 4; ++mi)
#pragma unroll
        for (int ni = 0; ni < 4; ++ni)
#pragma unroll
            for (int q = 0; q < 4; ++q) acc[mi][ni][q] = 0.f;

    int aR[4], aKV[4], bKR[4], bNV[4];
#pragma unroll
    for (int i = 0; i < 4; ++i) {
        int lin = tid + i * 256;
        aR[i]  = lin >> 3;
        aKV[i] = (lin & 7) * 4;
        bKR[i] = lin >> 5;
        bNV[i] = (lin & 31) * 4;
    }

    float4 avP[4], bvP[4];
    auto prefetch = [&](int kt) {
#pragma unroll
        for (int i = 0; i < 4; ++i)
            avP[i] = *(const float4*)(A + (size_t)(m0 + aR[i]) * lda + kt + aKV[i]);
#pragma unroll
        for (int i = 0; i < 4; ++i)
            bvP[i] = *(const float4*)(B + (size_t)(kt + bKR[i]) * ldb + n0 + bNV[i]);
    };

    prefetch(0);

    for (int kt = 0; kt < K; kt += TKT) {
        __syncthreads();
#pragma unroll
        for (int i = 0; i < 4; ++i) {
            float* p = &Asm[aR[i]][aKV[i]];
            p[0] = tf32r(avP[i].x); p[1] = tf32r(avP[i].y);
            p[2] = tf32r(avP[i].z); p[3] = tf32r(avP[i].w);
        }
#pragma unroll
        for (int i = 0; i < 4; ++i) {
            float* p = &Bsm[bKR[i]][bNV[i]];
            p[0] = tf32r(bvP[i].x); p[1] = tf32r(bvP[i].y);
            p[2] = tf32r(bvP[i].z); p[3] = tf32r(bvP[i].w);
        }
        __syncthreads();

        if (kt + TKT < K) prefetch(kt + TKT);

#pragma unroll
        for (int k0 = 0; k0 < TKT; k0 += 8) {
            unsigned af[4][4], bf[4][2];
#pragma unroll
            for (int mi = 0; mi < 4; ++mi) {
                int rb = wm + mi * 16;
                af[mi][0] = __float_as_uint(Asm[rb + fr][k0 + fc]);
                af[mi][1] = __float_as_uint(Asm[rb + fr + 8][k0 + fc]);
                af[mi][2] = __float_as_uint(Asm[rb + fr][k0 + fc + 4]);
                af[mi][3] = __float_as_uint(Asm[rb + fr + 8][k0 + fc + 4]);
            }
#pragma unroll
            for (int ni = 0; ni < 4; ++ni) {
                int nb = wn + ni * 8;
                bf[ni][0] = __float_as_uint(Bsm[k0 + fc][nb + fr]);
                bf[ni][1] = __float_as_uint(Bsm[k0 + fc + 4][nb + fr]);
            }
#pragma unroll
            for (int mi = 0; mi < 4; ++mi)
#pragma unroll
                for (int ni = 0; ni < 4; ++ni)
                    mma_tf32(acc[mi][ni], af[mi], bf[ni], acc[mi][ni]);
        }
    }

    const int cc = (lane & 3) * 2;
#pragma unroll
    for (int mi = 0; mi < 4; ++mi) {
        int rloc0 = m0 + wm + mi * 16 + fr;
        int rloc1 = rloc0 + 8;
#pragma unroll
        for (int ni = 0; ni < 4; ++ni) {
            int col = n0 + wn + ni * 8 + cc;
            {
                size_t cr = (size_t)rloc0 * ldc;
                C[cr + col]     = acc[mi][ni][0];
                C[cr + col + 1] = acc[mi][ni][1];
            }
            {
                size_t cr = (size_t)rloc1 * ldc;
                C[cr + col]     = acc[mi][ni][2];
                C[cr + col + 1] = acc[mi][ni][3];
            }
        }
    }
}

__global__ __launch_bounds__(256, 2) void mma_plain(
    const float* __restrict__ A, int lda,
    const float* __restrict__ B, int ldb,
    float* __restrict__ C, int ldc, int M, int K)
{
    mma_tile_dev(A, lda, B, ldb, C, ldc, M, K,
                 blockIdx.y * TM, blockIdx.x * TN);
}

// -------- fp16 expert GEMM: m16n8k16 + ldmatrix + register prefetch --------
#define HASTR 40
#define HBSTR 136

__device__ __forceinline__ void ldsm_x4(unsigned& r0, unsigned& r1,
                                        unsigned& r2, unsigned& r3,
                                        unsigned addr) {
    asm volatile("ldmatrix.sync.aligned.m8n8.x4.shared.b16 {%0,%1,%2,%3}, [%4];"
                 : "=r"(r0), "=r"(r1), "=r"(r2), "=r"(r3) : "r"(addr));
}
__device__ __forceinline__ void ldsm_x4_t(unsigned& r0, unsigned& r1,
                                          unsigned& r2, unsigned& r3,
                                          unsigned addr) {
    asm volatile("ldmatrix.sync.aligned.m8n8.x4.trans.shared.b16 {%0,%1,%2,%3}, [%4];"
                 : "=r"(r0), "=r"(r1), "=r"(r2), "=r"(r3) : "r"(addr));
}
__device__ __forceinline__ void mma_f16(float* d, const unsigned* a,
                                        const unsigned* b, const float* c) {
    asm volatile(
        "mma.sync.aligned.m16n8k16.row.col.f32.f16.f16.f32 "
        "{%0,%1,%2,%3}, {%4,%5,%6,%7}, {%8,%9}, {%10,%11,%12,%13};"
        : "=f"(d[0]), "=f"(d[1]), "=f"(d[2]), "=f"(d[3])
        : "r"(a[0]), "r"(a[1]), "r"(a[2]), "r"(a[3]),
          "r"(b[0]), "r"(b[1]),
          "f"(c[0]), "f"(c[1]), "f"(c[2]), "f"(c[3]));
}

__device__ __forceinline__ void hmma_tile_dev(
    const float* __restrict__ A, int lda,
    const float* __restrict__ B, int ldb,
    const float* __restrict__ bias,
    float* __restrict__ C, int ldc,
    int M, int K,
    const int* __restrict__ gmap,
    int m0, int n0, int cRow0)
{
    __shared__ __half AsmH[TM * HASTR];
    __shared__ __half BsmH[TKT * HBSTR];

    const int tid  = threadIdx.x;
    const int lane = tid & 31;
    const int warp = tid >> 5;
    const int wm = (warp & 1) * 64;
    const int wn = (warp >> 1) * 32;
    const int fr = lane >> 2;

    const int lm  = lane >> 3;
    const int l7  = lane & 7;
    const int aRowOff = (lm & 1) * 8 + l7;
    const int aKOff   = (lm >> 1) * 8;
    const int bKOff = (lm & 1) * 8 + l7;
    const int bNOff = (lm >> 1) * 8;

    float acc[4][4][4];
#pragma unroll
    for (int mi = 0; mi < 4; ++mi)
#pragma unroll
        for (int ni = 0; ni < 4; ++ni)
#pragma unroll
            for (int q = 0; q < 4; ++q) acc[mi][ni][q] = 0.f;

    int aR[4], aKV[4]; bool avalid[4]; size_t arow[4];
    int bKR[4], bNV[4];
#pragma unroll
    for (int i = 0; i < 4; ++i) {
        int lin = tid + i * 256;
        aR[i]  = lin >> 3;
        aKV[i] = (lin & 7) * 4;
        int gr = m0 + aR[i];
        avalid[i] = gr < M;
        arow[i] = avalid[i] ? (size_t)(gmap ? gmap[gr] : gr) : 0;
        bKR[i] = lin >> 5;
        bNV[i] = (lin & 31) * 4;
    }

    float4 avP[4], bvP[4];
    auto prefetch = [&](int kt) {
#pragma unroll
        for (int i = 0; i < 4; ++i)
            avP[i] = avalid[i] ? *(const float4*)(A + arow[i] * lda + kt + aKV[i])
                               : make_float4(0.f, 0.f, 0.f, 0.f);
#pragma unroll
        for (int i = 0; i < 4; ++i)
            bvP[i] = *(const float4*)(B + (size_t)(kt + bKR[i]) * ldb + n0 + bNV[i]);
    };

    prefetch(0);

    for (int kt = 0; kt < K; kt += TKT) {
        __syncthreads();
#pragma unroll
        for (int i = 0; i < 4; ++i) {
            __half2* dst = (__half2*)&AsmH[aR[i] * HASTR + aKV[i]];
            dst[0] = __floats2half2_rn(avP[i].x, avP[i].y);
            dst[1] = __floats2half2_rn(avP[i].z, avP[i].w);
        }
#pragma unroll
        for (int i = 0; i < 4; ++i) {
            __half2* dst = (__half2*)&BsmH[bKR[i] * HBSTR + bNV[i]];
            dst[0] = __floats2half2_rn(bvP[i].x, bvP[i].y);
            dst[1] = __floats2half2_rn(bvP[i].z, bvP[i].w);
        }
        __syncthreads();

        if (kt + TKT < K) prefetch(kt + TKT);

#pragma unroll
        for (int k0 = 0; k0 < TKT; k0 += 16) {
            unsigned af[4][4], bf[4][2];
#pragma unroll
            for (int mi = 0; mi < 4; ++mi) {
                int rb = wm + mi * 16;
                unsigned addr = (unsigned)__cvta_generic_to_shared(
                    &AsmH[(rb + aRowOff) * HASTR + k0 + aKOff]);
                ldsm_x4(af[mi][0], af[mi][1], af[mi][2], af[mi][3], addr);
            }
#pragma unroll
            for (int p = 0; p < 2; ++p) {
                int nb = wn + p * 16;
                unsigned addr = (unsigned)__cvta_generic_to_shared(
                    &BsmH[(k0 + bKOff) * HBSTR + nb + bNOff]);
                ldsm_x4_t(bf[2 * p][0], bf[2 * p][1],
                          bf[2 * p + 1][0], bf[2 * p + 1][1], addr);
            }
#pragma unroll
            for (int mi = 0; mi < 4; ++mi)
#pragma unroll
                for (int ni = 0; ni < 4; ++ni)
                    mma_f16(acc[mi][ni], af[mi], bf[ni], acc[mi][ni]);
        }
    }

    const int cc = (lane & 3) * 2;
#pragma unroll
    for (int mi = 0; mi < 4; ++mi) {
        int rloc0 = m0 + wm + mi * 16 + fr;
        int rloc1 = rloc0 + 8;
#pragma unroll
        for (int ni = 0; ni < 4; ++ni) {
            int col = n0 + wn + ni * 8 + cc;
            float b0 = bias ? bias[col] : 0.f;
            float b1 = bias ? bias[col + 1] : 0.f;
            if (rloc0 < M) {
                size_t cr = (size_t)(cRow0 + rloc0) * ldc;
                C[cr + col]     = acc[mi][ni][0] + b0;
                C[cr + col + 1] = acc[mi][ni][1] + b1;
            }
            if (rloc1 < M) {
                size_t cr = (size_t)(cRow0 + rloc1) * ldc;
                C[cr + col]     = acc[mi][ni][2] + b0;
                C[cr + col + 1] = acc[mi][ni][3] + b1;
            }
        }
    }
}

// expert GEMM1 (token gather, xf @ W1 + b1)
__global__ __launch_bounds__(256, 2) void hmma_expert_up(
    const float* __restrict__ xf,
    const float* __restrict__ W1, const float* __restrict__ b1,
    float* __restrict__ h1)
{
    int e = blockIdx.z;
    int cnt = d_cnt[e];
    int m0 = blockIdx.y * TM;
    if (m0 >= cnt) return;
    int off = d_offs[e];
    hmma_tile_dev(xf, DMODEL,
                  W1 + (size_t)e * DMODEL * HID, HID,
                  b1 + (size_t)e * HID,
                  h1, HID, cnt, DMODEL,
                  d_tokrow + off, m0, blockIdx.x * TN, off);
}

// fused GEMM2+3: blockIdx.x halves pick Wg/Wv (halves h1 re-reads, better tail)
__global__ __launch_bounds__(256, 2) void hmma_expert_gv(
    const float* __restrict__ h1,
    const float* __restrict__ Wg, const float* __restrict__ bg,
    const float* __restrict__ Wv, const float* __restrict__ bv,
    float* __restrict__ Ge, float* __restrict__ Ve)
{
    int e = blockIdx.z;
    int cnt = d_cnt[e];
    int m0 = blockIdx.y * TM;
    if (m0 >= cnt) return;
    int off = d_offs[e];
    const int halfTiles = DMODEL / TN;      // 8
    bool isV = blockIdx.x >= halfTiles;
    int n0 = (blockIdx.x - (isV ? halfTiles : 0)) * TN;
    const float* B    = (isV ? Wv : Wg) + (size_t)e * HID * DMODEL;
    const float* bias = (isV ? bv : bg) + (size_t)e * DMODEL;
    float* C = isV ? Ve : Ge;
    hmma_tile_dev(h1 + (size_t)off * HID, HID, B, DMODEL, bias,
                  C, DMODEL, cnt, HID, nullptr, m0, n0, off);
}

// ---------------- flash attention (fp32, causal, GQA) ----------------
__global__ __launch_bounds__(64) void attn_kernel(
    const float* __restrict__ Q, const float* __restrict__ Kb,
    const float* __restrict__ Vb, float* __restrict__ ctx)
{
    const int qb = blockIdx.x, h = blockIdx.y, b = blockIdx.z;
    const int r = threadIdx.x;
    const int qglob = qb * 64 + r;
    const size_t t = (size_t)b * SEQ + qglob;
    const int kh = h >> 2;

    float q[DK];
    const float* qp = Q + t * DMODEL + h * DK;
#pragma unroll
    for (int d4 = 0; d4 < 16; ++d4) {
        float4 v = *(const float4*)(qp + d4 * 4);
        q[d4 * 4 + 0] = v.x; q[d4 * 4 + 1] = v.y;
        q[d4 * 4 + 2] = v.z; q[d4 * 4 + 3] = v.w;
    }
    float acc[DK];
#pragma unroll
    for (int d = 0; d < DK; ++d) acc[d] = 0.f;
    float mval = -3.4e38f, lsum = 0.f;

    __shared__ float Ksm[64][DK];
    __shared__ float Vsm[64][DK];

    for (int kt = 0; kt <= qb; ++kt) {
        __syncthreads();
        {
            size_t krow = (size_t)b * SEQ + kt * 64 + r;
            const float4* kp = (const float4*)(Kb + krow * KVDIM + kh * DK);
            const float4* vp = (const float4*)(Vb + krow * KVDIM + kh * DK);
#pragma unroll
            for (int c = 0; c < 16; ++c) {
                ((float4*)Ksm[r])[c] = kp[c];
                ((float4*)Vsm[r])[c] = vp[c];
            }
        }
        __syncthreads();
        const int kmax = (kt == qb) ? r : 63;
        for (int c0 = 0; c0 <= kmax; c0 += 16) {
            float s[16];
            float mch = -3.4e38f;
#pragma unroll
            for (int j = 0; j < 16; ++j) {
                int k = c0 + j;
                float dot = 0.f;
                const float4* kr = (const float4*)Ksm[k];
#pragma unroll
                for (int d4 = 0; d4 < 16; ++d4) {
                    float4 kv = kr[d4];
                    dot += q[d4 * 4 + 0] * kv.x + q[d4 * 4 + 1] * kv.y
                         + q[d4 * 4 + 2] * kv.z + q[d4 * 4 + 3] * kv.w;
                }
                s[j] = (k <= kmax) ? dot * 0.125f : -3.4e38f;
                mch = fmaxf(mch, s[j]);
            }
            float mnew = fmaxf(mval, mch);
            float corr = __expf(mval - mnew);
            lsum *= corr;
#pragma unroll
            for (int d = 0; d < DK; ++d) acc[d] *= corr;
#pragma unroll
            for (int j = 0; j < 16; ++j) {
                float p = __expf(s[j] - mnew);
                lsum += p;
                const float4* vr = (const float4*)Vsm[c0 + j];
#pragma unroll
                for (int d4 = 0; d4 < 16; ++d4) {
                    float4 vv = vr[d4];
                    acc[d4 * 4 + 0] += p * vv.x;
                    acc[d4 * 4 + 1] += p * vv.y;
                    acc[d4 * 4 + 2] += p * vv.z;
                    acc[d4 * 4 + 3] += p * vv.w;
                }
            }
            mval = mnew;
        }
    }
    float inv = 1.f / lsum;
    float* op = ctx + t * DMODEL + h * DK;
#pragma unroll
    for (int d = 0; d < DK; ++d) op[d] = acc[d] * inv;
}

// ---------------- gating ----------------
__global__ void gate_kernel(const float* __restrict__ xf,
                            const float* __restrict__ gateE) {
    int warp = (blockIdx.x * blockDim.x + threadIdx.x) >> 5;
    int lane = threadIdx.x & 31;
    if (warp >= TTOK) return;
    int t = warp;
    float acc[NEXP];
#pragma unroll
    for (int e = 0; e < NEXP; ++e) acc[e] = 0.f;
    for (int d = lane; d < DMODEL; d += 32) {
        float xv = xf[(size_t)t * DMODEL + d];
#pragma unroll
        for (int e = 0; e < NEXP; ++e) acc[e] += xv * gateE[d * NEXP + e];
    }
#pragma unroll
    for (int e = 0; e < NEXP; ++e)
#pragma unroll
        for (int o = 16; o > 0; o >>= 1)
            acc[e] += __shfl_xor_sync(0xffffffff, acc[e], o);
    if (lane == 0) {
        int i0 = 0; float v0 = acc[0];
#pragma unroll
        for (int e = 1; e < NEXP; ++e) if (acc[e] > v0) { v0 = acc[e]; i0 = e; }
        int i1 = -1; float v1 = -3.4e38f;
#pragma unroll
        for (int e = 0; e < NEXP; ++e)
            if (e != i0 && acc[e] > v1) { v1 = acc[e]; i1 = e; }
        if (i1 < 0) { i1 = (i0 + 1) & (NEXP - 1); v1 = v0; }
        float w0 = 1.f / (1.f + __expf(v1 - v0));
        float w1 = 1.f - w0;
        d_top[2 * t]     = i0;  d_tw[2 * t]     = w0;
        d_top[2 * t + 1] = i1;  d_tw[2 * t + 1] = w1;
    }
}

__global__ void bucket_kernel() {
    __shared__ int tops[NSLOT];
    __shared__ int cnt[NEXP];
    for (int s = threadIdx.x; s < NSLOT; s += blockDim.x) tops[s] = d_top[s];
    if (threadIdx.x < NEXP) cnt[threadIdx.x] = 0;
    __syncthreads();
    if (threadIdx.x == 0) {
        for (int s = 0; s < NSLOT; ++s) {
            int e = tops[s];
            d_pos[s] = cnt[e]++;
        }
        int o = 0;
        for (int e = 0; e < NEXP; ++e) { d_offs[e] = o; d_cnt[e] = cnt[e]; o += cnt[e]; }
    }
    __syncthreads();
    for (int s = threadIdx.x; s < NSLOT; s += blockDim.x) {
        int e = tops[s];
        int j = d_offs[e] + d_pos[s];
        d_rowof[s] = j;
        d_tokrow[j] = s >> 1;
    }
}

__global__ void combine_kernel(const float* __restrict__ Ge,
                               const float* __restrict__ Ve,
                               float* __restrict__ out) {
    int t = blockIdx.x;
    int j0 = d_rowof[2 * t],     j1 = d_rowof[2 * t + 1];
    float w0 = d_tw[2 * t],      w1 = d_tw[2 * t + 1];
    const float4* g0p = (const float4*)(Ge + (size_t)j0 * DMODEL);
    const float4* v0p = (const float4*)(Ve + (size_t)j0 * DMODEL);
    const float4* g1p = (const float4*)(Ge + (size_t)j1 * DMODEL);
    const float4* v1p = (const float4*)(Ve + (size_t)j1 * DMODEL);
    float4* op = (float4*)(out + (size_t)t * DMODEL);
    for (int d = threadIdx.x; d < DMODEL / 4; d += blockDim.x) {
        float4 g0 = g0p[d], g1 = g1p[d], v0 = v0p[d], v1 = v1p[d], o = op[d];
        o.x += w0 * (g0.x / (1.f + __expf(-g0.x))) * v0.x + w1 * (g1.x / (1.f + __expf(-g1.x))) * v1.x;
        o.y += w0 * (g0.y / (1.f + __expf(-g0.y))) * v0.y + w1 * (g1.y / (1.f + __expf(-g1.y))) * v1.y;
        o.z += w0 * (g0.z / (1.f + __expf(-g0.z))) * v0.z + w1 * (g1.z / (1.f + __expf(-g1.z))) * v1.z;
        o.w += w0 * (g0.w / (1.f + __expf(-g0.w))) * v0.w + w1 * (g1.w / (1.f + __expf(-g1.w))) * v1.w;
        op[d] = o;
    }
}

// ---------------- launch ----------------
extern "C" void kernel_launch(void* const* d_in, const int* in_sizes, int n_in,
                              void* d_out, int out_size) {
    const float* x      = (const float*)d_in[0];
    const float* fcos   = (const float*)d_in[1];
    const float* fsin   = (const float*)d_in[2];
    const int*   taskid = (const int*)  d_in[3];
    const float* n1w    = (const float*)d_in[4];
    const float* n2w    = (const float*)d_in[5];
    const float* WqT    = (const float*)d_in[6];
    const float* WkT    = (const float*)d_in[7];
    const float* WvT    = (const float*)d_in[8];
    const float* WoT    = (const float*)d_in[9];
    const float* qA     = (const float*)d_in[10];
    const float* qB     = (const float*)d_in[11];
    const float* kA     = (const float*)d_in[12];
    const float* kB     = (const float*)d_in[13];
    const float* vA     = (const float*)d_in[14];
    const float* vB     = (const float*)d_in[15];
    const float* gateWT = (const float*)d_in[16];
    const float* gA     = (const float*)d_in[17];
    const float* gB     = (const float*)d_in[18];
    const float* temb   = (const float*)d_in[19];
    const float* eW1    = (const float*)d_in[20];
    const float* eb1    = (const float*)d_in[21];
    const float* eWg    = (const float*)d_in[22];
    const float* ebg    = (const float*)d_in[23];
    const float* eWv    = (const float*)d_in[24];
    const float* ebv    = (const float*)d_in[25];
    float* out = (float*)d_out;

    float *p_h, *p_WqE, *p_WkE, *p_WvE, *p_gateE, *p_Q, *p_Kb, *p_Vb,
          *p_ctx, *p_xf, *p_h1, *p_Ge, *p_Ve;
    cudaGetSymbolAddress((void**)&p_h,     d_h);
    cudaGetSymbolAddress((void**)&p_WqE,   d_WqE);
    cudaGetSymbolAddress((void**)&p_WkE,   d_WkE);
    cudaGetSymbolAddress((void**)&p_WvE,   d_WvE);
    cudaGetSymbolAddress((void**)&p_gateE, d_gateE);
    cudaGetSymbolAddress((void**)&p_Q,     d_Q);
    cudaGetSymbolAddress((void**)&p_Kb,    d_Kb);
    cudaGetSymbolAddress((void**)&p_Vb,    d_Vb);
    cudaGetSymbolAddress((void**)&p_ctx,   d_ctx);
    cudaGetSymbolAddress((void**)&p_xf,    d_xf);
    cudaGetSymbolAddress((void**)&p_h1,    d_h1);
    cudaGetSymbolAddress((void**)&p_Ge,    d_Ge);
    cudaGetSymbolAddress((void**)&p_Ve,    d_Ve);

    eff_weight_kernel<<<(DMODEL * DMODEL + 255) / 256, 256>>>(WqT, qA, qB, p_WqE, DMODEL, DMODEL * DMODEL);
    eff_weight_kernel<<<(DMODEL * KVDIM + 255) / 256, 256>>>(WkT, kA, kB, p_WkE, KVDIM, DMODEL * KVDIM);
    eff_weight_kernel<<<(DMODEL * KVDIM + 255) / 256, 256>>>(WvT, vA, vB, p_WvE, KVDIM, DMODEL * KVDIM);
    eff_weight_kernel<<<(DMODEL * NEXP + 255) / 256, 256>>>(gateWT, gA, gB, p_gateE, NEXP, DMODEL * NEXP);

    rmsnorm1_kernel<<<TTOK, 256>>>(x, n1w, p_h);

    // QKV: tf32 tensor cores + register prefetch
    mma_plain<<<dim3(DMODEL / TN, TTOK / TM), 256>>>(p_h, DMODEL, p_WqE, DMODEL, p_Q, DMODEL, TTOK, DMODEL);
    mma_plain<<<dim3(KVDIM / TN, TTOK / TM), 256>>>(p_h, DMODEL, p_WkE, KVDIM, p_Kb, KVDIM, TTOK, DMODEL);
    mma_plain<<<dim3(KVDIM / TN, TTOK / TM), 256>>>(p_h, DMODEL, p_WvE, KVDIM, p_Vb, KVDIM, TTOK, DMODEL);

    rope_kernel<<<TTOK, 512>>>(p_Q, p_Kb, fcos, fsin);

    attn_kernel<<<dim3(SEQ / 64, NHEAD, 2), 64>>>(p_Q, p_Kb, p_Vb, p_ctx);

    // Wo stays exact fp32 (direct gate input — routing stability)
    sgemm_plain<<<dim3(DMODEL / BN, TTOK / BM), 256>>>(p_ctx, DMODEL, WoT, DMODEL, x, out, DMODEL, TTOK, DMODEL);

    rmsnorm2_kernel<<<TTOK, 256>>>(out, n2w, taskid, temb, p_xf);

    gate_kernel<<<(TTOK * 32 + 255) / 256, 256>>>(p_xf, p_gateE);
    bucket_kernel<<<1, 256>>>();

    // expert GEMMs: fp16 + ldmatrix + prefetch; GEMM2/3 fused
    hmma_expert_up<<<dim3(HID / TN, TTOK / TM, NEXP), 256>>>(
        p_xf, eW1, eb1, p_h1);
    hmma_expert_gv<<<dim3(2 * DMODEL / TN, TTOK / TM, NEXP), 256>>>(
        p_h1, eWg, ebg, eWv, ebv, p_Ge, p_Ve);

    combine_kernel<<<TTOK, 256>>>(p_Ge, p_Ve, out);
}

// round 16
// speedup vs baseline: 1.4284x; 1.0260x over previous
#include <cuda_runtime.h>
#include <cuda_fp16.h>
#include <cuda_bf16.h>
#include <math.h>

// ---------------- problem constants ----------------
#define DMODEL 1024
#define NHEAD  16
#define NKV    4
#define DK     64
#define NEXP   8
#define TOPK   2
#define RLORA  16
#define SCALE_LORA 2.0f
#define HID    4096
#define TTOK   2048
#define SEQ    1024
#define KVDIM  256
#define NSLOT  (TTOK * TOPK)

// ---------------- scratch ----------------
__device__ float d_h   [TTOK * DMODEL];
__device__ float d_WqE [DMODEL * DMODEL];
__device__ float d_WkE [DMODEL * KVDIM];
__device__ float d_WvE [DMODEL * KVDIM];
__device__ float d_gateE[DMODEL * NEXP];
__device__ float d_Q   [TTOK * DMODEL];
__device__ float d_Kb  [TTOK * KVDIM];
__device__ float d_Vb  [TTOK * KVDIM];
__device__ float d_ctx [TTOK * DMODEL];
__device__ float d_xf  [TTOK * DMODEL];
__device__ float d_h1  [NSLOT * HID];
__device__ float d_Ge  [NSLOT * DMODEL];
__device__ float d_Ve  [NSLOT * DMODEL];
__device__ int   d_top   [NSLOT];
__device__ float d_tw    [NSLOT];
__device__ int   d_pos   [NSLOT];
__device__ int   d_rowof [NSLOT];
__device__ int   d_tokrow[NSLOT];
__device__ int   d_cnt   [NEXP];
__device__ int   d_offs  [NEXP];

// ---------------- small kernels ----------------
__global__ void eff_weight_kernel(const float* __restrict__ WT,
                                  const float* __restrict__ A,
                                  const float* __restrict__ B,
                                  float* __restrict__ out, int N, int total) {
    int i = blockIdx.x * blockDim.x + threadIdx.x;
    if (i >= total) return;
    int k = i / N, n = i - k * N;
    float s = 0.f;
#pragma unroll
    for (int r = 0; r < RLORA; ++r) s += A[k * RLORA + r] * B[r * N + n];
    out[i] = WT[i] + SCALE_LORA * s;
}

__global__ void rmsnorm1_kernel(const float* __restrict__ x,
                                const float* __restrict__ w,
                                float* __restrict__ h) {
    int t = blockIdx.x;
    __shared__ float red[256];
    float ss = 0.f;
    for (int d = threadIdx.x; d < DMODEL; d += 256) {
        float v = x[(size_t)t * DMODEL + d];
        ss += v * v;
    }
    red[threadIdx.x] = ss; __syncthreads();
    for (int s = 128; s > 0; s >>= 1) {
        if (threadIdx.x < s) red[threadIdx.x] += red[threadIdx.x + s];
        __syncthreads();
    }
    float rs = rsqrtf(red[0] / (float)DMODEL + 1e-6f);
    for (int d = threadIdx.x; d < DMODEL; d += 256)
        h[(size_t)t * DMODEL + d] = x[(size_t)t * DMODEL + d] * rs * w[d];
}

__global__ void rmsnorm2_kernel(const float* __restrict__ xin,
                                const float* __restrict__ w,
                                const int* __restrict__ taskid,
                                const float* __restrict__ temb,
                                float* __restrict__ xf) {
    int t = blockIdx.x;
    __shared__ float red[256];
    float ss = 0.f;
    for (int d = threadIdx.x; d < DMODEL; d += 256) {
        float v = xin[(size_t)t * DMODEL + d];
        ss += v * v;
    }
    red[threadIdx.x] = ss; __syncthreads();
    for (int s = 128; s > 0; s >>= 1) {
        if (threadIdx.x < s) red[threadIdx.x] += red[threadIdx.x + s];
        __syncthreads();
    }
    float rs = rsqrtf(red[0] / (float)DMODEL + 1e-6f);
    int tk = taskid[t];
    for (int d = threadIdx.x; d < DMODEL; d += 256)
        xf[(size_t)t * DMODEL + d] =
            xin[(size_t)t * DMODEL + d] * rs * w[d] + temb[tk * DMODEL + d];
}

__global__ void rope_kernel(float* __restrict__ Q, float* __restrict__ K,
                            const float* __restrict__ fcos,
                            const float* __restrict__ fsin) {
    int t = blockIdx.x;
    int s = t & (SEQ - 1);
    int tid = threadIdx.x;
    int h = tid >> 5;
    int d = tid & 31;
    float c1 = fcos[s * DK + d],      s1 = fsin[s * DK + d];
    float c2 = fcos[s * DK + d + 32], s2 = fsin[s * DK + d + 32];
    {
        float* q = Q + (size_t)t * DMODEL + h * DK;
        float x1 = q[d], x2 = q[d + 32];
        q[d]      = x1 * c1 - x2 * s1;
        q[d + 32] = x2 * c2 + x1 * s2;
    }
    if (h < NKV) {
        float* k = K + (size_t)t * KVDIM + h * DK;
        float x1 = k[d], x2 = k[d + 32];
        k[d]      = x1 * c1 - x2 * s1;
        k[d + 32] = x2 * c2 + x1 * s2;
    }
}

// ---------------- mma helpers ----------------
__device__ __forceinline__ float tf32r(float f) {
    unsigned u;
    asm("cvt.rna.tf32.f32 %0, %1;" : "=r"(u) : "f"(f));
    return __uint_as_float(u);
}

__device__ __forceinline__ void mma_tf32(float* d, const unsigned* a,
                                         const unsigned* b, const float* c) {
    asm volatile(
        "mma.sync.aligned.m16n8k8.row.col.f32.tf32.tf32.f32 "
        "{%0,%1,%2,%3}, {%4,%5,%6,%7}, {%8,%9}, {%10,%11,%12,%13};"
        : "=f"(d[0]), "=f"(d[1]), "=f"(d[2]), "=f"(d[3])
        : "r"(a[0]), "r"(a[1]), "r"(a[2]), "r"(a[3]),
          "r"(b[0]), "r"(b[1]),
          "f"(c[0]), "f"(c[1]), "f"(c[2]), "f"(c[3]));
}

// ------- tf32 tensor-core GEMM (QKV path) + register prefetch ----------
#define TM 128
#define TN 128
#define TKT 32
#define ASTR 36
#define BSTR 136

__device__ __forceinline__ void mma_tile_dev(
    const float* __restrict__ A, int lda,
    const float* __restrict__ B, int ldb,
    float* __restrict__ C, int ldc,
    int M, int K, int m0, int n0)
{
    __shared__ float Asm[TM][ASTR];
    __shared__ float Bsm[TKT][BSTR];
    const int tid  = threadIdx.x;
    const int lane = tid & 31;
    const int warp = tid >> 5;
    const int wm = (warp & 1) * 64;
    const int wn = (warp >> 1) * 32;
    const int fr = lane >> 2;
    const int fc = lane & 3;

    float acc[4][4][4];
#pragma unroll
    for (int mi = 0; mi < 4; ++mi)
#pragma unroll
        for (int ni = 0; ni < 4; ++ni)
#pragma unroll
            for (int q = 0; q < 4; ++q) acc[mi][ni][q] = 0.f;

    int aR[4], aKV[4], bKR[4], bNV[4];
#pragma unroll
    for (int i = 0; i < 4; ++i) {
        int lin = tid + i * 256;
        aR[i]  = lin >> 3;
        aKV[i] = (lin & 7) * 4;
        bKR[i] = lin >> 5;
        bNV[i] = (lin & 31) * 4;
    }

    float4 avP[4], bvP[4];
    auto prefetch = [&](int kt) {
#pragma unroll
        for (int i = 0; i < 4; ++i)
            avP[i] = *(const float4*)(A + (size_t)(m0 + aR[i]) * lda + kt + aKV[i]);
#pragma unroll
        for (int i = 0; i < 4; ++i)
            bvP[i] = *(const float4*)(B + (size_t)(kt + bKR[i]) * ldb + n0 + bNV[i]);
    };

    prefetch(0);

    for (int kt = 0; kt < K; kt += TKT) {
        __syncthreads();
#pragma unroll
        for (int i = 0; i < 4; ++i) {
            float* p = &Asm[aR[i]][aKV[i]];
            p[0] = tf32r(avP[i].x); p[1] = tf32r(avP[i].y);
            p[2] = tf32r(avP[i].z); p[3] = tf32r(avP[i].w);
        }
#pragma unroll
        for (int i = 0; i < 4; ++i) {
            float* p = &Bsm[bKR[i]][bNV[i]];
            p[0] = tf32r(bvP[i].x); p[1] = tf32r(bvP[i].y);
            p[2] = tf32r(bvP[i].z); p[3] = tf32r(bvP[i].w);
        }
        __syncthreads();

        if (kt + TKT < K) prefetch(kt + TKT);

#pragma unroll
        for (int k0 = 0; k0 < TKT; k0 += 8) {
            unsigned af[4][4], bf[4][2];
#pragma unroll
            for (int mi = 0; mi < 4; ++mi) {
                int rb = wm + mi * 16;
                af[mi][0] = __float_as_uint(Asm[rb + fr][k0 + fc]);
                af[mi][1] = __float_as_uint(Asm[rb + fr + 8][k0 + fc]);
                af[mi][2] = __float_as_uint(Asm[rb + fr][k0 + fc + 4]);
                af[mi][3] = __float_as_uint(Asm[rb + fr + 8][k0 + fc + 4]);
            }
#pragma unroll
            for (int ni = 0; ni < 4; ++ni) {
                int nb = wn + ni * 8;
                bf[ni][0] = __float_as_uint(Bsm[k0 + fc][nb + fr]);
                bf[ni][1] = __float_as_uint(Bsm[k0 + fc + 4][nb + fr]);
            }
#pragma unroll
            for (int mi = 0; mi < 4; ++mi)
#pragma unroll
                for (int ni = 0; ni < 4; ++ni)
                    mma_tf32(acc[mi][ni], af[mi], bf[ni], acc[mi][ni]);
        }
    }

    const int cc = (lane & 3) * 2;
#pragma unroll
    for (int mi = 0; mi < 4; ++mi) {
        int rloc0 = m0 + wm + mi * 16 + fr;
        int rloc1 = rloc0 + 8;
#pragma unroll
        for (int ni = 0; ni < 4; ++ni) {
            int col = n0 + wn + ni * 8 + cc;
            {
                size_t cr = (size_t)rloc0 * ldc;
                C[cr + col]     = acc[mi][ni][0];
                C[cr + col + 1] = acc[mi][ni][1];
            }
            {
                size_t cr = (size_t)rloc1 * ldc;
                C[cr + col]     = acc[mi][ni][2];
                C[cr + col + 1] = acc[mi][ni][3];
            }
        }
    }
}

__global__ __launch_bounds__(256, 2) void mma_plain(
    const float* __restrict__ A, int lda,
    const float* __restrict__ B, int ldb,
    float* __restrict__ C, int ldc, int M, int K)
{
    mma_tile_dev(A, lda, B, ldb, C, ldc, M, K,
                 blockIdx.y * TM, blockIdx.x * TN);
}

// ----- 3xTF32 split GEMM (Wo path: near-fp32 precision on tensor cores) -----
// a = hi + lo (hi = tf32rna(a), lo = tf32rna(a-hi)); ab ~= hh + hl + lh.
// Per-element error ~2^-22: routing-flip-safe (gate needs <=~5e-6 on xf).
#define T3K 16
#define A3STR 20    // (20*fr + fc) covers all 32 banks
#define B3STR 136

__global__ __launch_bounds__(256) void mma3_plain(
    const float* __restrict__ A, int lda,
    const float* __restrict__ B, int ldb,
    const float* __restrict__ Cadd,
    float* __restrict__ C, int ldc, int M, int K)
{
    __shared__ float Ah[TM][A3STR], Al[TM][A3STR];
    __shared__ float Bh[T3K][B3STR], Bl[T3K][B3STR];
    const int tid  = threadIdx.x;
    const int lane = tid & 31;
    const int warp = tid >> 5;
    const int wm = (warp & 1) * 64;
    const int wn = (warp >> 1) * 32;
    const int fr = lane >> 2;
    const int fc = lane & 3;
    const int m0 = blockIdx.y * TM;
    const int n0 = blockIdx.x * TN;

    float acc[4][4][4];
#pragma unroll
    for (int mi = 0; mi < 4; ++mi)
#pragma unroll
        for (int ni = 0; ni < 4; ++ni)
#pragma unroll
            for (int q = 0; q < 4; ++q) acc[mi][ni][q] = 0.f;

    // loaders: A 128x16 = 512 float4 -> 2/thread; B 16x128 = 512 -> 2/thread
    int aR[2], aKV[2], bKR[2], bNV[2];
#pragma unroll
    for (int i = 0; i < 2; ++i) {
        int lin = tid + i * 256;
        aR[i]  = lin >> 2;
        aKV[i] = (lin & 3) * 4;
        bKR[i] = lin >> 5;
        bNV[i] = (lin & 31) * 4;
    }

    float4 avP[2], bvP[2];
    auto prefetch = [&](int kt) {
#pragma unroll
        for (int i = 0; i < 2; ++i)
            avP[i] = *(const float4*)(A + (size_t)(m0 + aR[i]) * lda + kt + aKV[i]);
#pragma unroll
        for (int i = 0; i < 2; ++i)
            bvP[i] = *(const float4*)(B + (size_t)(kt + bKR[i]) * ldb + n0 + bNV[i]);
    };

    prefetch(0);

    for (int kt = 0; kt < K; kt += T3K) {
        __syncthreads();
#pragma unroll
        for (int i = 0; i < 2; ++i) {
            float* ph = &Ah[aR[i]][aKV[i]];
            float* pl = &Al[aR[i]][aKV[i]];
            float h;
            h = tf32r(avP[i].x); ph[0] = h; pl[0] = tf32r(avP[i].x - h);
            h = tf32r(avP[i].y); ph[1] = h; pl[1] = tf32r(avP[i].y - h);
            h = tf32r(avP[i].z); ph[2] = h; pl[2] = tf32r(avP[i].z - h);
            h = tf32r(avP[i].w); ph[3] = h; pl[3] = tf32r(avP[i].w - h);
        }
#pragma unroll
        for (int i = 0; i < 2; ++i) {
            float* ph = &Bh[bKR[i]][bNV[i]];
            float* pl = &Bl[bKR[i]][bNV[i]];
            float h;
            h = tf32r(bvP[i].x); ph[0] = h; pl[0] = tf32r(bvP[i].x - h);
            h = tf32r(bvP[i].y); ph[1] = h; pl[1] = tf32r(bvP[i].y - h);
            h = tf32r(bvP[i].z); ph[2] = h; pl[2] = tf32r(bvP[i].z - h);
            h = tf32r(bvP[i].w); ph[3] = h; pl[3] = tf32r(bvP[i].w - h);
        }
        __syncthreads();

        if (kt + T3K < K) prefetch(kt + T3K);

#pragma unroll
        for (int k0 = 0; k0 < T3K; k0 += 8) {
            unsigned afh[4][4], afl[4][4], bfh[4][2], bfl[4][2];
#pragma unroll
            for (int mi = 0; mi < 4; ++mi) {
                int rb = wm + mi * 16;
                afh[mi][0] = __float_as_uint(Ah[rb + fr][k0 + fc]);
                afh[mi][1] = __float_as_uint(Ah[rb + fr + 8][k0 + fc]);
                afh[mi][2] = __float_as_uint(Ah[rb + fr][k0 + fc + 4]);
                afh[mi][3] = __float_as_uint(Ah[rb + fr + 8][k0 + fc + 4]);
                afl[mi][0] = __float_as_uint(Al[rb + fr][k0 + fc]);
                afl[mi][1] = __float_as_uint(Al[rb + fr + 8][k0 + fc]);
                afl[mi][2] = __float_as_uint(Al[rb + fr][k0 + fc + 4]);
                afl[mi][3] = __float_as_uint(Al[rb + fr + 8][k0 + fc + 4]);
            }
#pragma unroll
            for (int ni = 0; ni < 4; ++ni) {
                int nb = wn + ni * 8;
                bfh[ni][0] = __float_as_uint(Bh[k0 + fc][nb + fr]);
                bfh[ni][1] = __float_as_uint(Bh[k0 + fc + 4][nb + fr]);
                bfl[ni][0] = __float_as_uint(Bl[k0 + fc][nb + fr]);
                bfl[ni][1] = __float_as_uint(Bl[k0 + fc + 4][nb + fr]);
            }
#pragma unroll
            for (int mi = 0; mi < 4; ++mi)
#pragma unroll
                for (int ni = 0; ni < 4; ++ni) {
                    mma_tf32(acc[mi][ni], afl[mi], bfh[ni], acc[mi][ni]);
                    mma_tf32(acc[mi][ni], afh[mi], bfl[ni], acc[mi][ni]);
                    mma_tf32(acc[mi][ni], afh[mi], bfh[ni], acc[mi][ni]);
                }
        }
    }

    const int cc = (lane & 3) * 2;
#pragma unroll
    for (int mi = 0; mi < 4; ++mi) {
        int rloc0 = m0 + wm + mi * 16 + fr;
        int rloc1 = rloc0 + 8;
#pragma unroll
        for (int ni = 0; ni < 4; ++ni) {
            int col = n0 + wn + ni * 8 + cc;
            {
                size_t cr = (size_t)rloc0 * ldc;
                C[cr + col]     = acc[mi][ni][0] + Cadd[cr + col];
                C[cr + col + 1] = acc[mi][ni][1] + Cadd[cr + col + 1];
            }
            {
                size_t cr = (size_t)rloc1 * ldc;
                C[cr + col]     = acc[mi][ni][2] + Cadd[cr + col];
                C[cr + col + 1] = acc[mi][ni][3] + Cadd[cr + col + 1];
            }
        }
    }
}

// -------- shared fp16 mma helpers --------
__device__ __forceinline__ void ldsm_x4(unsigned& r0, unsigned& r1,
                                        unsigned& r2, unsigned& r3,
                                        unsigned addr) {
    asm volatile("ldmatrix.sync.aligned.m8n8.x4.shared.b16 {%0,%1,%2,%3}, [%4];"
                 : "=r"(r0), "=r"(r1), "=r"(r2), "=r"(r3) : "r"(addr));
}
__device__ __forceinline__ void ldsm_x4_t(unsigned& r0, unsigned& r1,
                                          unsigned& r2, unsigned& r3,
                                          unsigned addr) {
    asm volatile("ldmatrix.sync.aligned.m8n8.x4.trans.shared.b16 {%0,%1,%2,%3}, [%4];"
                 : "=r"(r0), "=r"(r1), "=r"(r2), "=r"(r3) : "r"(addr));
}
__device__ __forceinline__ void mma_f16(float* d, const unsigned* a,
                                        const unsigned* b, const float* c) {
    asm volatile(
        "mma.sync.aligned.m16n8k16.row.col.f32.f16.f16.f32 "
        "{%0,%1,%2,%3}, {%4,%5,%6,%7}, {%8,%9}, {%10,%11,%12,%13};"
        : "=f"(d[0]), "=f"(d[1]), "=f"(d[2]), "=f"(d[3])
        : "r"(a[0]), "r"(a[1]), "r"(a[2]), "r"(a[3]),
          "r"(b[0]), "r"(b[1]),
          "f"(c[0]), "f"(c[1]), "f"(c[2]), "f"(c[3]));
}

// -------- fp16 expert GEMM: m16n8k16 + ldmatrix + register prefetch --------
#define HASTR 40
#define HBSTR 136

__device__ __forceinline__ void hmma_tile_dev(
    const float* __restrict__ A, int lda,
    const float* __restrict__ B, int ldb,
    const float* __restrict__ bias,
    float* __restrict__ C, int ldc,
    int M, int K,
    const int* __restrict__ gmap,
    int m0, int n0, int cRow0)
{
    __shared__ __half AsmH[TM * HASTR];
    __shared__ __half BsmH[TKT * HBSTR];

    const int tid  = threadIdx.x;
    const int lane = tid & 31;
    const int warp = tid >> 5;
    const int wm = (warp & 1) * 64;
    const int wn = (warp >> 1) * 32;
    const int fr = lane >> 2;

    const int lm  = lane >> 3;
    const int l7  = lane & 7;
    const int aRowOff = (lm & 1) * 8 + l7;
    const int aKOff   = (lm >> 1) * 8;
    const int bKOff = (lm & 1) * 8 + l7;
    const int bNOff = (lm >> 1) * 8;

    float acc[4][4][4];
#pragma unroll
    for (int mi = 0; mi < 4; ++mi)
#pragma unroll
        for (int ni = 0; ni < 4; ++ni)
#pragma unroll
            for (int q = 0; q < 4; ++q) acc[mi][ni][q] = 0.f;

    int aR[4], aKV[4]; bool avalid[4]; size_t arow[4];
    int bKR[4], bNV[4];
#pragma unroll
    for (int i = 0; i < 4; ++i) {
        int lin = tid + i * 256;
        aR[i]  = lin >> 3;
        aKV[i] = (lin & 7) * 4;
        int gr = m0 + aR[i];
        avalid[i] = gr < M;
        arow[i] = avalid[i] ? (size_t)(gmap ? gmap[gr] : gr) : 0;
        bKR[i] = lin >> 5;
        bNV[i] = (lin & 31) * 4;
    }

    float4 avP[4], bvP[4];
    auto prefetch = [&](int kt) {
#pragma unroll
        for (int i = 0; i < 4; ++i)
            avP[i] = avalid[i] ? *(const float4*)(A + arow[i] * lda + kt + aKV[i])
                               : make_float4(0.f, 0.f, 0.f, 0.f);
#pragma unroll
        for (int i = 0; i < 4; ++i)
            bvP[i] = *(const float4*)(B + (size_t)(kt + bKR[i]) * ldb + n0 + bNV[i]);
    };

    prefetch(0);

    for (int kt = 0; kt < K; kt += TKT) {
        __syncthreads();
#pragma unroll
        for (int i = 0; i < 4; ++i) {
            __half2* dst = (__half2*)&AsmH[aR[i] * HASTR + aKV[i]];
            dst[0] = __floats2half2_rn(avP[i].x, avP[i].y);
            dst[1] = __floats2half2_rn(avP[i].z, avP[i].w);
        }
#pragma unroll
        for (int i = 0; i < 4; ++i) {
            __half2* dst = (__half2*)&BsmH[bKR[i] * HBSTR + bNV[i]];
            dst[0] = __floats2half2_rn(bvP[i].x, bvP[i].y);
            dst[1] = __floats2half2_rn(bvP[i].z, bvP[i].w);
        }
        __syncthreads();

        if (kt + TKT < K) prefetch(kt + TKT);

#pragma unroll
        for (int k0 = 0; k0 < TKT; k0 += 16) {
            unsigned af[4][4], bf[4][2];
#pragma unroll
            for (int mi = 0; mi < 4; ++mi) {
                int rb = wm + mi * 16;
                unsigned addr = (unsigned)__cvta_generic_to_shared(
                    &AsmH[(rb + aRowOff) * HASTR + k0 + aKOff]);
                ldsm_x4(af[mi][0], af[mi][1], af[mi][2], af[mi][3], addr);
            }
#pragma unroll
            for (int p = 0; p < 2; ++p) {
                int nb = wn + p * 16;
                unsigned addr = (unsigned)__cvta_generic_to_shared(
                    &BsmH[(k0 + bKOff) * HBSTR + nb + bNOff]);
                ldsm_x4_t(bf[2 * p][0], bf[2 * p][1],
                          bf[2 * p + 1][0], bf[2 * p + 1][1], addr);
            }
#pragma unroll
            for (int mi = 0; mi < 4; ++mi)
#pragma unroll
                for (int ni = 0; ni < 4; ++ni)
                    mma_f16(acc[mi][ni], af[mi], bf[ni], acc[mi][ni]);
        }
    }

    const int cc = (lane & 3) * 2;
#pragma unroll
    for (int mi = 0; mi < 4; ++mi) {
        int rloc0 = m0 + wm + mi * 16 + fr;
        int rloc1 = rloc0 + 8;
#pragma unroll
        for (int ni = 0; ni < 4; ++ni) {
            int col = n0 + wn + ni * 8 + cc;
            float b0 = bias ? bias[col] : 0.f;
            float b1 = bias ? bias[col + 1] : 0.f;
            if (rloc0 < M) {
                size_t cr = (size_t)(cRow0 + rloc0) * ldc;
                C[cr + col]     = acc[mi][ni][0] + b0;
                C[cr + col + 1] = acc[mi][ni][1] + b1;
            }
            if (rloc1 < M) {
                size_t cr = (size_t)(cRow0 + rloc1) * ldc;
                C[cr + col]     = acc[mi][ni][2] + b0;
                C[cr + col + 1] = acc[mi][ni][3] + b1;
            }
        }
    }
}

__global__ __launch_bounds__(256, 2) void hmma_expert_up(
    const float* __restrict__ xf,
    const float* __restrict__ W1, const float* __restrict__ b1,
    float* __restrict__ h1)
{
    int e = blockIdx.z;
    int cnt = d_cnt[e];
    int m0 = blockIdx.y * TM;
    if (m0 >= cnt) return;
    int off = d_offs[e];
    hmma_tile_dev(xf, DMODEL,
                  W1 + (size_t)e * DMODEL * HID, HID,
                  b1 + (size_t)e * HID,
                  h1, HID, cnt, DMODEL,
                  d_tokrow + off, m0, blockIdx.x * TN, off);
}

__global__ __launch_bounds__(256, 2) void hmma_expert_gv(
    const float* __restrict__ h1,
    const float* __restrict__ Wg, const float* __restrict__ bg,
    const float* __restrict__ Wv, const float* __restrict__ bv,
    float* __restrict__ Ge, float* __restrict__ Ve)
{
    int e = blockIdx.z;
    int cnt = d_cnt[e];
    int m0 = blockIdx.y * TM;
    if (m0 >= cnt) return;
    int off = d_offs[e];
    const int halfTiles = DMODEL / TN;
    bool isV = blockIdx.x >= halfTiles;
    int n0 = (blockIdx.x - (isV ? halfTiles : 0)) * TN;
    const float* B    = (isV ? Wv : Wg) + (size_t)e * HID * DMODEL;
    const float* bias = (isV ? bv : bg) + (size_t)e * DMODEL;
    float* C = isV ? Ve : Ge;
    hmma_tile_dev(h1 + (size_t)off * HID, HID, B, DMODEL, bias,
                  C, DMODEL, cnt, HID, nullptr, m0, n0, off);
}

// ---------------- flash attention (fp32, causal, GQA — R14 proven) ----------
__global__ __launch_bounds__(64) void attn_kernel(
    const float* __restrict__ Q, const float* __restrict__ Kb,
    const float* __restrict__ Vb, float* __restrict__ ctx)
{
    const int qb = blockIdx.x, h = blockIdx.y, b = blockIdx.z;
    const int r = threadIdx.x;
    const int qglob = qb * 64 + r;
    const size_t t = (size_t)b * SEQ + qglob;
    const int kh = h >> 2;

    float q[DK];
    const float* qp = Q + t * DMODEL + h * DK;
#pragma unroll
    for (int d4 = 0; d4 < 16; ++d4) {
        float4 v = *(const float4*)(qp + d4 * 4);
        q[d4 * 4 + 0] = v.x; q[d4 * 4 + 1] = v.y;
        q[d4 * 4 + 2] = v.z; q[d4 * 4 + 3] = v.w;
    }
    float acc[DK];
#pragma unroll
    for (int d = 0; d < DK; ++d) acc[d] = 0.f;
    float mval = -3.4e38f, lsum = 0.f;

    __shared__ float Ksm[64][DK];
    __shared__ float Vsm[64][DK];

    for (int kt = 0; kt <= qb; ++kt) {
        __syncthreads();
        {
            size_t krow = (size_t)b * SEQ + kt * 64 + r;
            const float4* kp = (const float4*)(Kb + krow * KVDIM + kh * DK);
            const float4* vp = (const float4*)(Vb + krow * KVDIM + kh * DK);
#pragma unroll
            for (int c = 0; c < 16; ++c) {
                ((float4*)Ksm[r])[c] = kp[c];
                ((float4*)Vsm[r])[c] = vp[c];
            }
        }
        __syncthreads();
        const int kmax = (kt == qb) ? r : 63;
        for (int c0 = 0; c0 <= kmax; c0 += 16) {
            float s[16];
            float mch = -3.4e38f;
#pragma unroll
            for (int j = 0; j < 16; ++j) {
                int k = c0 + j;
                float dot = 0.f;
                const float4* kr = (const float4*)Ksm[k];
#pragma unroll
                for (int d4 = 0; d4 < 16; ++d4) {
                    float4 kv = kr[d4];
                    dot += q[d4 * 4 + 0] * kv.x + q[d4 * 4 + 1] * kv.y
                         + q[d4 * 4 + 2] * kv.z + q[d4 * 4 + 3] * kv.w;
                }
                s[j] = (k <= kmax) ? dot * 0.125f : -3.4e38f;
                mch = fmaxf(mch, s[j]);
            }
            float mnew = fmaxf(mval, mch);
            float corr = __expf(mval - mnew);
            lsum *= corr;
#pragma unroll
            for (int d = 0; d < DK; ++d) acc[d] *= corr;
#pragma unroll
            for (int j = 0; j < 16; ++j) {
                float p = __expf(s[j] - mnew);
                lsum += p;
                const float4* vr = (const float4*)Vsm[c0 + j];
#pragma unroll
                for (int d4 = 0; d4 < 16; ++d4) {
                    float4 vv = vr[d4];
                    acc[d4 * 4 + 0] += p * vv.x;
                    acc[d4 * 4 + 1] += p * vv.y;
                    acc[d4 * 4 + 2] += p * vv.z;
                    acc[d4 * 4 + 3] += p * vv.w;
                }
            }
            mval = mnew;
        }
    }
    float inv = 1.f / lsum;
    float* op = ctx + t * DMODEL + h * DK;
#pragma unroll
    for (int d = 0; d < DK; ++d) op[d] = acc[d] * inv;
}

// ---------------- gating ----------------
__global__ void gate_kernel(const float* __restrict__ xf,
                            const float* __restrict__ gateE) {
    int warp = (blockIdx.x * blockDim.x + threadIdx.x) >> 5;
    int lane = threadIdx.x & 31;
    if (warp >= TTOK) return;
    int t = warp;
    float acc[NEXP];
#pragma unroll
    for (int e = 0; e < NEXP; ++e) acc[e] = 0.f;
    for (int d = lane; d < DMODEL; d += 32) {
        float xv = xf[(size_t)t * DMODEL + d];
#pragma unroll
        for (int e = 0; e < NEXP; ++e) acc[e] += xv * gateE[d * NEXP + e];
    }
#pragma unroll
    for (int e = 0; e < NEXP; ++e)
#pragma unroll
        for (int o = 16; o > 0; o >>= 1)
            acc[e] += __shfl_xor_sync(0xffffffff, acc[e], o);
    if (lane == 0) {
        int i0 = 0; float v0 = acc[0];
#pragma unroll
        for (int e = 1; e < NEXP; ++e) if (acc[e] > v0) { v0 = acc[e]; i0 = e; }
        int i1 = -1; float v1 = -3.4e38f;
#pragma unroll
        for (int e = 0; e < NEXP; ++e)
            if (e != i0 && acc[e] > v1) { v1 = acc[e]; i1 = e; }
        if (i1 < 0) { i1 = (i0 + 1) & (NEXP - 1); v1 = v0; }
        float w0 = 1.f / (1.f + __expf(v1 - v0));
        float w1 = 1.f - w0;
        d_top[2 * t]     = i0;  d_tw[2 * t]     = w0;
        d_top[2 * t + 1] = i1;  d_tw[2 * t + 1] = w1;
    }
}

__global__ void bucket_kernel() {
    __shared__ int tops[NSLOT];
    __shared__ int cnt[NEXP];
    for (int s = threadIdx.x; s < NSLOT; s += blockDim.x) tops[s] = d_top[s];
    if (threadIdx.x < NEXP) cnt[threadIdx.x] = 0;
    __syncthreads();
    if (threadIdx.x == 0) {
        for (int s = 0; s < NSLOT; ++s) {
            int e = tops[s];
            d_pos[s] = cnt[e]++;
        }
        int o = 0;
        for (int e = 0; e < NEXP; ++e) { d_offs[e] = o; d_cnt[e] = cnt[e]; o += cnt[e]; }
    }
    __syncthreads();
    for (int s = threadIdx.x; s < NSLOT; s += blockDim.x) {
        int e = tops[s];
        int j = d_offs[e] + d_pos[s];
        d_rowof[s] = j;
        d_tokrow[j] = s >> 1;
    }
}

__global__ void combine_kernel(const float* __restrict__ Ge,
                               const float* __restrict__ Ve,
                               float* __restrict__ out) {
    int t = blockIdx.x;
    int j0 = d_rowof[2 * t],     j1 = d_rowof[2 * t + 1];
    float w0 = d_tw[2 * t],      w1 = d_tw[2 * t + 1];
    const float4* g0p = (const float4*)(Ge + (size_t)j0 * DMODEL);
    const float4* v0p = (const float4*)(Ve + (size_t)j0 * DMODEL);
    const float4* g1p = (const float4*)(Ge + (size_t)j1 * DMODEL);
    const float4* v1p = (const float4*)(Ve + (size_t)j1 * DMODEL);
    float4* op = (float4*)(out + (size_t)t * DMODEL);
    for (int d = threadIdx.x; d < DMODEL / 4; d += blockDim.x) {
        float4 g0 = g0p[d], g1 = g1p[d], v0 = v0p[d], v1 = v1p[d], o = op[d];
        o.x += w0 * (g0.x / (1.f + __expf(-g0.x))) * v0.x + w1 * (g1.x / (1.f + __expf(-g1.x))) * v1.x;
        o.y += w0 * (g0.y / (1.f + __expf(-g0.y))) * v0.y + w1 * (g1.y / (1.f + __expf(-g1.y))) * v1.y;
        o.z += w0 * (g0.z / (1.f + __expf(-g0.z))) * v0.z + w1 * (g1.z / (1.f + __expf(-g1.z))) * v1.z;
        o.w += w0 * (g0.w / (1.f + __expf(-g0.w))) * v0.w + w1 * (g1.w / (1.f + __expf(-g1.w))) * v1.w;
        op[d] = o;
    }
}

// ---------------- launch ----------------
extern "C" void kernel_launch(void* const* d_in, const int* in_sizes, int n_in,
                              void* d_out, int out_size) {
    const float* x      = (const float*)d_in[0];
    const float* fcos   = (const float*)d_in[1];
    const float* fsin   = (const float*)d_in[2];
    const int*   taskid = (const int*)  d_in[3];
    const float* n1w    = (const float*)d_in[4];
    const float* n2w    = (const float*)d_in[5];
    const float* WqT    = (const float*)d_in[6];
    const float* WkT    = (const float*)d_in[7];
    const float* WvT    = (const float*)d_in[8];
    const float* WoT    = (const float*)d_in[9];
    const float* qA     = (const float*)d_in[10];
    const float* qB     = (const float*)d_in[11];
    const float* kA     = (const float*)d_in[12];
    const float* kB     = (const float*)d_in[13];
    const float* vA     = (const float*)d_in[14];
    const float* vB     = (const float*)d_in[15];
    const float* gateWT = (const float*)d_in[16];
    const float* gA     = (const float*)d_in[17];
    const float* gB     = (const float*)d_in[18];
    const float* temb   = (const float*)d_in[19];
    const float* eW1    = (const float*)d_in[20];
    const float* eb1    = (const float*)d_in[21];
    const float* eWg    = (const float*)d_in[22];
    const float* ebg    = (const float*)d_in[23];
    const float* eWv    = (const float*)d_in[24];
    const float* ebv    = (const float*)d_in[25];
    float* out = (float*)d_out;

    float *p_h, *p_WqE, *p_WkE, *p_WvE, *p_gateE, *p_Q, *p_Kb, *p_Vb,
          *p_ctx, *p_xf, *p_h1, *p_Ge, *p_Ve;
    cudaGetSymbolAddress((void**)&p_h,     d_h);
    cudaGetSymbolAddress((void**)&p_WqE,   d_WqE);
    cudaGetSymbolAddress((void**)&p_WkE,   d_WkE);
    cudaGetSymbolAddress((void**)&p_WvE,   d_WvE);
    cudaGetSymbolAddress((void**)&p_gateE, d_gateE);
    cudaGetSymbolAddress((void**)&p_Q,     d_Q);
    cudaGetSymbolAddress((void**)&p_Kb,    d_Kb);
    cudaGetSymbolAddress((void**)&p_Vb,    d_Vb);
    cudaGetSymbolAddress((void**)&p_ctx,   d_ctx);
    cudaGetSymbolAddress((void**)&p_xf,    d_xf);
    cudaGetSymbolAddress((void**)&p_h1,    d_h1);
    cudaGetSymbolAddress((void**)&p_Ge,    d_Ge);
    cudaGetSymbolAddress((void**)&p_Ve,    d_Ve);

    eff_weight_kernel<<<(DMODEL * DMODEL + 255) / 256, 256>>>(WqT, qA, qB, p_WqE, DMODEL, DMODEL * DMODEL);
    eff_weight_kernel<<<(DMODEL * KVDIM + 255) / 256, 256>>>(WkT, kA, kB, p_WkE, KVDIM, DMODEL * KVDIM);
    eff_weight_kernel<<<(DMODEL * KVDIM + 255) / 256, 256>>>(WvT, vA, vB, p_WvE, KVDIM, DMODEL * KVDIM);
    eff_weight_kernel<<<(DMODEL * NEXP + 255) / 256, 256>>>(gateWT, gA, gB, p_gateE, NEXP, DMODEL * NEXP);

    rmsnorm1_kernel<<<TTOK, 256>>>(x, n1w, p_h);

    // QKV: tf32 tensor cores + register prefetch
    mma_plain<<<dim3(DMODEL / TN, TTOK / TM), 256>>>(p_h, DMODEL, p_WqE, DMODEL, p_Q, DMODEL, TTOK, DMODEL);
    mma_plain<<<dim3(KVDIM / TN, TTOK / TM), 256>>>(p_h, DMODEL, p_WkE, KVDIM, p_Kb, KVDIM, TTOK, DMODEL);
    mma_plain<<<dim3(KVDIM / TN, TTOK / TM), 256>>>(p_h, DMODEL, p_WvE, KVDIM, p_Vb, KVDIM, TTOK, DMODEL);

    rope_kernel<<<TTOK, 512>>>(p_Q, p_Kb, fcos, fsin);

    // flash attention: scalar fp32 (R14 proven; fp16 TC flips routing)
    attn_kernel<<<dim3(SEQ / 64, NHEAD, 2), 64>>>(p_Q, p_Kb, p_Vb, p_ctx);

    // Wo: 3xTF32 split — near-fp32 precision on tensor cores (gate-safe)
    mma3_plain<<<dim3(DMODEL / TN, TTOK / TM), 256>>>(p_ctx, DMODEL, WoT, DMODEL, x, out, DMODEL, TTOK, DMODEL);

    rmsnorm2_kernel<<<TTOK, 256>>>(out, n2w, taskid, temb, p_xf);

    gate_kernel<<<(TTOK * 32 + 255) / 256, 256>>>(p_xf, p_gateE);
    bucket_kernel<<<1, 256>>>();

    // expert GEMMs: fp16 + ldmatrix + prefetch; GEMM2/3 fused
    hmma_expert_up<<<dim3(HID / TN, TTOK / TM, NEXP), 256>>>(
        p_xf, eW1, eb1, p_h1);
    hmma_expert_gv<<<dim3(2 * DMODEL / TN, TTOK / TM, NEXP), 256>>>(
        p_h1, eWg, ebg, eWv, ebv, p_Ge, p_Ve);

    combine_kernel<<<TTOK, 256>>>(p_Ge, p_Ve, out);
}

// round 17
// speedup vs baseline: 1.4498x; 1.0150x over previous
#include <cuda_runtime.h>
#include <cuda_fp16.h>
#include <cuda_bf16.h>
#include <math.h>

// ---------------- problem constants ----------------
#define DMODEL 1024
#define NHEAD  16
#define NKV    4
#define DK     64
#define NEXP   8
#define TOPK   2
#define RLORA  16
#define SCALE_LORA 2.0f
#define HID    4096
#define TTOK   2048
#define SEQ    1024
#define KVDIM  256
#define NSLOT  (TTOK * TOPK)

// ---------------- scratch ----------------
__device__ float d_h   [TTOK * DMODEL];
__device__ float d_WqE [DMODEL * DMODEL];
__device__ float d_WkE [DMODEL * KVDIM];
__device__ float d_WvE [DMODEL * KVDIM];
__device__ float d_gateE[DMODEL * NEXP];
__device__ float d_Q   [TTOK * DMODEL];
__device__ float d_Kb  [TTOK * KVDIM];
__device__ float d_Vb  [TTOK * KVDIM];
__device__ float d_ctx [TTOK * DMODEL];
__device__ float d_xf  [TTOK * DMODEL];
__device__ float d_h1  [NSLOT * HID];
__device__ float d_Ge  [NSLOT * DMODEL];
__device__ float d_Ve  [NSLOT * DMODEL];
__device__ int   d_top   [NSLOT];
__device__ float d_tw    [NSLOT];
__device__ int   d_pos   [NSLOT];
__device__ int   d_rowof [NSLOT];
__device__ int   d_tokrow[NSLOT];
__device__ int   d_cnt   [NEXP];
__device__ int   d_offs  [NEXP];

// ---------------- small kernels ----------------
__global__ void eff_weight_kernel(const float* __restrict__ WT,
                                  const float* __restrict__ A,
                                  const float* __restrict__ B,
                                  float* __restrict__ out, int N, int total) {
    int i = blockIdx.x * blockDim.x + threadIdx.x;
    if (i >= total) return;
    int k = i / N, n = i - k * N;
    float s = 0.f;
#pragma unroll
    for (int r = 0; r < RLORA; ++r) s += A[k * RLORA + r] * B[r * N + n];
    out[i] = WT[i] + SCALE_LORA * s;
}

__global__ void rmsnorm1_kernel(const float* __restrict__ x,
                                const float* __restrict__ w,
                                float* __restrict__ h) {
    int t = blockIdx.x;
    __shared__ float red[256];
    float ss = 0.f;
    for (int d = threadIdx.x; d < DMODEL; d += 256) {
        float v = x[(size_t)t * DMODEL + d];
        ss += v * v;
    }
    red[threadIdx.x] = ss; __syncthreads();
    for (int s = 128; s > 0; s >>= 1) {
        if (threadIdx.x < s) red[threadIdx.x] += red[threadIdx.x + s];
        __syncthreads();
    }
    float rs = rsqrtf(red[0] / (float)DMODEL + 1e-6f);
    for (int d = threadIdx.x; d < DMODEL; d += 256)
        h[(size_t)t * DMODEL + d] = x[(size_t)t * DMODEL + d] * rs * w[d];
}

__global__ void rmsnorm2_kernel(const float* __restrict__ xin,
                                const float* __restrict__ w,
                                const int* __restrict__ taskid,
                                const float* __restrict__ temb,
                                float* __restrict__ xf) {
    int t = blockIdx.x;
    __shared__ float red[256];
    float ss = 0.f;
    for (int d = threadIdx.x; d < DMODEL; d += 256) {
        float v = xin[(size_t)t * DMODEL + d];
        ss += v * v;
    }
    red[threadIdx.x] = ss; __syncthreads();
    for (int s = 128; s > 0; s >>= 1) {
        if (threadIdx.x < s) red[threadIdx.x] += red[threadIdx.x + s];
        __syncthreads();
    }
    float rs = rsqrtf(red[0] / (float)DMODEL + 1e-6f);
    int tk = taskid[t];
    for (int d = threadIdx.x; d < DMODEL; d += 256)
        xf[(size_t)t * DMODEL + d] =
            xin[(size_t)t * DMODEL + d] * rs * w[d] + temb[tk * DMODEL + d];
}

__global__ void rope_kernel(float* __restrict__ Q, float* __restrict__ K,
                            const float* __restrict__ fcos,
                            const float* __restrict__ fsin) {
    int t = blockIdx.x;
    int s = t & (SEQ - 1);
    int tid = threadIdx.x;
    int h = tid >> 5;
    int d = tid & 31;
    float c1 = fcos[s * DK + d],      s1 = fsin[s * DK + d];
    float c2 = fcos[s * DK + d + 32], s2 = fsin[s * DK + d + 32];
    {
        float* q = Q + (size_t)t * DMODEL + h * DK;
        float x1 = q[d], x2 = q[d + 32];
        q[d]      = x1 * c1 - x2 * s1;
        q[d + 32] = x2 * c2 + x1 * s2;
    }
    if (h < NKV) {
        float* k = K + (size_t)t * KVDIM + h * DK;
        float x1 = k[d], x2 = k[d + 32];
        k[d]      = x1 * c1 - x2 * s1;
        k[d + 32] = x2 * c2 + x1 * s2;
    }
}

// ---------------- mma helpers ----------------
__device__ __forceinline__ float tf32r(float f) {
    unsigned u;
    asm("cvt.rna.tf32.f32 %0, %1;" : "=r"(u) : "f"(f));
    return __uint_as_float(u);
}

__device__ __forceinline__ void mma_tf32(float* d, const unsigned* a,
                                         const unsigned* b, const float* c) {
    asm volatile(
        "mma.sync.aligned.m16n8k8.row.col.f32.tf32.tf32.f32 "
        "{%0,%1,%2,%3}, {%4,%5,%6,%7}, {%8,%9}, {%10,%11,%12,%13};"
        : "=f"(d[0]), "=f"(d[1]), "=f"(d[2]), "=f"(d[3])
        : "r"(a[0]), "r"(a[1]), "r"(a[2]), "r"(a[3]),
          "r"(b[0]), "r"(b[1]),
          "f"(c[0]), "f"(c[1]), "f"(c[2]), "f"(c[3]));
}

// ------- tf32 tensor-core GEMM (QKV path) + register prefetch ----------
#define TM 128
#define TN 128
#define TKT 32
#define ASTR 36
#define BSTR 136

__device__ __forceinline__ void mma_tile_dev(
    const float* __restrict__ A, int lda,
    const float* __restrict__ B, int ldb,
    float* __restrict__ C, int ldc,
    int M, int K, int m0, int n0)
{
    __shared__ float Asm[TM][ASTR];
    __shared__ float Bsm[TKT][BSTR];
    const int tid  = threadIdx.x;
    const int lane = tid & 31;
    const int warp = tid >> 5;
    const int wm = (warp & 1) * 64;
    const int wn = (warp >> 1) * 32;
    const int fr = lane >> 2;
    const int fc = lane & 3;

    float acc[4][4][4];
#pragma unroll
    for (int mi = 0; mi < 4; ++mi)
#pragma unroll
        for (int ni = 0; ni < 4; ++ni)
#pragma unroll
            for (int q = 0; q < 4; ++q) acc[mi][ni][q] = 0.f;

    int aR[4], aKV[4], bKR[4], bNV[4];
#pragma unroll
    for (int i = 0; i < 4; ++i) {
        int lin = tid + i * 256;
        aR[i]  = lin >> 3;
        aKV[i] = (lin & 7) * 4;
        bKR[i] = lin >> 5;
        bNV[i] = (lin & 31) * 4;
    }

    float4 avP[4], bvP[4];
    auto prefetch = [&](int kt) {
#pragma unroll
        for (int i = 0; i < 4; ++i)
            avP[i] = *(const float4*)(A + (size_t)(m0 + aR[i]) * lda + kt + aKV[i]);
#pragma unroll
        for (int i = 0; i < 4; ++i)
            bvP[i] = *(const float4*)(B + (size_t)(kt + bKR[i]) * ldb + n0 + bNV[i]);
    };

    prefetch(0);

    for (int kt = 0; kt < K; kt += TKT) {
        __syncthreads();
#pragma unroll
        for (int i = 0; i < 4; ++i) {
            float* p = &Asm[aR[i]][aKV[i]];
            p[0] = tf32r(avP[i].x); p[1] = tf32r(avP[i].y);
            p[2] = tf32r(avP[i].z); p[3] = tf32r(avP[i].w);
        }
#pragma unroll
        for (int i = 0; i < 4; ++i) {
            float* p = &Bsm[bKR[i]][bNV[i]];
            p[0] = tf32r(bvP[i].x); p[1] = tf32r(bvP[i].y);
            p[2] = tf32r(bvP[i].z); p[3] = tf32r(bvP[i].w);
        }
        __syncthreads();

        if (kt + TKT < K) prefetch(kt + TKT);

#pragma unroll
        for (int k0 = 0; k0 < TKT; k0 += 8) {
            unsigned af[4][4], bf[4][2];
#pragma unroll
            for (int mi = 0; mi < 4; ++mi) {
                int rb = wm + mi * 16;
                af[mi][0] = __float_as_uint(Asm[rb + fr][k0 + fc]);
                af[mi][1] = __float_as_uint(Asm[rb + fr + 8][k0 + fc]);
                af[mi][2] = __float_as_uint(Asm[rb + fr][k0 + fc + 4]);
                af[mi][3] = __float_as_uint(Asm[rb + fr + 8][k0 + fc + 4]);
            }
#pragma unroll
            for (int ni = 0; ni < 4; ++ni) {
                int nb = wn + ni * 8;
                bf[ni][0] = __float_as_uint(Bsm[k0 + fc][nb + fr]);
                bf[ni][1] = __float_as_uint(Bsm[k0 + fc + 4][nb + fr]);
            }
#pragma unroll
            for (int mi = 0; mi < 4; ++mi)
#pragma unroll
                for (int ni = 0; ni < 4; ++ni)
                    mma_tf32(acc[mi][ni], af[mi], bf[ni], acc[mi][ni]);
        }
    }

    const int cc = (lane & 3) * 2;
#pragma unroll
    for (int mi = 0; mi < 4; ++mi) {
        int rloc0 = m0 + wm + mi * 16 + fr;
        int rloc1 = rloc0 + 8;
#pragma unroll
        for (int ni = 0; ni < 4; ++ni) {
            int col = n0 + wn + ni * 8 + cc;
            {
                size_t cr = (size_t)rloc0 * ldc;
                C[cr + col]     = acc[mi][ni][0];
                C[cr + col + 1] = acc[mi][ni][1];
            }
            {
                size_t cr = (size_t)rloc1 * ldc;
                C[cr + col]     = acc[mi][ni][2];
                C[cr + col + 1] = acc[mi][ni][3];
            }
        }
    }
}

__global__ __launch_bounds__(256, 2) void mma_plain(
    const float* __restrict__ A, int lda,
    const float* __restrict__ B, int ldb,
    float* __restrict__ C, int ldc, int M, int K)
{
    mma_tile_dev(A, lda, B, ldb, C, ldc, M, K,
                 blockIdx.y * TM, blockIdx.x * TN);
}

// ----- 3xTF32 split GEMM (Wo path: near-fp32 precision on tensor cores) -----
#define T3K 16
#define A3STR 20
#define B3STR 136

__global__ __launch_bounds__(256) void mma3_plain(
    const float* __restrict__ A, int lda,
    const float* __restrict__ B, int ldb,
    const float* __restrict__ Cadd,
    float* __restrict__ C, int ldc, int M, int K)
{
    __shared__ float Ah[TM][A3STR], Al[TM][A3STR];
    __shared__ float Bh[T3K][B3STR], Bl[T3K][B3STR];
    const int tid  = threadIdx.x;
    const int lane = tid & 31;
    const int warp = tid >> 5;
    const int wm = (warp & 1) * 64;
    const int wn = (warp >> 1) * 32;
    const int fr = lane >> 2;
    const int fc = lane & 3;
    const int m0 = blockIdx.y * TM;
    const int n0 = blockIdx.x * TN;

    float acc[4][4][4];
#pragma unroll
    for (int mi = 0; mi < 4; ++mi)
#pragma unroll
        for (int ni = 0; ni < 4; ++ni)
#pragma unroll
            for (int q = 0; q < 4; ++q) acc[mi][ni][q] = 0.f;

    int aR[2], aKV[2], bKR[2], bNV[2];
#pragma unroll
    for (int i = 0; i < 2; ++i) {
        int lin = tid + i * 256;
        aR[i]  = lin >> 2;
        aKV[i] = (lin & 3) * 4;
        bKR[i] = lin >> 5;
        bNV[i] = (lin & 31) * 4;
    }

    float4 avP[2], bvP[2];
    auto prefetch = [&](int kt) {
#pragma unroll
        for (int i = 0; i < 2; ++i)
            avP[i] = *(const float4*)(A + (size_t)(m0 + aR[i]) * lda + kt + aKV[i]);
#pragma unroll
        for (int i = 0; i < 2; ++i)
            bvP[i] = *(const float4*)(B + (size_t)(kt + bKR[i]) * ldb + n0 + bNV[i]);
    };

    prefetch(0);

    for (int kt = 0; kt < K; kt += T3K) {
        __syncthreads();
#pragma unroll
        for (int i = 0; i < 2; ++i) {
            float* ph = &Ah[aR[i]][aKV[i]];
            float* pl = &Al[aR[i]][aKV[i]];
            float h;
            h = tf32r(avP[i].x); ph[0] = h; pl[0] = tf32r(avP[i].x - h);
            h = tf32r(avP[i].y); ph[1] = h; pl[1] = tf32r(avP[i].y - h);
            h = tf32r(avP[i].z); ph[2] = h; pl[2] = tf32r(avP[i].z - h);
            h = tf32r(avP[i].w); ph[3] = h; pl[3] = tf32r(avP[i].w - h);
        }
#pragma unroll
        for (int i = 0; i < 2; ++i) {
            float* ph = &Bh[bKR[i]][bNV[i]];
            float* pl = &Bl[bKR[i]][bNV[i]];
            float h;
            h = tf32r(bvP[i].x); ph[0] = h; pl[0] = tf32r(bvP[i].x - h);
            h = tf32r(bvP[i].y); ph[1] = h; pl[1] = tf32r(bvP[i].y - h);
            h = tf32r(bvP[i].z); ph[2] = h; pl[2] = tf32r(bvP[i].z - h);
            h = tf32r(bvP[i].w); ph[3] = h; pl[3] = tf32r(bvP[i].w - h);
        }
        __syncthreads();

        if (kt + T3K < K) prefetch(kt + T3K);

#pragma unroll
        for (int k0 = 0; k0 < T3K; k0 += 8) {
            unsigned afh[4][4], afl[4][4], bfh[4][2], bfl[4][2];
#pragma unroll
            for (int mi = 0; mi < 4; ++mi) {
                int rb = wm + mi * 16;
                afh[mi][0] = __float_as_uint(Ah[rb + fr][k0 + fc]);
                afh[mi][1] = __float_as_uint(Ah[rb + fr + 8][k0 + fc]);
                afh[mi][2] = __float_as_uint(Ah[rb + fr][k0 + fc + 4]);
                afh[mi][3] = __float_as_uint(Ah[rb + fr + 8][k0 + fc + 4]);
                afl[mi][0] = __float_as_uint(Al[rb + fr][k0 + fc]);
                afl[mi][1] = __float_as_uint(Al[rb + fr + 8][k0 + fc]);
                afl[mi][2] = __float_as_uint(Al[rb + fr][k0 + fc + 4]);
                afl[mi][3] = __float_as_uint(Al[rb + fr + 8][k0 + fc + 4]);
            }
#pragma unroll
            for (int ni = 0; ni < 4; ++ni) {
                int nb = wn + ni * 8;
                bfh[ni][0] = __float_as_uint(Bh[k0 + fc][nb + fr]);
                bfh[ni][1] = __float_as_uint(Bh[k0 + fc + 4][nb + fr]);
                bfl[ni][0] = __float_as_uint(Bl[k0 + fc][nb + fr]);
                bfl[ni][1] = __float_as_uint(Bl[k0 + fc + 4][nb + fr]);
            }
#pragma unroll
            for (int mi = 0; mi < 4; ++mi)
#pragma unroll
                for (int ni = 0; ni < 4; ++ni) {
                    mma_tf32(acc[mi][ni], afl[mi], bfh[ni], acc[mi][ni]);
                    mma_tf32(acc[mi][ni], afh[mi], bfl[ni], acc[mi][ni]);
                    mma_tf32(acc[mi][ni], afh[mi], bfh[ni], acc[mi][ni]);
                }
        }
    }

    const int cc = (lane & 3) * 2;
#pragma unroll
    for (int mi = 0; mi < 4; ++mi) {
        int rloc0 = m0 + wm + mi * 16 + fr;
        int rloc1 = rloc0 + 8;
#pragma unroll
        for (int ni = 0; ni < 4; ++ni) {
            int col = n0 + wn + ni * 8 + cc;
            {
                size_t cr = (size_t)rloc0 * ldc;
                C[cr + col]     = acc[mi][ni][0] + Cadd[cr + col];
                C[cr + col + 1] = acc[mi][ni][1] + Cadd[cr + col + 1];
            }
            {
                size_t cr = (size_t)rloc1 * ldc;
                C[cr + col]     = acc[mi][ni][2] + Cadd[cr + col];
                C[cr + col + 1] = acc[mi][ni][3] + Cadd[cr + col + 1];
            }
        }
    }
}

// -------- shared fp16 mma helpers --------
__device__ __forceinline__ void ldsm_x4(unsigned& r0, unsigned& r1,
                                        unsigned& r2, unsigned& r3,
                                        unsigned addr) {
    asm volatile("ldmatrix.sync.aligned.m8n8.x4.shared.b16 {%0,%1,%2,%3}, [%4];"
                 : "=r"(r0), "=r"(r1), "=r"(r2), "=r"(r3) : "r"(addr));
}
__device__ __forceinline__ void ldsm_x4_t(unsigned& r0, unsigned& r1,
                                          unsigned& r2, unsigned& r3,
                                          unsigned addr) {
    asm volatile("ldmatrix.sync.aligned.m8n8.x4.trans.shared.b16 {%0,%1,%2,%3}, [%4];"
                 : "=r"(r0), "=r"(r1), "=r"(r2), "=r"(r3) : "r"(addr));
}
__device__ __forceinline__ void mma_f16(float* d, const unsigned* a,
                                        const unsigned* b, const float* c) {
    asm volatile(
        "mma.sync.aligned.m16n8k16.row.col.f32.f16.f16.f32 "
        "{%0,%1,%2,%3}, {%4,%5,%6,%7}, {%8,%9}, {%10,%11,%12,%13};"
        : "=f"(d[0]), "=f"(d[1]), "=f"(d[2]), "=f"(d[3])
        : "r"(a[0]), "r"(a[1]), "r"(a[2]), "r"(a[3]),
          "r"(b[0]), "r"(b[1]),
          "f"(c[0]), "f"(c[1]), "f"(c[2]), "f"(c[3]));
}

// -------- fp16 expert GEMM: m16n8k16 + ldmatrix + register prefetch --------
#define HASTR 40
#define HBSTR 136

__device__ __forceinline__ void hmma_tile_dev(
    const float* __restrict__ A, int lda,
    const float* __restrict__ B, int ldb,
    const float* __restrict__ bias,
    float* __restrict__ C, int ldc,
    int M, int K,
    const int* __restrict__ gmap,
    int m0, int n0, int cRow0)
{
    __shared__ __half AsmH[TM * HASTR];
    __shared__ __half BsmH[TKT * HBSTR];

    const int tid  = threadIdx.x;
    const int lane = tid & 31;
    const int warp = tid >> 5;
    const int wm = (warp & 1) * 64;
    const int wn = (warp >> 1) * 32;
    const int fr = lane >> 2;

    const int lm  = lane >> 3;
    const int l7  = lane & 7;
    const int aRowOff = (lm & 1) * 8 + l7;
    const int aKOff   = (lm >> 1) * 8;
    const int bKOff = (lm & 1) * 8 + l7;
    const int bNOff = (lm >> 1) * 8;

    float acc[4][4][4];
#pragma unroll
    for (int mi = 0; mi < 4; ++mi)
#pragma unroll
        for (int ni = 0; ni < 4; ++ni)
#pragma unroll
            for (int q = 0; q < 4; ++q) acc[mi][ni][q] = 0.f;

    int aR[4], aKV[4]; bool avalid[4]; size_t arow[4];
    int bKR[4], bNV[4];
#pragma unroll
    for (int i = 0; i < 4; ++i) {
        int lin = tid + i * 256;
        aR[i]  = lin >> 3;
        aKV[i] = (lin & 7) * 4;
        int gr = m0 + aR[i];
        avalid[i] = gr < M;
        arow[i] = avalid[i] ? (size_t)(gmap ? gmap[gr] : gr) : 0;
        bKR[i] = lin >> 5;
        bNV[i] = (lin & 31) * 4;
    }

    float4 avP[4], bvP[4];
    auto prefetch = [&](int kt) {
#pragma unroll
        for (int i = 0; i < 4; ++i)
            avP[i] = avalid[i] ? *(const float4*)(A + arow[i] * lda + kt + aKV[i])
                               : make_float4(0.f, 0.f, 0.f, 0.f);
#pragma unroll
        for (int i = 0; i < 4; ++i)
            bvP[i] = *(const float4*)(B + (size_t)(kt + bKR[i]) * ldb + n0 + bNV[i]);
    };

    prefetch(0);

    for (int kt = 0; kt < K; kt += TKT) {
        __syncthreads();
#pragma unroll
        for (int i = 0; i < 4; ++i) {
            __half2* dst = (__half2*)&AsmH[aR[i] * HASTR + aKV[i]];
            dst[0] = __floats2half2_rn(avP[i].x, avP[i].y);
            dst[1] = __floats2half2_rn(avP[i].z, avP[i].w);
        }
#pragma unroll
        for (int i = 0; i < 4; ++i) {
            __half2* dst = (__half2*)&BsmH[bKR[i] * HBSTR + bNV[i]];
            dst[0] = __floats2half2_rn(bvP[i].x, bvP[i].y);
            dst[1] = __floats2half2_rn(bvP[i].z, bvP[i].w);
        }
        __syncthreads();

        if (kt + TKT < K) prefetch(kt + TKT);

#pragma unroll
        for (int k0 = 0; k0 < TKT; k0 += 16) {
            unsigned af[4][4], bf[4][2];
#pragma unroll
            for (int mi = 0; mi < 4; ++mi) {
                int rb = wm + mi * 16;
                unsigned addr = (unsigned)__cvta_generic_to_shared(
                    &AsmH[(rb + aRowOff) * HASTR + k0 + aKOff]);
                ldsm_x4(af[mi][0], af[mi][1], af[mi][2], af[mi][3], addr);
            }
#pragma unroll
            for (int p = 0; p < 2; ++p) {
                int nb = wn + p * 16;
                unsigned addr = (unsigned)__cvta_generic_to_shared(
                    &BsmH[(k0 + bKOff) * HBSTR + nb + bNOff]);
                ldsm_x4_t(bf[2 * p][0], bf[2 * p][1],
                          bf[2 * p + 1][0], bf[2 * p + 1][1], addr);
            }
#pragma unroll
            for (int mi = 0; mi < 4; ++mi)
#pragma unroll
                for (int ni = 0; ni < 4; ++ni)
                    mma_f16(acc[mi][ni], af[mi], bf[ni], acc[mi][ni]);
        }
    }

    const int cc = (lane & 3) * 2;
#pragma unroll
    for (int mi = 0; mi < 4; ++mi) {
        int rloc0 = m0 + wm + mi * 16 + fr;
        int rloc1 = rloc0 + 8;
#pragma unroll
        for (int ni = 0; ni < 4; ++ni) {
            int col = n0 + wn + ni * 8 + cc;
            float b0 = bias ? bias[col] : 0.f;
            float b1 = bias ? bias[col + 1] : 0.f;
            if (rloc0 < M) {
                size_t cr = (size_t)(cRow0 + rloc0) * ldc;
                C[cr + col]     = acc[mi][ni][0] + b0;
                C[cr + col + 1] = acc[mi][ni][1] + b1;
            }
            if (rloc1 < M) {
                size_t cr = (size_t)(cRow0 + rloc1) * ldc;
                C[cr + col]     = acc[mi][ni][2] + b0;
                C[cr + col + 1] = acc[mi][ni][3] + b1;
            }
        }
    }
}

__global__ __launch_bounds__(256, 2) void hmma_expert_up(
    const float* __restrict__ xf,
    const float* __restrict__ W1, const float* __restrict__ b1,
    float* __restrict__ h1)
{
    int e = blockIdx.z;
    int cnt = d_cnt[e];
    int m0 = blockIdx.y * TM;
    if (m0 >= cnt) return;
    int off = d_offs[e];
    hmma_tile_dev(xf, DMODEL,
                  W1 + (size_t)e * DMODEL * HID, HID,
                  b1 + (size_t)e * HID,
                  h1, HID, cnt, DMODEL,
                  d_tokrow + off, m0, blockIdx.x * TN, off);
}

__global__ __launch_bounds__(256, 2) void hmma_expert_gv(
    const float* __restrict__ h1,
    const float* __restrict__ Wg, const float* __restrict__ bg,
    const float* __restrict__ Wv, const float* __restrict__ bv,
    float* __restrict__ Ge, float* __restrict__ Ve)
{
    int e = blockIdx.z;
    int cnt = d_cnt[e];
    int m0 = blockIdx.y * TM;
    if (m0 >= cnt) return;
    int off = d_offs[e];
    const int halfTiles = DMODEL / TN;
    bool isV = blockIdx.x >= halfTiles;
    int n0 = (blockIdx.x - (isV ? halfTiles : 0)) * TN;
    const float* B    = (isV ? Wv : Wg) + (size_t)e * HID * DMODEL;
    const float* bias = (isV ? bv : bg) + (size_t)e * DMODEL;
    float* C = isV ? Ve : Ge;
    hmma_tile_dev(h1 + (size_t)off * HID, HID, B, DMODEL, bias,
                  C, DMODEL, cnt, HID, nullptr, m0, n0, off);
}

// ------- flash attention (fp32, causal, GQA) — padded smem, heavy-first -----
#define KVP 68   // row pitch: 68 % 32 = 4 -> store conflicts <= 4-way; 16B aligned

__global__ __launch_bounds__(64) void attn_kernel(
    const float* __restrict__ Q, const float* __restrict__ Kb,
    const float* __restrict__ Vb, float* __restrict__ ctx)
{
    const int qb = gridDim.x - 1 - blockIdx.x;   // heavy blocks first
    const int h = blockIdx.y, b = blockIdx.z;
    const int r = threadIdx.x;
    const int qglob = qb * 64 + r;
    const size_t t = (size_t)b * SEQ + qglob;
    const int kh = h >> 2;

    float q[DK];
    const float* qp = Q + t * DMODEL + h * DK;
#pragma unroll
    for (int d4 = 0; d4 < 16; ++d4) {
        float4 v = *(const float4*)(qp + d4 * 4);
        q[d4 * 4 + 0] = v.x; q[d4 * 4 + 1] = v.y;
        q[d4 * 4 + 2] = v.z; q[d4 * 4 + 3] = v.w;
    }
    float acc[DK];
#pragma unroll
    for (int d = 0; d < DK; ++d) acc[d] = 0.f;
    float mval = -3.4e38f, lsum = 0.f;

    __shared__ float Ksm[64][KVP];
    __shared__ float Vsm[64][KVP];

    for (int kt = 0; kt <= qb; ++kt) {
        __syncthreads();
        {
            size_t krow = (size_t)b * SEQ + kt * 64 + r;
            const float4* kp = (const float4*)(Kb + krow * KVDIM + kh * DK);
            const float4* vp = (const float4*)(Vb + krow * KVDIM + kh * DK);
#pragma unroll
            for (int c = 0; c < 16; ++c) {
                *(float4*)&Ksm[r][c * 4] = kp[c];
                *(float4*)&Vsm[r][c * 4] = vp[c];
            }
        }
        __syncthreads();
        const int kmax = (kt == qb) ? r : 63;
        for (int c0 = 0; c0 <= kmax; c0 += 16) {
            float s[16];
            float mch = -3.4e38f;
#pragma unroll
            for (int j = 0; j < 16; ++j) {
                int k = c0 + j;
                float dot = 0.f;
                const float4* kr = (const float4*)Ksm[k];
#pragma unroll
                for (int d4 = 0; d4 < 16; ++d4) {
                    float4 kv = kr[d4];
                    dot += q[d4 * 4 + 0] * kv.x + q[d4 * 4 + 1] * kv.y
                         + q[d4 * 4 + 2] * kv.z + q[d4 * 4 + 3] * kv.w;
                }
                s[j] = (k <= kmax) ? dot * 0.125f : -3.4e38f;
                mch = fmaxf(mch, s[j]);
            }
            float mnew = fmaxf(mval, mch);
            float corr = __expf(mval - mnew);
            lsum *= corr;
#pragma unroll
            for (int d = 0; d < DK; ++d) acc[d] *= corr;
#pragma unroll
            for (int j = 0; j < 16; ++j) {
                float p = __expf(s[j] - mnew);
                lsum += p;
                const float4* vr = (const float4*)Vsm[c0 + j];
#pragma unroll
                for (int d4 = 0; d4 < 16; ++d4) {
                    float4 vv = vr[d4];
                    acc[d4 * 4 + 0] += p * vv.x;
                    acc[d4 * 4 + 1] += p * vv.y;
                    acc[d4 * 4 + 2] += p * vv.z;
                    acc[d4 * 4 + 3] += p * vv.w;
                }
            }
            mval = mnew;
        }
    }
    float inv = 1.f / lsum;
    float* op = ctx + t * DMODEL + h * DK;
#pragma unroll
    for (int d = 0; d < DK; ++d) op[d] = acc[d] * inv;
}

// ---------------- gating ----------------
__global__ void gate_kernel(const float* __restrict__ xf,
                            const float* __restrict__ gateE) {
    int warp = (blockIdx.x * blockDim.x + threadIdx.x) >> 5;
    int lane = threadIdx.x & 31;
    if (warp >= TTOK) return;
    int t = warp;
    float acc[NEXP];
#pragma unroll
    for (int e = 0; e < NEXP; ++e) acc[e] = 0.f;
    for (int d = lane; d < DMODEL; d += 32) {
        float xv = xf[(size_t)t * DMODEL + d];
#pragma unroll
        for (int e = 0; e < NEXP; ++e) acc[e] += xv * gateE[d * NEXP + e];
    }
#pragma unroll
    for (int e = 0; e < NEXP; ++e)
#pragma unroll
        for (int o = 16; o > 0; o >>= 1)
            acc[e] += __shfl_xor_sync(0xffffffff, acc[e], o);
    if (lane == 0) {
        int i0 = 0; float v0 = acc[0];
#pragma unroll
        for (int e = 1; e < NEXP; ++e) if (acc[e] > v0) { v0 = acc[e]; i0 = e; }
        int i1 = -1; float v1 = -3.4e38f;
#pragma unroll
        for (int e = 0; e < NEXP; ++e)
            if (e != i0 && acc[e] > v1) { v1 = acc[e]; i1 = e; }
        if (i1 < 0) { i1 = (i0 + 1) & (NEXP - 1); v1 = v0; }
        float w0 = 1.f / (1.f + __expf(v1 - v0));
        float w1 = 1.f - w0;
        d_top[2 * t]     = i0;  d_tw[2 * t]     = w0;
        d_top[2 * t + 1] = i1;  d_tw[2 * t + 1] = w1;
    }
}

__global__ void bucket_kernel() {
    __shared__ int tops[NSLOT];
    __shared__ int cnt[NEXP];
    for (int s = threadIdx.x; s < NSLOT; s += blockDim.x) tops[s] = d_top[s];
    if (threadIdx.x < NEXP) cnt[threadIdx.x] = 0;
    __syncthreads();
    if (threadIdx.x == 0) {
        for (int s = 0; s < NSLOT; ++s) {
            int e = tops[s];
            d_pos[s] = cnt[e]++;
        }
        int o = 0;
        for (int e = 0; e < NEXP; ++e) { d_offs[e] = o; d_cnt[e] = cnt[e]; o += cnt[e]; }
    }
    __syncthreads();
    for (int s = threadIdx.x; s < NSLOT; s += blockDim.x) {
        int e = tops[s];
        int j = d_offs[e] + d_pos[s];
        d_rowof[s] = j;
        d_tokrow[j] = s >> 1;
    }
}

__global__ void combine_kernel(const float* __restrict__ Ge,
                               const float* __restrict__ Ve,
                               float* __restrict__ out) {
    int t = blockIdx.x;
    int j0 = d_rowof[2 * t],     j1 = d_rowof[2 * t + 1];
    float w0 = d_tw[2 * t],      w1 = d_tw[2 * t + 1];
    const float4* g0p = (const float4*)(Ge + (size_t)j0 * DMODEL);
    const float4* v0p = (const float4*)(Ve + (size_t)j0 * DMODEL);
    const float4* g1p = (const float4*)(Ge + (size_t)j1 * DMODEL);
    const float4* v1p = (const float4*)(Ve + (size_t)j1 * DMODEL);
    float4* op = (float4*)(out + (size_t)t * DMODEL);
    for (int d = threadIdx.x; d < DMODEL / 4; d += blockDim.x) {
        float4 g0 = g0p[d], g1 = g1p[d], v0 = v0p[d], v1 = v1p[d], o = op[d];
        o.x += w0 * (g0.x / (1.f + __expf(-g0.x))) * v0.x + w1 * (g1.x / (1.f + __expf(-g1.x))) * v1.x;
        o.y += w0 * (g0.y / (1.f + __expf(-g0.y))) * v0.y + w1 * (g1.y / (1.f + __expf(-g1.y))) * v1.y;
        o.z += w0 * (g0.z / (1.f + __expf(-g0.z))) * v0.z + w1 * (g1.z / (1.f + __expf(-g1.z))) * v1.z;
        o.w += w0 * (g0.w / (1.f + __expf(-g0.w))) * v0.w + w1 * (g1.w / (1.f + __expf(-g1.w))) * v1.w;
        op[d] = o;
    }
}

// ---------------- launch ----------------
extern "C" void kernel_launch(void* const* d_in, const int* in_sizes, int n_in,
                              void* d_out, int out_size) {
    const float* x      = (const float*)d_in[0];
    const float* fcos   = (const float*)d_in[1];
    const float* fsin   = (const float*)d_in[2];
    const int*   taskid = (const int*)  d_in[3];
    const float* n1w    = (const float*)d_in[4];
    const float* n2w    = (const float*)d_in[5];
    const float* WqT    = (const float*)d_in[6];
    const float* WkT    = (const float*)d_in[7];
    const float* WvT    = (const float*)d_in[8];
    const float* WoT    = (const float*)d_in[9];
    const float* qA     = (const float*)d_in[10];
    const float* qB     = (const float*)d_in[11];
    const float* kA     = (const float*)d_in[12];
    const float* kB     = (const float*)d_in[13];
    const float* vA     = (const float*)d_in[14];
    const float* vB     = (const float*)d_in[15];
    const float* gateWT = (const float*)d_in[16];
    const float* gA     = (const float*)d_in[17];
    const float* gB     = (const float*)d_in[18];
    const float* temb   = (const float*)d_in[19];
    const float* eW1    = (const float*)d_in[20];
    const float* eb1    = (const float*)d_in[21];
    const float* eWg    = (const float*)d_in[22];
    const float* ebg    = (const float*)d_in[23];
    const float* eWv    = (const float*)d_in[24];
    const float* ebv    = (const float*)d_in[25];
    float* out = (float*)d_out;

    float *p_h, *p_WqE, *p_WkE, *p_WvE, *p_gateE, *p_Q, *p_Kb, *p_Vb,
          *p_ctx, *p_xf, *p_h1, *p_Ge, *p_Ve;
    cudaGetSymbolAddress((void**)&p_h,     d_h);
    cudaGetSymbolAddress((void**)&p_WqE,   d_WqE);
    cudaGetSymbolAddress((void**)&p_WkE,   d_WkE);
    cudaGetSymbolAddress((void**)&p_WvE,   d_WvE);
    cudaGetSymbolAddress((void**)&p_gateE, d_gateE);
    cudaGetSymbolAddress((void**)&p_Q,     d_Q);
    cudaGetSymbolAddress((void**)&p_Kb,    d_Kb);
    cudaGetSymbolAddress((void**)&p_Vb,    d_Vb);
    cudaGetSymbolAddress((void**)&p_ctx,   d_ctx);
    cudaGetSymbolAddress((void**)&p_xf,    d_xf);
    cudaGetSymbolAddress((void**)&p_h1,    d_h1);
    cudaGetSymbolAddress((void**)&p_Ge,    d_Ge);
    cudaGetSymbolAddress((void**)&p_Ve,    d_Ve);

    eff_weight_kernel<<<(DMODEL * DMODEL + 255) / 256, 256>>>(WqT, qA, qB, p_WqE, DMODEL, DMODEL * DMODEL);
    eff_weight_kernel<<<(DMODEL * KVDIM + 255) / 256, 256>>>(WkT, kA, kB, p_WkE, KVDIM, DMODEL * KVDIM);
    eff_weight_kernel<<<(DMODEL * KVDIM + 255) / 256, 256>>>(WvT, vA, vB, p_WvE, KVDIM, DMODEL * KVDIM);
    eff_weight_kernel<<<(DMODEL * NEXP + 255) / 256, 256>>>(gateWT, gA, gB, p_gateE, NEXP, DMODEL * NEXP);

    rmsnorm1_kernel<<<TTOK, 256>>>(x, n1w, p_h);

    // QKV: tf32 tensor cores + register prefetch
    mma_plain<<<dim3(DMODEL / TN, TTOK / TM), 256>>>(p_h, DMODEL, p_WqE, DMODEL, p_Q, DMODEL, TTOK, DMODEL);
    mma_plain<<<dim3(KVDIM / TN, TTOK / TM), 256>>>(p_h, DMODEL, p_WkE, KVDIM, p_Kb, KVDIM, TTOK, DMODEL);
    mma_plain<<<dim3(KVDIM / TN, TTOK / TM), 256>>>(p_h, DMODEL, p_WvE, KVDIM, p_Vb, KVDIM, TTOK, DMODEL);

    rope_kernel<<<TTOK, 512>>>(p_Q, p_Kb, fcos, fsin);

    // flash attention: scalar fp32, padded smem (no 32-way store conflicts)
    attn_kernel<<<dim3(SEQ / 64, NHEAD, 2), 64>>>(p_Q, p_Kb, p_Vb, p_ctx);

    // Wo: 3xTF32 split — near-fp32 precision on tensor cores (gate-safe)
    mma3_plain<<<dim3(DMODEL / TN, TTOK / TM), 256>>>(p_ctx, DMODEL, WoT, DMODEL, x, out, DMODEL, TTOK, DMODEL);

    rmsnorm2_kernel<<<TTOK, 256>>>(out, n2w, taskid, temb, p_xf);

    gate_kernel<<<(TTOK * 32 + 255) / 256, 256>>>(p_xf, p_gateE);
    bucket_kernel<<<1, 256>>>();

    // expert GEMMs: fp16 + ldmatrix + prefetch; GEMM2/3 fused
    hmma_expert_up<<<dim3(HID / TN, TTOK / TM, NEXP), 256>>>(
        p_xf, eW1, eb1, p_h1);
    hmma_expert_gv<<<dim3(2 * DMODEL / TN, TTOK / TM, NEXP), 256>>>(
        p_h1, eWg, ebg, eWv, ebv, p_Ge, p_Ve);

    combine_kernel<<<TTOK, 256>>>(p_Ge, p_Ve, out);
}